// round 1
// baseline (speedup 1.0000x reference)
#include <cuda_runtime.h>
#include <math.h>

// ---------------------------------------------------------------------------
// Problem constants (shapes fixed by the dataset)
// ---------------------------------------------------------------------------
#define Nn   32768
#define Dd   128
#define Hh   2
#define HDm  64
#define Ee   262144
#define Mm   131072
#define NGg  32
#define PW   896          // 128(Q2)+128(K2)+256(Q3)+256(K3)+128(Qm)
#define KSL  32           // memory slots
// softplus(inverse_softplus(x)) == x  ->  lam2=1, lam3=0.5, lamm=1, b2=b3=bm=1
#define LAM3 0.5f
#define EPSV 1e-5f

// ---------------------------------------------------------------------------
// Scratch (static device globals; no runtime allocation allowed)
// ---------------------------------------------------------------------------
__device__ float g_G[(size_t)Nn * Dd];
__device__ float g_mu[Nn];
__device__ float g_rstd[Nn];
__device__ float g_P[(size_t)Nn * PW];     // [Q2 | K2 | Q3 | K3 | Qm] per node
__device__ float g_U[(size_t)Nn * PW];     // grads wrt the projections
__device__ float g_dG[(size_t)Nn * Dd];
__device__ float g_Wcat[PW * Dd];
__device__ float g_WcatT[Dd * PW];
__device__ float g_Km[Hh * KSL * HDm];     // [h][k][z]
__device__ float g_KmT[Hh * HDm * KSL];    // [h][z][k]
__device__ float g_s2[(size_t)Ee * Hh];
__device__ float g_Z2[Nn * Hh];
__device__ float g_qk[(size_t)Mm * 4];
__device__ float g_tv[(size_t)Mm * 4];
__device__ float g_s3[(size_t)Mm * Hh];
__device__ float g_Z3[Nn * Hh];
__device__ float g_Lm[Nn * Hh];

// ---------------------------------------------------------------------------
// Warp reduce helpers
// ---------------------------------------------------------------------------
__device__ __forceinline__ float wsum32(float v) {
#pragma unroll
    for (int m = 16; m > 0; m >>= 1) v += __shfl_xor_sync(0xffffffffu, v, m);
    return v;
}
__device__ __forceinline__ float wsum16(float v) {
#pragma unroll
    for (int m = 8; m > 0; m >>= 1) v += __shfl_xor_sync(0xffffffffu, v, m);
    return v;
}
__device__ __forceinline__ float wsum8(float v) {
#pragma unroll
    for (int m = 4; m > 0; m >>= 1) v += __shfl_xor_sync(0xffffffffu, v, m);
    return v;
}

// ---------------------------------------------------------------------------
// LayerNorm forward (warp per row), saves mu/rstd
// ---------------------------------------------------------------------------
__global__ void k_ln(const float* __restrict__ X, const float* __restrict__ gamma,
                     const float* __restrict__ beta) {
    int w = (blockIdx.x * blockDim.x + threadIdx.x) >> 5;
    int lane = threadIdx.x & 31;
    if (w >= Nn) return;
    const float4 x = *(const float4*)(X + (size_t)w * Dd + lane * 4);
    float s = x.x + x.y + x.z + x.w;
    float mu = wsum32(s) * (1.0f / Dd);
    float4 xc = make_float4(x.x - mu, x.y - mu, x.z - mu, x.w - mu);
    float v = xc.x * xc.x + xc.y * xc.y + xc.z * xc.z + xc.w * xc.w;
    v = wsum32(v) * (1.0f / Dd);
    float rstd = rsqrtf(v + EPSV);
    const float4 g4 = *(const float4*)(gamma + lane * 4);
    const float4 b4 = *(const float4*)(beta + lane * 4);
    float4 G;
    G.x = g4.x * xc.x * rstd + b4.x;
    G.y = g4.y * xc.y * rstd + b4.y;
    G.z = g4.z * xc.z * rstd + b4.z;
    G.w = g4.w * xc.w * rstd + b4.w;
    *(float4*)(g_G + (size_t)w * Dd + lane * 4) = G;
    if (lane == 0) { g_mu[w] = mu; g_rstd[w] = rstd; }
}

// ---------------------------------------------------------------------------
// Build stacked weight matrix (and its transpose)
// ---------------------------------------------------------------------------
__global__ void k_wcat(const float* __restrict__ WQ2, const float* __restrict__ WK2,
                       const float* __restrict__ WQ3, const float* __restrict__ WK3,
                       const float* __restrict__ WQm) {
    int idx = blockIdx.x * blockDim.x + threadIdx.x;
    if (idx >= PW * Dd) return;
    int j = idx / Dd, d = idx - j * Dd;
    float v;
    if (j < 128)      v = WQ2[j * Dd + d];
    else if (j < 256) v = WK2[(j - 128) * Dd + d];
    else if (j < 512) v = WQ3[(j - 256) * Dd + d];
    else if (j < 768) v = WK3[(j - 512) * Dd + d];
    else              v = WQm[(j - 768) * Dd + d];
    g_Wcat[j * Dd + d] = v;
    g_WcatT[d * PW + j] = v;
}

// ---------------------------------------------------------------------------
// Km = B_mem @ W_Km^T per head (tiny), both layouts
// ---------------------------------------------------------------------------
__global__ void k_km(const float* __restrict__ Bm, const float* __restrict__ WKm) {
    int idx = blockIdx.x * blockDim.x + threadIdx.x;
    if (idx >= Hh * KSL * HDm) return;
    int h = idx / (KSL * HDm);
    int k = (idx / HDm) % KSL;
    int z = idx % HDm;
    const float* b = Bm + k * Dd;
    const float* w = WKm + (h * HDm + z) * Dd;
    float acc = 0.f;
#pragma unroll 8
    for (int d = 0; d < Dd; d++) acc += b[d] * w[d];
    g_Km[idx] = acc;
    g_KmT[(h * HDm + z) * KSL + k] = acc;
}

// ---------------------------------------------------------------------------
// Tiled SGEMM: C[M,J] = A[M,K] * B[K,J], all row-major. 64x64x16, 256 thr.
// All dims are multiples of the tile in our uses (no bounds checks).
// ---------------------------------------------------------------------------
__global__ void k_gemm(const float* __restrict__ A, int lda,
                       const float* __restrict__ B, int ldb,
                       float* __restrict__ C, int ldc, int Kdim) {
    __shared__ float As[16][64];
    __shared__ float Bs[16][64];
    int tid = threadIdx.x;
    int tx = tid & 15, ty = tid >> 4;
    int row0 = blockIdx.y * 64, col0 = blockIdx.x * 64;
    int arow = tid >> 2, acq = (tid & 3) * 4;
    int brow = tid >> 4, bcol = (tid & 15) * 4;
    const float* Aptr = A + (size_t)(row0 + arow) * lda + acq;
    const float* Bptr = B + (size_t)brow * ldb + col0 + bcol;
    float acc[4][4];
#pragma unroll
    for (int i = 0; i < 4; i++)
#pragma unroll
        for (int j = 0; j < 4; j++) acc[i][j] = 0.f;

    for (int k0 = 0; k0 < Kdim; k0 += 16) {
        float4 av = *(const float4*)(Aptr + k0);
        As[acq + 0][arow] = av.x;
        As[acq + 1][arow] = av.y;
        As[acq + 2][arow] = av.z;
        As[acq + 3][arow] = av.w;
        float4 bv = *(const float4*)(Bptr + (size_t)k0 * ldb);
        *(float4*)&Bs[brow][bcol] = bv;
        __syncthreads();
#pragma unroll
        for (int kk = 0; kk < 16; kk++) {
            float4 a = *(const float4*)&As[kk][ty * 4];
            float4 b = *(const float4*)&Bs[kk][tx * 4];
            acc[0][0] += a.x * b.x; acc[0][1] += a.x * b.y; acc[0][2] += a.x * b.z; acc[0][3] += a.x * b.w;
            acc[1][0] += a.y * b.x; acc[1][1] += a.y * b.y; acc[1][2] += a.y * b.z; acc[1][3] += a.y * b.w;
            acc[2][0] += a.z * b.x; acc[2][1] += a.z * b.y; acc[2][2] += a.z * b.z; acc[2][3] += a.z * b.w;
            acc[3][0] += a.w * b.x; acc[3][1] += a.w * b.y; acc[3][2] += a.w * b.z; acc[3][3] += a.w * b.w;
        }
        __syncthreads();
    }
#pragma unroll
    for (int i = 0; i < 4; i++) {
        float4 o = make_float4(acc[i][0], acc[i][1], acc[i][2], acc[i][3]);
        *(float4*)(C + (size_t)(row0 + ty * 4 + i) * ldc + col0 + tx * 4) = o;
    }
}

// ---------------------------------------------------------------------------
// Pair term forward: warp per edge. s2[e,h] = Q2[c]·K2[u]/8 + a2; Z2 += exp(s2)
// ---------------------------------------------------------------------------
__global__ void k_pair_fwd(const int* __restrict__ c2, const int* __restrict__ u2,
                           const float* __restrict__ a2) {
    int e = (blockIdx.x * 256 + threadIdx.x) >> 5;
    int lane = threadIdx.x & 31;
    if (e >= Ee) return;
    int c = c2[e], u = u2[e];
    const float4 q = *(const float4*)(g_P + (size_t)c * PW + lane * 4);
    const float4 k = *(const float4*)(g_P + (size_t)u * PW + 128 + lane * 4);
    float part = q.x * k.x + q.y * k.y + q.z * k.z + q.w * k.w;
    part = wsum16(part);
    int h = lane >> 4;
    if ((lane & 15) == 0) {
        float s = part * 0.125f + a2[e * 2 + h];
        g_s2[(size_t)e * 2 + h] = s;
        atomicAdd(&g_Z2[c * 2 + h], expf(s));
    }
}

// Pair backward: dQ2[c] += w*K2[u], dK2[u] += w*Q2[c], w = -p/8
__global__ void k_pair_bwd(const int* __restrict__ c2, const int* __restrict__ u2) {
    int e = (blockIdx.x * 256 + threadIdx.x) >> 5;
    int lane = threadIdx.x & 31;
    if (e >= Ee) return;
    int c = c2[e], u = u2[e];
    int h = lane >> 4;
    float p = expf(g_s2[(size_t)e * 2 + h]) / g_Z2[c * 2 + h];
    float wt = -0.125f * p;
    const float4 q = *(const float4*)(g_P + (size_t)c * PW + lane * 4);
    const float4 k = *(const float4*)(g_P + (size_t)u * PW + 128 + lane * 4);
    float* dq = g_U + (size_t)c * PW + lane * 4;
    atomicAdd(dq + 0, wt * k.x); atomicAdd(dq + 1, wt * k.y);
    atomicAdd(dq + 2, wt * k.z); atomicAdd(dq + 3, wt * k.w);
    float* dk = g_U + (size_t)u * PW + 128 + lane * 4;
    atomicAdd(dk + 0, wt * q.x); atomicAdd(dk + 1, wt * q.y);
    atomicAdd(dk + 2, wt * q.z); atomicAdd(dk + 3, wt * q.w);
}

// ---------------------------------------------------------------------------
// Motif forward: warp per motif. 8 dims/lane; groups of 8 lanes = (h,r).
// ---------------------------------------------------------------------------
__global__ void k_motif_fwd(const int* __restrict__ c3, const int* __restrict__ u3,
                            const int* __restrict__ v3, const int* __restrict__ tt,
                            const float* __restrict__ Ttau) {
    int m = (blockIdx.x * 256 + threadIdx.x) >> 5;
    int lane = threadIdx.x & 31;
    if (m >= Mm) return;
    int c = c3[m], ua = u3[m], vb = v3[m], t = tt[m];
    int off = lane * 8;
    const float* q  = g_P + (size_t)c  * PW + 256 + off;
    const float* ku = g_P + (size_t)ua * PW + 512 + off;
    const float* kv = g_P + (size_t)vb * PW + 512 + off;
    const float* tp = Ttau + t * 256 + off;
    float qk = 0.f, tv = 0.f;
#pragma unroll
    for (int i = 0; i < 8; i += 4) {
        float4 qv = *(const float4*)(q + i);
        float4 kuv = *(const float4*)(ku + i);
        float4 kvv = *(const float4*)(kv + i);
        float4 tv4 = *(const float4*)(tp + i);
        qk += qv.x * kuv.x + qv.y * kuv.y + qv.z * kuv.z + qv.w * kuv.w;
        tv += tv4.x * kvv.x + tv4.y * kvv.y + tv4.z * kvv.z + tv4.w * kvv.w;
    }
    qk = wsum8(qk);
    tv = wsum8(tv);
    int g = lane >> 3;
    if ((lane & 7) == 0) {
        g_qk[(size_t)m * 4 + g] = qk;
        g_tv[(size_t)m * 4 + g] = tv;
    }
    float qk0 = __shfl_sync(0xffffffffu, qk, 0),  tv0 = __shfl_sync(0xffffffffu, tv, 0);
    float qk1 = __shfl_sync(0xffffffffu, qk, 8),  tv1 = __shfl_sync(0xffffffffu, tv, 8);
    float qk2 = __shfl_sync(0xffffffffu, qk, 16), tv2 = __shfl_sync(0xffffffffu, tv, 16);
    float qk3 = __shfl_sync(0xffffffffu, qk, 24), tv3 = __shfl_sync(0xffffffffu, tv, 24);
    if (lane < 2) {
        float s3 = (lane == 0) ? (qk0 * tv0 + qk1 * tv1) * (1.0f / 64)
                               : (qk2 * tv2 + qk3 * tv3) * (1.0f / 64);
        g_s3[(size_t)m * 2 + lane] = s3;
        atomicAdd(&g_Z3[c * 2 + lane], expf(s3));
    }
}

// Motif backward
__global__ void k_motif_bwd(const int* __restrict__ c3, const int* __restrict__ u3,
                            const int* __restrict__ v3, const int* __restrict__ tt,
                            const float* __restrict__ Ttau) {
    int m = (blockIdx.x * 256 + threadIdx.x) >> 5;
    int lane = threadIdx.x & 31;
    if (m >= Mm) return;
    int c = c3[m], ua = u3[m], vb = v3[m], t = tt[m];
    int g = lane >> 3;
    int h = g >> 1;
    float p = expf(g_s3[(size_t)m * 2 + h]) / g_Z3[c * 2 + h];
    float gg = -LAM3 * p * (1.0f / 64);
    float cA = gg * g_tv[(size_t)m * 4 + g];
    float cB = gg * g_qk[(size_t)m * 4 + g];
    int off = lane * 8;
    const float* q  = g_P + (size_t)c  * PW + 256 + off;
    const float* ku = g_P + (size_t)ua * PW + 512 + off;
    const float* tp = Ttau + t * 256 + off;
    float* dq  = g_U + (size_t)c  * PW + 256 + off;
    float* dku = g_U + (size_t)ua * PW + 512 + off;
    float* dkv = g_U + (size_t)vb * PW + 512 + off;
#pragma unroll
    for (int i = 0; i < 8; i++) {
        float qi = q[i], kui = ku[i], ti = tp[i];
        atomicAdd(dq + i,  cA * kui);
        atomicAdd(dku + i, cA * qi);
        atomicAdd(dkv + i, cB * ti);
    }
}

// ---------------------------------------------------------------------------
// Memory term: warp per (node, head). Computes Lm and dQm directly (no atomics)
// ---------------------------------------------------------------------------
__global__ void k_mem() {
    int w = (blockIdx.x * 256 + threadIdx.x) >> 5;
    int lane = threadIdx.x & 31;
    if (w >= Nn * Hh) return;
    int n = w >> 1, h = w & 1;
    const float* qm = g_P + (size_t)n * PW + 768 + h * HDm;
    const float* kt = g_KmT + h * HDm * KSL;   // [z][k]
    const float* km = g_Km + h * KSL * HDm;    // [k][z]
    float sm = 0.f;
#pragma unroll 8
    for (int z = 0; z < HDm; z++) sm += qm[z] * kt[z * KSL + lane];
    sm *= 0.125f;
    float e = expf(sm);
    float Z = wsum32(e);
    float p = e / Z;
    if (lane == 0) g_Lm[w] = logf(Z);
    float a0 = 0.f, a1 = 0.f;
#pragma unroll
    for (int kk = 0; kk < KSL; kk++) {
        float pk = __shfl_sync(0xffffffffu, p, kk);
        a0 += pk * km[kk * HDm + lane];
        a1 += pk * km[kk * HDm + lane + 32];
    }
    float* du = g_U + (size_t)n * PW + 768 + h * HDm;
    du[lane] = -0.125f * a0;
    du[lane + 32] = -0.125f * a1;
}

// ---------------------------------------------------------------------------
// Per-node energy + per-graph reduction (batch is sorted; block-local bins)
// ---------------------------------------------------------------------------
__global__ void k_energy(const float* __restrict__ X, const int* __restrict__ batch,
                         float* __restrict__ Eg) {
    __shared__ float bins[NGg];
    int tid = threadIdx.x;
    if (tid < NGg) bins[tid] = 0.f;
    __syncthreads();
    int w = (blockIdx.x * 256 + tid) >> 5;
    int lane = tid & 31;
    if (w < Nn) {
        const float4 x = *(const float4*)(X + (size_t)w * Dd + lane * 4);
        float ss = wsum32(x.x * x.x + x.y * x.y + x.z * x.z + x.w * x.w);
        if (lane == 0) {
            float e = 0.5f * ss;
            float z0 = g_Z2[w * 2], z1 = g_Z2[w * 2 + 1];
            e -= (z0 > 0.f ? logf(z0) : 0.f) + (z1 > 0.f ? logf(z1) : 0.f);
            float y0 = g_Z3[w * 2], y1 = g_Z3[w * 2 + 1];
            e -= LAM3 * ((y0 > 0.f ? logf(y0) : 0.f) + (y1 > 0.f ? logf(y1) : 0.f));
            e -= g_Lm[w * 2] + g_Lm[w * 2 + 1];
            atomicAdd(&bins[batch[w]], e);
        }
    }
    __syncthreads();
    if (tid < NGg) atomicAdd(&Eg[tid], bins[tid]);
}

// ---------------------------------------------------------------------------
// LN backward + grad clip + step + state clip (warp per row)
// ---------------------------------------------------------------------------
__global__ void k_final(const float* __restrict__ X, const float* __restrict__ gamma,
                        const float* __restrict__ step, float* __restrict__ out) {
    int w = (blockIdx.x * blockDim.x + threadIdx.x) >> 5;
    int lane = threadIdx.x & 31;
    if (w >= Nn) return;
    const float4 x = *(const float4*)(X + (size_t)w * Dd + lane * 4);
    const float4 dg = *(const float4*)(g_dG + (size_t)w * Dd + lane * 4);
    const float4 gm = *(const float4*)(gamma + lane * 4);
    float mu = g_mu[w], rstd = g_rstd[w];
    float4 xh = make_float4((x.x - mu) * rstd, (x.y - mu) * rstd,
                            (x.z - mu) * rstd, (x.w - mu) * rstd);
    float4 dxh = make_float4(dg.x * gm.x, dg.y * gm.y, dg.z * gm.z, dg.w * gm.w);
    float S1 = wsum32(dxh.x + dxh.y + dxh.z + dxh.w) * (1.0f / Dd);
    float S2 = wsum32(dxh.x * xh.x + dxh.y * xh.y + dxh.z * xh.z + dxh.w * xh.w) * (1.0f / Dd);
    float4 g;
    g.x = x.x + rstd * (dxh.x - S1 - xh.x * S2);
    g.y = x.y + rstd * (dxh.y - S1 - xh.y * S2);
    g.z = x.z + rstd * (dxh.z - S1 - xh.z * S2);
    g.w = x.w + rstd * (dxh.w - S1 - xh.w * S2);
    float gss = wsum32(g.x * g.x + g.y * g.y + g.z * g.z + g.w * g.w);
    float sc1 = 1.0f / fmaxf(sqrtf(gss), 1.0f);   // GRAD_CLIP = 1
    float st = step[0] * sc1;                      // DAMPING = 1
    float4 xn = make_float4(x.x - st * g.x, x.y - st * g.y,
                            x.z - st * g.z, x.w - st * g.w);
    float sn = wsum32(xn.x * xn.x + xn.y * xn.y + xn.z * xn.z + xn.w * xn.w);
    float sc2 = 10.0f / fmaxf(sqrtf(sn), 10.0f);  // STATE_CLIP = 10
    float4 o = make_float4(xn.x * sc2, xn.y * sc2, xn.z * sc2, xn.w * sc2);
    *(float4*)(out + (size_t)w * Dd + lane * 4) = o;
}

// ---------------------------------------------------------------------------
// Launch
// ---------------------------------------------------------------------------
extern "C" void kernel_launch(void* const* d_in, const int* in_sizes, int n_in,
                              void* d_out, int out_size) {
    const float* X    = (const float*)d_in[0];
    const int* c2     = (const int*)d_in[1];
    const int* u2     = (const int*)d_in[2];
    const int* c3     = (const int*)d_in[3];
    const int* u3     = (const int*)d_in[4];
    const int* v3     = (const int*)d_in[5];
    const int* tt     = (const int*)d_in[6];
    const int* batch  = (const int*)d_in[7];
    const float* a2   = (const float*)d_in[8];
    const float* step = (const float*)d_in[9];
    const float* gamma= (const float*)d_in[10];
    const float* beta = (const float*)d_in[11];
    const float* WQ2  = (const float*)d_in[12];
    const float* WK2  = (const float*)d_in[13];
    const float* WQ3  = (const float*)d_in[14];
    const float* WK3  = (const float*)d_in[15];
    const float* Ttau = (const float*)d_in[16];
    const float* WQm  = (const float*)d_in[17];
    const float* WKm  = (const float*)d_in[18];
    const float* Bmem = (const float*)d_in[19];
    float* out = (float*)d_out;
    float* Eg  = out + (size_t)Nn * Dd;

    void *pU, *pZ2, *pZ3, *pG, *pP, *pWc, *pWcT, *pdG;
    cudaGetSymbolAddress(&pU, g_U);
    cudaGetSymbolAddress(&pZ2, g_Z2);
    cudaGetSymbolAddress(&pZ3, g_Z3);
    cudaGetSymbolAddress(&pG, g_G);
    cudaGetSymbolAddress(&pP, g_P);
    cudaGetSymbolAddress(&pWc, g_Wcat);
    cudaGetSymbolAddress(&pWcT, g_WcatT);
    cudaGetSymbolAddress(&pdG, g_dG);

    cudaMemsetAsync(pU, 0, sizeof(float) * (size_t)Nn * PW);
    cudaMemsetAsync(pZ2, 0, sizeof(float) * Nn * Hh);
    cudaMemsetAsync(pZ3, 0, sizeof(float) * Nn * Hh);
    cudaMemsetAsync(Eg, 0, sizeof(float) * NGg);

    k_ln<<<Nn / 8, 256>>>(X, gamma, beta);
    k_wcat<<<(PW * Dd + 255) / 256, 256>>>(WQ2, WK2, WQ3, WK3, WQm);
    k_km<<<(Hh * KSL * HDm + 255) / 256, 256>>>(Bmem, WKm);

    // Forward projections: P = G[N,128] x WcatT[128,896]
    k_gemm<<<dim3(PW / 64, Nn / 64), 256>>>((const float*)pG, Dd,
                                            (const float*)pWcT, PW,
                                            (float*)pP, PW, Dd);

    k_pair_fwd<<<Ee / 8, 256>>>(c2, u2, a2);
    k_motif_fwd<<<Mm / 8, 256>>>(c3, u3, v3, tt, Ttau);
    k_mem<<<(Nn * Hh) / 8, 256>>>();

    k_energy<<<Nn / 8, 256>>>(X, batch, Eg);

    k_pair_bwd<<<Ee / 8, 256>>>(c2, u2);
    k_motif_bwd<<<Mm / 8, 256>>>(c3, u3, v3, tt, Ttau);

    // Backward projections: dG = U[N,896] x Wcat[896,128]
    k_gemm<<<dim3(Dd / 64, Nn / 64), 256>>>((const float*)pU, PW,
                                            (const float*)pWc, Dd,
                                            (float*)pdG, Dd, PW);

    k_final<<<Nn / 8, 256>>>(X, gamma, step, out);
}

// round 4
// speedup vs baseline: 1.6736x; 1.6736x over previous
#include <cuda_runtime.h>
#include <math.h>

// ---------------------------------------------------------------------------
// Problem constants (shapes fixed by the dataset)
// ---------------------------------------------------------------------------
#define Nn   32768
#define Dd   128
#define Hh   2
#define HDm  64
#define Ee   262144
#define Mm   131072
#define NGg  32
#define PW   896          // 128(Q2)+128(K2)+256(Q3)+256(K3)+128(Qm)
#define KSL  32           // memory slots
// softplus(inverse_softplus(x)) == x  ->  lam2=1, lam3=0.5, lamm=1, b2=b3=bm=1
#define LAM3 0.5f
#define EPSV 1e-5f

// ---------------------------------------------------------------------------
// Scratch (static device globals; no runtime allocation allowed)
// ---------------------------------------------------------------------------
__device__ float g_G[(size_t)Nn * Dd];
__device__ float g_mu[Nn];
__device__ float g_rstd[Nn];
__device__ float g_P[(size_t)Nn * PW];     // [Q2 | K2 | Q3 | K3 | Qm] per node
__device__ float g_U[(size_t)Nn * PW];     // grads wrt the projections
__device__ float g_dG[(size_t)Nn * Dd];
__device__ float g_Wcat[PW * Dd];
__device__ float g_WcatT[Dd * PW];
__device__ float g_Km[Hh * KSL * HDm];     // [h][k][z]
__device__ float g_KmT[Hh * HDm * KSL];    // [h][z][k]
__device__ float g_s2[(size_t)Ee * Hh];
__device__ float g_Z2[Nn * Hh];
__device__ float g_qk[(size_t)Mm * 4];
__device__ float g_tv[(size_t)Mm * 4];
__device__ float g_s3[(size_t)Mm * Hh];
__device__ float g_Z3[Nn * Hh];
__device__ float g_Lm[Nn * Hh];

// ---------------------------------------------------------------------------
// Helpers
// ---------------------------------------------------------------------------
__device__ __forceinline__ float wsum32(float v) {
#pragma unroll
    for (int m = 16; m > 0; m >>= 1) v += __shfl_xor_sync(0xffffffffu, v, m);
    return v;
}
__device__ __forceinline__ float wsum16(float v) {
#pragma unroll
    for (int m = 8; m > 0; m >>= 1) v += __shfl_xor_sync(0xffffffffu, v, m);
    return v;
}
__device__ __forceinline__ float wsum8(float v) {
#pragma unroll
    for (int m = 4; m > 0; m >>= 1) v += __shfl_xor_sync(0xffffffffu, v, m);
    return v;
}
// Vectorized no-return atomic add (sm_90+): 4 floats in one RED op.
__device__ __forceinline__ void red_add_v4(float* addr, float a, float b, float c, float d) {
    asm volatile("red.global.add.v4.f32 [%0], {%1, %2, %3, %4};"
                 :: "l"(addr), "f"(a), "f"(b), "f"(c), "f"(d) : "memory");
}

// ---------------------------------------------------------------------------
// LayerNorm forward (warp per row), saves mu/rstd
// ---------------------------------------------------------------------------
__global__ void k_ln(const float* __restrict__ X, const float* __restrict__ gamma,
                     const float* __restrict__ beta) {
    int w = (blockIdx.x * blockDim.x + threadIdx.x) >> 5;
    int lane = threadIdx.x & 31;
    if (w >= Nn) return;
    const float4 x = *(const float4*)(X + (size_t)w * Dd + lane * 4);
    float s = x.x + x.y + x.z + x.w;
    float mu = wsum32(s) * (1.0f / Dd);
    float4 xc = make_float4(x.x - mu, x.y - mu, x.z - mu, x.w - mu);
    float v = xc.x * xc.x + xc.y * xc.y + xc.z * xc.z + xc.w * xc.w;
    v = wsum32(v) * (1.0f / Dd);
    float rstd = rsqrtf(v + EPSV);
    const float4 g4 = *(const float4*)(gamma + lane * 4);
    const float4 b4 = *(const float4*)(beta + lane * 4);
    float4 G;
    G.x = g4.x * xc.x * rstd + b4.x;
    G.y = g4.y * xc.y * rstd + b4.y;
    G.z = g4.z * xc.z * rstd + b4.z;
    G.w = g4.w * xc.w * rstd + b4.w;
    *(float4*)(g_G + (size_t)w * Dd + lane * 4) = G;
    if (lane == 0) { g_mu[w] = mu; g_rstd[w] = rstd; }
}

// ---------------------------------------------------------------------------
// Build stacked weight matrix (and its transpose)
// ---------------------------------------------------------------------------
__global__ void k_wcat(const float* __restrict__ WQ2, const float* __restrict__ WK2,
                       const float* __restrict__ WQ3, const float* __restrict__ WK3,
                       const float* __restrict__ WQm) {
    int idx = blockIdx.x * blockDim.x + threadIdx.x;
    if (idx >= PW * Dd) return;
    int j = idx / Dd, d = idx - j * Dd;
    float v;
    if (j < 128)      v = WQ2[j * Dd + d];
    else if (j < 256) v = WK2[(j - 128) * Dd + d];
    else if (j < 512) v = WQ3[(j - 256) * Dd + d];
    else if (j < 768) v = WK3[(j - 512) * Dd + d];
    else              v = WQm[(j - 768) * Dd + d];
    g_Wcat[j * Dd + d] = v;
    g_WcatT[d * PW + j] = v;
}

// ---------------------------------------------------------------------------
// Km = B_mem @ W_Km^T per head (tiny), both layouts
// ---------------------------------------------------------------------------
__global__ void k_km(const float* __restrict__ Bm, const float* __restrict__ WKm) {
    int idx = blockIdx.x * blockDim.x + threadIdx.x;
    if (idx >= Hh * KSL * HDm) return;
    int h = idx / (KSL * HDm);
    int k = (idx / HDm) % KSL;
    int z = idx % HDm;
    const float* b = Bm + k * Dd;
    const float* w = WKm + (h * HDm + z) * Dd;
    float acc = 0.f;
#pragma unroll 8
    for (int d = 0; d < Dd; d++) acc += b[d] * w[d];
    g_Km[idx] = acc;
    g_KmT[(h * HDm + z) * KSL + k] = acc;
}

// ---------------------------------------------------------------------------
// SGEMM 128x128x8, 8x8 microtile, double-buffered. C = A[M,K] * B[K,J].
// All dims multiples of tile (true for our uses). 256 threads.
// ---------------------------------------------------------------------------
__global__ void __launch_bounds__(256, 2)
k_gemm128(const float* __restrict__ A, int lda,
          const float* __restrict__ B, int ldb,
          float* __restrict__ C, int ldc, int Kdim) {
    __shared__ float As[2][8][128];
    __shared__ float Bs[2][8][128];
    int tid = threadIdx.x;
    int tx = tid & 15, ty = tid >> 4;
    int row0 = blockIdx.y * 128, col0 = blockIdx.x * 128;
    int arow = tid >> 1;           // 0..127
    int acol = (tid & 1) * 4;      // 0 or 4
    int brow = tid >> 5;           // 0..7
    int bcol = (tid & 31) * 4;     // 0..124
    const float* Ap = A + (size_t)(row0 + arow) * lda + acol;
    const float* Bp = B + (size_t)brow * ldb + col0 + bcol;

    float acc[8][8];
#pragma unroll
    for (int i = 0; i < 8; i++)
#pragma unroll
        for (int j = 0; j < 8; j++) acc[i][j] = 0.f;

    // preload tile 0
    float4 av = *(const float4*)(Ap);
    float4 bv = *(const float4*)(Bp);
    As[0][acol + 0][arow] = av.x; As[0][acol + 1][arow] = av.y;
    As[0][acol + 2][arow] = av.z; As[0][acol + 3][arow] = av.w;
    *(float4*)&Bs[0][brow][bcol] = bv;
    __syncthreads();

    int nk = Kdim >> 3;
    for (int kt = 0; kt < nk; kt++) {
        int cur = kt & 1, nxt = cur ^ 1;
        if (kt + 1 < nk) {
            av = *(const float4*)(Ap + (kt + 1) * 8);
            bv = *(const float4*)(Bp + (size_t)(kt + 1) * 8 * ldb);
        }
#pragma unroll
        for (int kk = 0; kk < 8; kk++) {
            float ar[8], br[8];
            *(float4*)&ar[0] = *(const float4*)&As[cur][kk][ty * 4];
            *(float4*)&ar[4] = *(const float4*)&As[cur][kk][64 + ty * 4];
            *(float4*)&br[0] = *(const float4*)&Bs[cur][kk][tx * 4];
            *(float4*)&br[4] = *(const float4*)&Bs[cur][kk][64 + tx * 4];
#pragma unroll
            for (int i = 0; i < 8; i++)
#pragma unroll
                for (int j = 0; j < 8; j++)
                    acc[i][j] += ar[i] * br[j];
        }
        if (kt + 1 < nk) {
            As[nxt][acol + 0][arow] = av.x; As[nxt][acol + 1][arow] = av.y;
            As[nxt][acol + 2][arow] = av.z; As[nxt][acol + 3][arow] = av.w;
            *(float4*)&Bs[nxt][brow][bcol] = bv;
            __syncthreads();
        }
    }
#pragma unroll
    for (int i = 0; i < 8; i++) {
        int row = row0 + ((i < 4) ? (ty * 4 + i) : (64 + ty * 4 + i - 4));
        *(float4*)(C + (size_t)row * ldc + col0 + tx * 4) =
            make_float4(acc[i][0], acc[i][1], acc[i][2], acc[i][3]);
        *(float4*)(C + (size_t)row * ldc + col0 + 64 + tx * 4) =
            make_float4(acc[i][4], acc[i][5], acc[i][6], acc[i][7]);
    }
}

// ---------------------------------------------------------------------------
// Pair term forward: warp per edge. s2[e,h] = Q2[c]·K2[u]/8 + a2; Z2 += exp(s2)
// ---------------------------------------------------------------------------
__global__ void k_pair_fwd(const int* __restrict__ c2, const int* __restrict__ u2,
                           const float* __restrict__ a2) {
    int e = (blockIdx.x * 256 + threadIdx.x) >> 5;
    int lane = threadIdx.x & 31;
    if (e >= Ee) return;
    int c = c2[e], u = u2[e];
    const float4 q = *(const float4*)(g_P + (size_t)c * PW + lane * 4);
    const float4 k = *(const float4*)(g_P + (size_t)u * PW + 128 + lane * 4);
    float part = q.x * k.x + q.y * k.y + q.z * k.z + q.w * k.w;
    part = wsum16(part);
    int h = lane >> 4;
    if ((lane & 15) == 0) {
        float s = part * 0.125f + a2[e * 2 + h];
        g_s2[(size_t)e * 2 + h] = s;
        atomicAdd(&g_Z2[c * 2 + h], expf(s));
    }
}

// Pair backward: dQ2[c] += w*K2[u], dK2[u] += w*Q2[c], w = -p/8  (vector RED)
__global__ void k_pair_bwd(const int* __restrict__ c2, const int* __restrict__ u2) {
    int e = (blockIdx.x * 256 + threadIdx.x) >> 5;
    int lane = threadIdx.x & 31;
    if (e >= Ee) return;
    int c = c2[e], u = u2[e];
    int h = lane >> 4;
    float p = expf(g_s2[(size_t)e * 2 + h]) / g_Z2[c * 2 + h];
    float wt = -0.125f * p;
    const float4 q = *(const float4*)(g_P + (size_t)c * PW + lane * 4);
    const float4 k = *(const float4*)(g_P + (size_t)u * PW + 128 + lane * 4);
    red_add_v4(g_U + (size_t)c * PW + lane * 4, wt * k.x, wt * k.y, wt * k.z, wt * k.w);
    red_add_v4(g_U + (size_t)u * PW + 128 + lane * 4, wt * q.x, wt * q.y, wt * q.z, wt * q.w);
}

// ---------------------------------------------------------------------------
// Motif forward: warp per motif. 8 dims/lane; groups of 8 lanes = (h,r).
// ---------------------------------------------------------------------------
__global__ void k_motif_fwd(const int* __restrict__ c3, const int* __restrict__ u3,
                            const int* __restrict__ v3, const int* __restrict__ tt,
                            const float* __restrict__ Ttau) {
    int m = (blockIdx.x * 256 + threadIdx.x) >> 5;
    int lane = threadIdx.x & 31;
    if (m >= Mm) return;
    int c = c3[m], ua = u3[m], vb = v3[m], t = tt[m];
    int off = lane * 8;
    const float* q  = g_P + (size_t)c  * PW + 256 + off;
    const float* ku = g_P + (size_t)ua * PW + 512 + off;
    const float* kv = g_P + (size_t)vb * PW + 512 + off;
    const float* tp = Ttau + t * 256 + off;
    float qk = 0.f, tv = 0.f;
#pragma unroll
    for (int i = 0; i < 8; i += 4) {
        float4 qv = *(const float4*)(q + i);
        float4 kuv = *(const float4*)(ku + i);
        float4 kvv = *(const float4*)(kv + i);
        float4 tv4 = *(const float4*)(tp + i);
        qk += qv.x * kuv.x + qv.y * kuv.y + qv.z * kuv.z + qv.w * kuv.w;
        tv += tv4.x * kvv.x + tv4.y * kvv.y + tv4.z * kvv.z + tv4.w * kvv.w;
    }
    qk = wsum8(qk);
    tv = wsum8(tv);
    int g = lane >> 3;
    if ((lane & 7) == 0) {
        g_qk[(size_t)m * 4 + g] = qk;
        g_tv[(size_t)m * 4 + g] = tv;
    }
    float qk0 = __shfl_sync(0xffffffffu, qk, 0),  tv0 = __shfl_sync(0xffffffffu, tv, 0);
    float qk1 = __shfl_sync(0xffffffffu, qk, 8),  tv1 = __shfl_sync(0xffffffffu, tv, 8);
    float qk2 = __shfl_sync(0xffffffffu, qk, 16), tv2 = __shfl_sync(0xffffffffu, tv, 16);
    float qk3 = __shfl_sync(0xffffffffu, qk, 24), tv3 = __shfl_sync(0xffffffffu, tv, 24);
    if (lane < 2) {
        float s3 = (lane == 0) ? (qk0 * tv0 + qk1 * tv1) * (1.0f / 64)
                               : (qk2 * tv2 + qk3 * tv3) * (1.0f / 64);
        g_s3[(size_t)m * 2 + lane] = s3;
        atomicAdd(&g_Z3[c * 2 + lane], expf(s3));
    }
}

// Motif backward (vector loads + vector RED)
__global__ void k_motif_bwd(const int* __restrict__ c3, const int* __restrict__ u3,
                            const int* __restrict__ v3, const int* __restrict__ tt,
                            const float* __restrict__ Ttau) {
    int m = (blockIdx.x * 256 + threadIdx.x) >> 5;
    int lane = threadIdx.x & 31;
    if (m >= Mm) return;
    int c = c3[m], ua = u3[m], vb = v3[m], t = tt[m];
    int g = lane >> 3;
    int h = g >> 1;
    float p = expf(g_s3[(size_t)m * 2 + h]) / g_Z3[c * 2 + h];
    float gg = -LAM3 * p * (1.0f / 64);
    float cA = gg * g_tv[(size_t)m * 4 + g];
    float cB = gg * g_qk[(size_t)m * 4 + g];
    int off = lane * 8;
    const float* q  = g_P + (size_t)c  * PW + 256 + off;
    const float* ku = g_P + (size_t)ua * PW + 512 + off;
    const float* tp = Ttau + t * 256 + off;
    float* dq  = g_U + (size_t)c  * PW + 256 + off;
    float* dku = g_U + (size_t)ua * PW + 512 + off;
    float* dkv = g_U + (size_t)vb * PW + 512 + off;
#pragma unroll
    for (int i = 0; i < 8; i += 4) {
        float4 qv  = *(const float4*)(q + i);
        float4 kuv = *(const float4*)(ku + i);
        float4 tv4 = *(const float4*)(tp + i);
        red_add_v4(dq + i,  cA * kuv.x, cA * kuv.y, cA * kuv.z, cA * kuv.w);
        red_add_v4(dku + i, cA * qv.x,  cA * qv.y,  cA * qv.z,  cA * qv.w);
        red_add_v4(dkv + i, cB * tv4.x, cB * tv4.y, cB * tv4.z, cB * tv4.w);
    }
}

// ---------------------------------------------------------------------------
// Memory term: warp per (node, head). Computes Lm and dQm directly (no atomics)
// ---------------------------------------------------------------------------
__global__ void k_mem() {
    int w = (blockIdx.x * 256 + threadIdx.x) >> 5;
    int lane = threadIdx.x & 31;
    if (w >= Nn * Hh) return;
    int n = w >> 1, h = w & 1;
    const float* qm = g_P + (size_t)n * PW + 768 + h * HDm;
    const float* kt = g_KmT + h * HDm * KSL;   // [z][k]
    const float* km = g_Km + h * KSL * HDm;    // [k][z]
    float sm = 0.f;
#pragma unroll 8
    for (int z = 0; z < HDm; z++) sm += qm[z] * kt[z * KSL + lane];
    sm *= 0.125f;
    float e = expf(sm);
    float Z = wsum32(e);
    float p = e / Z;
    if (lane == 0) g_Lm[w] = logf(Z);
    float a0 = 0.f, a1 = 0.f;
#pragma unroll
    for (int kk = 0; kk < KSL; kk++) {
        float pk = __shfl_sync(0xffffffffu, p, kk);
        a0 += pk * km[kk * HDm + lane];
        a1 += pk * km[kk * HDm + lane + 32];
    }
    float* du = g_U + (size_t)n * PW + 768 + h * HDm;
    du[lane] = -0.125f * a0;
    du[lane + 32] = -0.125f * a1;
}

// ---------------------------------------------------------------------------
// Per-node energy + per-graph reduction (block-local bins)
// ---------------------------------------------------------------------------
__global__ void k_energy(const float* __restrict__ X, const int* __restrict__ batch,
                         float* __restrict__ Eg) {
    __shared__ float bins[NGg];
    int tid = threadIdx.x;
    if (tid < NGg) bins[tid] = 0.f;
    __syncthreads();
    int w = (blockIdx.x * 256 + tid) >> 5;
    int lane = tid & 31;
    if (w < Nn) {
        const float4 x = *(const float4*)(X + (size_t)w * Dd + lane * 4);
        float ss = wsum32(x.x * x.x + x.y * x.y + x.z * x.z + x.w * x.w);
        if (lane == 0) {
            float e = 0.5f * ss;
            float z0 = g_Z2[w * 2], z1 = g_Z2[w * 2 + 1];
            e -= (z0 > 0.f ? logf(z0) : 0.f) + (z1 > 0.f ? logf(z1) : 0.f);
            float y0 = g_Z3[w * 2], y1 = g_Z3[w * 2 + 1];
            e -= LAM3 * ((y0 > 0.f ? logf(y0) : 0.f) + (y1 > 0.f ? logf(y1) : 0.f));
            e -= g_Lm[w * 2] + g_Lm[w * 2 + 1];
            atomicAdd(&bins[batch[w]], e);
        }
    }
    __syncthreads();
    if (tid < NGg) atomicAdd(&Eg[tid], bins[tid]);
}

// ---------------------------------------------------------------------------
// LN backward + grad clip + step + state clip (warp per row)
// ---------------------------------------------------------------------------
__global__ void k_final(const float* __restrict__ X, const float* __restrict__ gamma,
                        const float* __restrict__ step, float* __restrict__ out) {
    int w = (blockIdx.x * blockDim.x + threadIdx.x) >> 5;
    int lane = threadIdx.x & 31;
    if (w >= Nn) return;
    const float4 x = *(const float4*)(X + (size_t)w * Dd + lane * 4);
    const float4 dg = *(const float4*)(g_dG + (size_t)w * Dd + lane * 4);
    const float4 gm = *(const float4*)(gamma + lane * 4);
    float mu = g_mu[w], rstd = g_rstd[w];
    float4 xh = make_float4((x.x - mu) * rstd, (x.y - mu) * rstd,
                            (x.z - mu) * rstd, (x.w - mu) * rstd);
    float4 dxh = make_float4(dg.x * gm.x, dg.y * gm.y, dg.z * gm.z, dg.w * gm.w);
    float S1 = wsum32(dxh.x + dxh.y + dxh.z + dxh.w) * (1.0f / Dd);
    float S2 = wsum32(dxh.x * xh.x + dxh.y * xh.y + dxh.z * xh.z + dxh.w * xh.w) * (1.0f / Dd);
    float4 g;
    g.x = x.x + rstd * (dxh.x - S1 - xh.x * S2);
    g.y = x.y + rstd * (dxh.y - S1 - xh.y * S2);
    g.z = x.z + rstd * (dxh.z - S1 - xh.z * S2);
    g.w = x.w + rstd * (dxh.w - S1 - xh.w * S2);
    float gss = wsum32(g.x * g.x + g.y * g.y + g.z * g.z + g.w * g.w);
    float sc1 = 1.0f / fmaxf(sqrtf(gss), 1.0f);   // GRAD_CLIP = 1
    float st = step[0] * sc1;                      // DAMPING = 1
    float4 xn = make_float4(x.x - st * g.x, x.y - st * g.y,
                            x.z - st * g.z, x.w - st * g.w);
    float sn = wsum32(xn.x * xn.x + xn.y * xn.y + xn.z * xn.z + xn.w * xn.w);
    float sc2 = 10.0f / fmaxf(sqrtf(sn), 10.0f);  // STATE_CLIP = 10
    float4 o = make_float4(xn.x * sc2, xn.y * sc2, xn.z * sc2, xn.w * sc2);
    *(float4*)(out + (size_t)w * Dd + lane * 4) = o;
}

// ---------------------------------------------------------------------------
// Launch
// ---------------------------------------------------------------------------
extern "C" void kernel_launch(void* const* d_in, const int* in_sizes, int n_in,
                              void* d_out, int out_size) {
    const float* X    = (const float*)d_in[0];
    const int* c2     = (const int*)d_in[1];
    const int* u2     = (const int*)d_in[2];
    const int* c3     = (const int*)d_in[3];
    const int* u3     = (const int*)d_in[4];
    const int* v3     = (const int*)d_in[5];
    const int* tt     = (const int*)d_in[6];
    const int* batch  = (const int*)d_in[7];
    const float* a2   = (const float*)d_in[8];
    const float* step = (const float*)d_in[9];
    const float* gamma= (const float*)d_in[10];
    const float* beta = (const float*)d_in[11];
    const float* WQ2  = (const float*)d_in[12];
    const float* WK2  = (const float*)d_in[13];
    const float* WQ3  = (const float*)d_in[14];
    const float* WK3  = (const float*)d_in[15];
    const float* Ttau = (const float*)d_in[16];
    const float* WQm  = (const float*)d_in[17];
    const float* WKm  = (const float*)d_in[18];
    const float* Bmem = (const float*)d_in[19];
    float* out = (float*)d_out;
    float* Eg  = out + (size_t)Nn * Dd;

    void *pU, *pZ2, *pZ3, *pG, *pP, *pWc, *pWcT, *pdG;
    cudaGetSymbolAddress(&pU, g_U);
    cudaGetSymbolAddress(&pZ2, g_Z2);
    cudaGetSymbolAddress(&pZ3, g_Z3);
    cudaGetSymbolAddress(&pG, g_G);
    cudaGetSymbolAddress(&pP, g_P);
    cudaGetSymbolAddress(&pWc, g_Wcat);
    cudaGetSymbolAddress(&pWcT, g_WcatT);
    cudaGetSymbolAddress(&pdG, g_dG);

    cudaMemsetAsync(pU, 0, sizeof(float) * (size_t)Nn * PW);
    cudaMemsetAsync(pZ2, 0, sizeof(float) * Nn * Hh);
    cudaMemsetAsync(pZ3, 0, sizeof(float) * Nn * Hh);
    cudaMemsetAsync(Eg, 0, sizeof(float) * NGg);

    k_ln<<<Nn / 8, 256>>>(X, gamma, beta);
    k_wcat<<<(PW * Dd + 255) / 256, 256>>>(WQ2, WK2, WQ3, WK3, WQm);
    k_km<<<(Hh * KSL * HDm + 255) / 256, 256>>>(Bmem, WKm);

    // Forward projections: P = G[N,128] x WcatT[128,896]
    k_gemm128<<<dim3(PW / 128, Nn / 128), 256>>>((const float*)pG, Dd,
                                                 (const float*)pWcT, PW,
                                                 (float*)pP, PW, Dd);

    k_pair_fwd<<<Ee / 8, 256>>>(c2, u2, a2);
    k_motif_fwd<<<Mm / 8, 256>>>(c3, u3, v3, tt, Ttau);
    k_mem<<<(Nn * Hh) / 8, 256>>>();

    k_energy<<<Nn / 8, 256>>>(X, batch, Eg);

    k_pair_bwd<<<Ee / 8, 256>>>(c2, u2);
    k_motif_bwd<<<Mm / 8, 256>>>(c3, u3, v3, tt, Ttau);

    // Backward projections: dG = U[N,896] x Wcat[896,128]
    k_gemm128<<<dim3(Dd / 128, Nn / 128), 256>>>((const float*)pU, PW,
                                                 (const float*)pWc, Dd,
                                                 (float*)pdG, Dd, PW);

    k_final<<<Nn / 8, 256>>>(X, gamma, step, out);
}

// round 5
// speedup vs baseline: 2.2463x; 1.3422x over previous
#include <cuda_runtime.h>
#include <math.h>
#include <stdint.h>

// ---------------------------------------------------------------------------
// Problem constants (shapes fixed by the dataset)
// ---------------------------------------------------------------------------
#define Nn   32768
#define Dd   128
#define Hh   2
#define HDm  64
#define Ee   262144
#define Mm   131072
#define NGg  32
#define PW   896          // 128(Q2)+128(K2)+256(Q3)+256(K3)+128(Qm)
#define KSL  32           // memory slots
#define LAM3 0.5f
#define EPSV 1e-5f

// ---------------------------------------------------------------------------
// Scratch (static device globals; no runtime allocation allowed)
// ---------------------------------------------------------------------------
__device__ float g_G[(size_t)Nn * Dd];
__device__ float g_mu[Nn];
__device__ float g_rstd[Nn];
__device__ float g_P[(size_t)Nn * PW];     // [Q2 | K2 | Q3 | K3 | Qm] per node
__device__ float g_U[(size_t)Nn * PW];     // grads wrt the projections
__device__ float g_dG[(size_t)Nn * Dd];
__device__ float g_Wcat[PW * Dd];
__device__ float g_WcatT[Dd * PW];
__device__ float g_Km[Hh * KSL * HDm];     // [h][k][z]
__device__ float g_KmT[Hh * HDm * KSL];    // [h][z][k]
__device__ float g_s2[(size_t)Ee * Hh];
__device__ float g_Z2[Nn * Hh];
__device__ float g_qk[(size_t)Mm * 4];
__device__ float g_tv[(size_t)Mm * 4];
__device__ float g_s3[(size_t)Mm * Hh];
__device__ float g_Z3[Nn * Hh];
__device__ float g_Lm[Nn * Hh];

// ---------------------------------------------------------------------------
// Helpers
// ---------------------------------------------------------------------------
__device__ __forceinline__ float wsum32(float v) {
#pragma unroll
    for (int m = 16; m > 0; m >>= 1) v += __shfl_xor_sync(0xffffffffu, v, m);
    return v;
}
__device__ __forceinline__ float wsum16(float v) {
#pragma unroll
    for (int m = 8; m > 0; m >>= 1) v += __shfl_xor_sync(0xffffffffu, v, m);
    return v;
}
__device__ __forceinline__ float wsum8(float v) {
#pragma unroll
    for (int m = 4; m > 0; m >>= 1) v += __shfl_xor_sync(0xffffffffu, v, m);
    return v;
}
__device__ __forceinline__ void red_add_v4(float* addr, float a, float b, float c, float d) {
    asm volatile("red.global.add.v4.f32 [%0], {%1, %2, %3, %4};"
                 :: "l"(addr), "f"(a), "f"(b), "f"(c), "f"(d) : "memory");
}
__device__ __forceinline__ float totf32(float x) {
    uint32_t r;
    asm("cvt.rna.tf32.f32 %0, %1;" : "=r"(r) : "f"(x));
    return __uint_as_float(r);
}

// ---------------------------------------------------------------------------
// LayerNorm forward (warp per row), saves mu/rstd
// ---------------------------------------------------------------------------
__global__ void k_ln(const float* __restrict__ X, const float* __restrict__ gamma,
                     const float* __restrict__ beta) {
    int w = (blockIdx.x * blockDim.x + threadIdx.x) >> 5;
    int lane = threadIdx.x & 31;
    if (w >= Nn) return;
    const float4 x = *(const float4*)(X + (size_t)w * Dd + lane * 4);
    float s = x.x + x.y + x.z + x.w;
    float mu = wsum32(s) * (1.0f / Dd);
    float4 xc = make_float4(x.x - mu, x.y - mu, x.z - mu, x.w - mu);
    float v = xc.x * xc.x + xc.y * xc.y + xc.z * xc.z + xc.w * xc.w;
    v = wsum32(v) * (1.0f / Dd);
    float rstd = rsqrtf(v + EPSV);
    const float4 g4 = *(const float4*)(gamma + lane * 4);
    const float4 b4 = *(const float4*)(beta + lane * 4);
    float4 G;
    G.x = g4.x * xc.x * rstd + b4.x;
    G.y = g4.y * xc.y * rstd + b4.y;
    G.z = g4.z * xc.z * rstd + b4.z;
    G.w = g4.w * xc.w * rstd + b4.w;
    *(float4*)(g_G + (size_t)w * Dd + lane * 4) = G;
    if (lane == 0) { g_mu[w] = mu; g_rstd[w] = rstd; }
}

// ---------------------------------------------------------------------------
// Build stacked weight matrix (and its transpose)
// ---------------------------------------------------------------------------
__global__ void k_wcat(const float* __restrict__ WQ2, const float* __restrict__ WK2,
                       const float* __restrict__ WQ3, const float* __restrict__ WK3,
                       const float* __restrict__ WQm) {
    int idx = blockIdx.x * blockDim.x + threadIdx.x;
    if (idx >= PW * Dd) return;
    int j = idx / Dd, d = idx - j * Dd;
    float v;
    if (j < 128)      v = WQ2[j * Dd + d];
    else if (j < 256) v = WK2[(j - 128) * Dd + d];
    else if (j < 512) v = WQ3[(j - 256) * Dd + d];
    else if (j < 768) v = WK3[(j - 512) * Dd + d];
    else              v = WQm[(j - 768) * Dd + d];
    g_Wcat[j * Dd + d] = v;
    g_WcatT[d * PW + j] = v;
}

// ---------------------------------------------------------------------------
// Km = B_mem @ W_Km^T per head (tiny), both layouts
// ---------------------------------------------------------------------------
__global__ void k_km(const float* __restrict__ Bm, const float* __restrict__ WKm) {
    int idx = blockIdx.x * blockDim.x + threadIdx.x;
    if (idx >= Hh * KSL * HDm) return;
    int h = idx / (KSL * HDm);
    int k = (idx / HDm) % KSL;
    int z = idx % HDm;
    const float* b = Bm + k * Dd;
    const float* w = WKm + (h * HDm + z) * Dd;
    float acc = 0.f;
#pragma unroll 8
    for (int d = 0; d < Dd; d++) acc += b[d] * w[d];
    g_Km[idx] = acc;
    g_KmT[(h * HDm + z) * KSL + k] = acc;
}

// ---------------------------------------------------------------------------
// TF32 tensor-core GEMM: C[M,J] = A[M,K] * B[K,J], row-major.
// Block 128x128x16, 8 warps, warp tile 64x32 (4x4 m16n8k8 frags).
// Double-buffered smem; A stored [m][k] pad 20, B stored [k][n] pad 136.
// M,J multiples of 128; K multiple of 16.
// ---------------------------------------------------------------------------
__global__ void __launch_bounds__(256)
k_gemm_tf32(const float* __restrict__ A, int lda,
            const float* __restrict__ B, int ldb,
            float* __restrict__ C, int ldc, int Kdim) {
    __shared__ float As[2][128][20];
    __shared__ float Bs[2][16][136];
    int tid = threadIdx.x;
    int warp = tid >> 5, lane = tid & 31;
    int g = lane >> 2, tg = lane & 3;
    int wm = (warp >> 2) * 64;      // 0 or 64
    int wn = (warp & 3) * 32;       // 0,32,64,96
    int row0 = blockIdx.y * 128, col0 = blockIdx.x * 128;

    // global load indexing
    int ar = tid >> 2;              // 0..63 (+64 second pass)
    int ac = (tid & 3) * 4;         // 0,4,8,12
    int br = tid >> 5;              // 0..7 (+8 second pass)
    int bc = lane * 4;              // 0..124
    const float* Ap0 = A + (size_t)(row0 + ar) * lda + ac;
    const float* Ap1 = Ap0 + (size_t)64 * lda;
    const float* Bp0 = B + (size_t)br * ldb + col0 + bc;
    const float* Bp1 = Bp0 + (size_t)8 * ldb;

    float acc[16][4];
#pragma unroll
    for (int i = 0; i < 16; i++)
#pragma unroll
        for (int j = 0; j < 4; j++) acc[i][j] = 0.f;

    // preload tile 0
    float4 a0v = *(const float4*)(Ap0);
    float4 a1v = *(const float4*)(Ap1);
    float4 b0v = *(const float4*)(Bp0);
    float4 b1v = *(const float4*)(Bp1);
    {
        float* d0 = &As[0][ar][ac];
        d0[0] = totf32(a0v.x); d0[1] = totf32(a0v.y); d0[2] = totf32(a0v.z); d0[3] = totf32(a0v.w);
        float* d1 = &As[0][64 + ar][ac];
        d1[0] = totf32(a1v.x); d1[1] = totf32(a1v.y); d1[2] = totf32(a1v.z); d1[3] = totf32(a1v.w);
        float* e0 = &Bs[0][br][bc];
        e0[0] = totf32(b0v.x); e0[1] = totf32(b0v.y); e0[2] = totf32(b0v.z); e0[3] = totf32(b0v.w);
        float* e1 = &Bs[0][8 + br][bc];
        e1[0] = totf32(b1v.x); e1[1] = totf32(b1v.y); e1[2] = totf32(b1v.z); e1[3] = totf32(b1v.w);
    }
    __syncthreads();

    int nk = Kdim >> 4;
    for (int kt = 0; kt < nk; kt++) {
        int cur = kt & 1, nxt = cur ^ 1;
        if (kt + 1 < nk) {
            a0v = *(const float4*)(Ap0 + (kt + 1) * 16);
            a1v = *(const float4*)(Ap1 + (kt + 1) * 16);
            b0v = *(const float4*)(Bp0 + (size_t)(kt + 1) * 16 * ldb);
            b1v = *(const float4*)(Bp1 + (size_t)(kt + 1) * 16 * ldb);
        }
#pragma unroll
        for (int kk = 0; kk < 2; kk++) {
            int k0 = kk * 8;
            uint32_t af[4][4];   // [mi][4 regs]
            uint32_t bf[4][2];   // [ni][2 regs]
#pragma unroll
            for (int mi = 0; mi < 4; mi++) {
                int r = wm + mi * 16 + g;
                af[mi][0] = __float_as_uint(As[cur][r][k0 + tg]);
                af[mi][1] = __float_as_uint(As[cur][r + 8][k0 + tg]);
                af[mi][2] = __float_as_uint(As[cur][r][k0 + tg + 4]);
                af[mi][3] = __float_as_uint(As[cur][r + 8][k0 + tg + 4]);
            }
#pragma unroll
            for (int ni = 0; ni < 4; ni++) {
                int n = wn + ni * 8 + g;
                bf[ni][0] = __float_as_uint(Bs[cur][k0 + tg][n]);
                bf[ni][1] = __float_as_uint(Bs[cur][k0 + tg + 4][n]);
            }
#pragma unroll
            for (int mi = 0; mi < 4; mi++)
#pragma unroll
                for (int ni = 0; ni < 4; ni++) {
                    float* c = acc[mi * 4 + ni];
                    asm volatile(
                        "mma.sync.aligned.m16n8k8.row.col.f32.tf32.tf32.f32 "
                        "{%0,%1,%2,%3}, {%4,%5,%6,%7}, {%8,%9}, {%0,%1,%2,%3};"
                        : "+f"(c[0]), "+f"(c[1]), "+f"(c[2]), "+f"(c[3])
                        : "r"(af[mi][0]), "r"(af[mi][1]), "r"(af[mi][2]), "r"(af[mi][3]),
                          "r"(bf[ni][0]), "r"(bf[ni][1]));
                }
        }
        if (kt + 1 < nk) {
            float* d0 = &As[nxt][ar][ac];
            d0[0] = totf32(a0v.x); d0[1] = totf32(a0v.y); d0[2] = totf32(a0v.z); d0[3] = totf32(a0v.w);
            float* d1 = &As[nxt][64 + ar][ac];
            d1[0] = totf32(a1v.x); d1[1] = totf32(a1v.y); d1[2] = totf32(a1v.z); d1[3] = totf32(a1v.w);
            float* e0 = &Bs[nxt][br][bc];
            e0[0] = totf32(b0v.x); e0[1] = totf32(b0v.y); e0[2] = totf32(b0v.z); e0[3] = totf32(b0v.w);
            float* e1 = &Bs[nxt][8 + br][bc];
            e1[0] = totf32(b1v.x); e1[1] = totf32(b1v.y); e1[2] = totf32(b1v.z); e1[3] = totf32(b1v.w);
            __syncthreads();
        }
    }

    // epilogue: c0 (g, 2tg), c1 (g, 2tg+1), c2 (g+8, 2tg), c3 (g+8, 2tg+1)
#pragma unroll
    for (int mi = 0; mi < 4; mi++)
#pragma unroll
        for (int ni = 0; ni < 4; ni++) {
            float* c = acc[mi * 4 + ni];
            int r = row0 + wm + mi * 16 + g;
            int col = col0 + wn + ni * 8 + 2 * tg;
            *(float2*)(C + (size_t)r * ldc + col) = make_float2(c[0], c[1]);
            *(float2*)(C + (size_t)(r + 8) * ldc + col) = make_float2(c[2], c[3]);
        }
}

// ---------------------------------------------------------------------------
// Pair term forward: warp per edge. s2[e,h] = Q2[c]·K2[u]/8 + a2; Z2 += exp(s2)
// ---------------------------------------------------------------------------
__global__ void k_pair_fwd(const int* __restrict__ c2, const int* __restrict__ u2,
                           const float* __restrict__ a2) {
    int e = (blockIdx.x * 256 + threadIdx.x) >> 5;
    int lane = threadIdx.x & 31;
    if (e >= Ee) return;
    int c = c2[e], u = u2[e];
    const float4 q = *(const float4*)(g_P + (size_t)c * PW + lane * 4);
    const float4 k = *(const float4*)(g_P + (size_t)u * PW + 128 + lane * 4);
    float part = q.x * k.x + q.y * k.y + q.z * k.z + q.w * k.w;
    part = wsum16(part);
    int h = lane >> 4;
    if ((lane & 15) == 0) {
        float s = part * 0.125f + a2[e * 2 + h];
        g_s2[(size_t)e * 2 + h] = s;
        atomicAdd(&g_Z2[c * 2 + h], expf(s));
    }
}

// Pair backward: dQ2[c] += w*K2[u], dK2[u] += w*Q2[c], w = -p/8  (vector RED)
__global__ void k_pair_bwd(const int* __restrict__ c2, const int* __restrict__ u2) {
    int e = (blockIdx.x * 256 + threadIdx.x) >> 5;
    int lane = threadIdx.x & 31;
    if (e >= Ee) return;
    int c = c2[e], u = u2[e];
    int h = lane >> 4;
    float p = expf(g_s2[(size_t)e * 2 + h]) / g_Z2[c * 2 + h];
    float wt = -0.125f * p;
    const float4 q = *(const float4*)(g_P + (size_t)c * PW + lane * 4);
    const float4 k = *(const float4*)(g_P + (size_t)u * PW + 128 + lane * 4);
    red_add_v4(g_U + (size_t)c * PW + lane * 4, wt * k.x, wt * k.y, wt * k.z, wt * k.w);
    red_add_v4(g_U + (size_t)u * PW + 128 + lane * 4, wt * q.x, wt * q.y, wt * q.z, wt * q.w);
}

// ---------------------------------------------------------------------------
// Motif forward: warp per motif. 8 dims/lane; groups of 8 lanes = (h,r).
// ---------------------------------------------------------------------------
__global__ void k_motif_fwd(const int* __restrict__ c3, const int* __restrict__ u3,
                            const int* __restrict__ v3, const int* __restrict__ tt,
                            const float* __restrict__ Ttau) {
    int m = (blockIdx.x * 256 + threadIdx.x) >> 5;
    int lane = threadIdx.x & 31;
    if (m >= Mm) return;
    int c = c3[m], ua = u3[m], vb = v3[m], t = tt[m];
    int off = lane * 8;
    const float* q  = g_P + (size_t)c  * PW + 256 + off;
    const float* ku = g_P + (size_t)ua * PW + 512 + off;
    const float* kv = g_P + (size_t)vb * PW + 512 + off;
    const float* tp = Ttau + t * 256 + off;
    float qk = 0.f, tv = 0.f;
#pragma unroll
    for (int i = 0; i < 8; i += 4) {
        float4 qv = *(const float4*)(q + i);
        float4 kuv = *(const float4*)(ku + i);
        float4 kvv = *(const float4*)(kv + i);
        float4 tv4 = *(const float4*)(tp + i);
        qk += qv.x * kuv.x + qv.y * kuv.y + qv.z * kuv.z + qv.w * kuv.w;
        tv += tv4.x * kvv.x + tv4.y * kvv.y + tv4.z * kvv.z + tv4.w * kvv.w;
    }
    qk = wsum8(qk);
    tv = wsum8(tv);
    int g = lane >> 3;
    if ((lane & 7) == 0) {
        g_qk[(size_t)m * 4 + g] = qk;
        g_tv[(size_t)m * 4 + g] = tv;
    }
    float qk0 = __shfl_sync(0xffffffffu, qk, 0),  tv0 = __shfl_sync(0xffffffffu, tv, 0);
    float qk1 = __shfl_sync(0xffffffffu, qk, 8),  tv1 = __shfl_sync(0xffffffffu, tv, 8);
    float qk2 = __shfl_sync(0xffffffffu, qk, 16), tv2 = __shfl_sync(0xffffffffu, tv, 16);
    float qk3 = __shfl_sync(0xffffffffu, qk, 24), tv3 = __shfl_sync(0xffffffffu, tv, 24);
    if (lane < 2) {
        float s3 = (lane == 0) ? (qk0 * tv0 + qk1 * tv1) * (1.0f / 64)
                               : (qk2 * tv2 + qk3 * tv3) * (1.0f / 64);
        g_s3[(size_t)m * 2 + lane] = s3;
        atomicAdd(&g_Z3[c * 2 + lane], expf(s3));
    }
}

// Motif backward (vector loads + vector RED)
__global__ void k_motif_bwd(const int* __restrict__ c3, const int* __restrict__ u3,
                            const int* __restrict__ v3, const int* __restrict__ tt,
                            const float* __restrict__ Ttau) {
    int m = (blockIdx.x * 256 + threadIdx.x) >> 5;
    int lane = threadIdx.x & 31;
    if (m >= Mm) return;
    int c = c3[m], ua = u3[m], vb = v3[m], t = tt[m];
    int g = lane >> 3;
    int h = g >> 1;
    float p = expf(g_s3[(size_t)m * 2 + h]) / g_Z3[c * 2 + h];
    float gg = -LAM3 * p * (1.0f / 64);
    float cA = gg * g_tv[(size_t)m * 4 + g];
    float cB = gg * g_qk[(size_t)m * 4 + g];
    int off = lane * 8;
    const float* q  = g_P + (size_t)c  * PW + 256 + off;
    const float* ku = g_P + (size_t)ua * PW + 512 + off;
    const float* tp = Ttau + t * 256 + off;
    float* dq  = g_U + (size_t)c  * PW + 256 + off;
    float* dku = g_U + (size_t)ua * PW + 512 + off;
    float* dkv = g_U + (size_t)vb * PW + 512 + off;
#pragma unroll
    for (int i = 0; i < 8; i += 4) {
        float4 qv  = *(const float4*)(q + i);
        float4 kuv = *(const float4*)(ku + i);
        float4 tv4 = *(const float4*)(tp + i);
        red_add_v4(dq + i,  cA * kuv.x, cA * kuv.y, cA * kuv.z, cA * kuv.w);
        red_add_v4(dku + i, cA * qv.x,  cA * qv.y,  cA * qv.z,  cA * qv.w);
        red_add_v4(dkv + i, cB * tv4.x, cB * tv4.y, cB * tv4.z, cB * tv4.w);
    }
}

// ---------------------------------------------------------------------------
// Memory term: warp per (node, head). Computes Lm and dQm directly (no atomics)
// ---------------------------------------------------------------------------
__global__ void k_mem() {
    int w = (blockIdx.x * 256 + threadIdx.x) >> 5;
    int lane = threadIdx.x & 31;
    if (w >= Nn * Hh) return;
    int n = w >> 1, h = w & 1;
    const float* qm = g_P + (size_t)n * PW + 768 + h * HDm;
    const float* kt = g_KmT + h * HDm * KSL;   // [z][k]
    const float* km = g_Km + h * KSL * HDm;    // [k][z]
    float sm = 0.f;
#pragma unroll 8
    for (int z = 0; z < HDm; z++) sm += qm[z] * kt[z * KSL + lane];
    sm *= 0.125f;
    float e = expf(sm);
    float Z = wsum32(e);
    float p = e / Z;
    if (lane == 0) g_Lm[w] = logf(Z);
    float a0 = 0.f, a1 = 0.f;
#pragma unroll
    for (int kk = 0; kk < KSL; kk++) {
        float pk = __shfl_sync(0xffffffffu, p, kk);
        a0 += pk * km[kk * HDm + lane];
        a1 += pk * km[kk * HDm + lane + 32];
    }
    float* du = g_U + (size_t)n * PW + 768 + h * HDm;
    du[lane] = -0.125f * a0;
    du[lane + 32] = -0.125f * a1;
}

// ---------------------------------------------------------------------------
// Per-node energy + per-graph reduction (block-local bins)
// ---------------------------------------------------------------------------
__global__ void k_energy(const float* __restrict__ X, const int* __restrict__ batch,
                         float* __restrict__ Eg) {
    __shared__ float bins[NGg];
    int tid = threadIdx.x;
    if (tid < NGg) bins[tid] = 0.f;
    __syncthreads();
    int w = (blockIdx.x * 256 + tid) >> 5;
    int lane = tid & 31;
    if (w < Nn) {
        const float4 x = *(const float4*)(X + (size_t)w * Dd + lane * 4);
        float ss = wsum32(x.x * x.x + x.y * x.y + x.z * x.z + x.w * x.w);
        if (lane == 0) {
            float e = 0.5f * ss;
            float z0 = g_Z2[w * 2], z1 = g_Z2[w * 2 + 1];
            e -= (z0 > 0.f ? logf(z0) : 0.f) + (z1 > 0.f ? logf(z1) : 0.f);
            float y0 = g_Z3[w * 2], y1 = g_Z3[w * 2 + 1];
            e -= LAM3 * ((y0 > 0.f ? logf(y0) : 0.f) + (y1 > 0.f ? logf(y1) : 0.f));
            e -= g_Lm[w * 2] + g_Lm[w * 2 + 1];
            atomicAdd(&bins[batch[w]], e);
        }
    }
    __syncthreads();
    if (tid < NGg) atomicAdd(&Eg[tid], bins[tid]);
}

// ---------------------------------------------------------------------------
// LN backward + grad clip + step + state clip (warp per row)
// ---------------------------------------------------------------------------
__global__ void k_final(const float* __restrict__ X, const float* __restrict__ gamma,
                        const float* __restrict__ step, float* __restrict__ out) {
    int w = (blockIdx.x * blockDim.x + threadIdx.x) >> 5;
    int lane = threadIdx.x & 31;
    if (w >= Nn) return;
    const float4 x = *(const float4*)(X + (size_t)w * Dd + lane * 4);
    const float4 dg = *(const float4*)(g_dG + (size_t)w * Dd + lane * 4);
    const float4 gm = *(const float4*)(gamma + lane * 4);
    float mu = g_mu[w], rstd = g_rstd[w];
    float4 xh = make_float4((x.x - mu) * rstd, (x.y - mu) * rstd,
                            (x.z - mu) * rstd, (x.w - mu) * rstd);
    float4 dxh = make_float4(dg.x * gm.x, dg.y * gm.y, dg.z * gm.z, dg.w * gm.w);
    float S1 = wsum32(dxh.x + dxh.y + dxh.z + dxh.w) * (1.0f / Dd);
    float S2 = wsum32(dxh.x * xh.x + dxh.y * xh.y + dxh.z * xh.z + dxh.w * xh.w) * (1.0f / Dd);
    float4 g;
    g.x = x.x + rstd * (dxh.x - S1 - xh.x * S2);
    g.y = x.y + rstd * (dxh.y - S1 - xh.y * S2);
    g.z = x.z + rstd * (dxh.z - S1 - xh.z * S2);
    g.w = x.w + rstd * (dxh.w - S1 - xh.w * S2);
    float gss = wsum32(g.x * g.x + g.y * g.y + g.z * g.z + g.w * g.w);
    float sc1 = 1.0f / fmaxf(sqrtf(gss), 1.0f);   // GRAD_CLIP = 1
    float st = step[0] * sc1;                      // DAMPING = 1
    float4 xn = make_float4(x.x - st * g.x, x.y - st * g.y,
                            x.z - st * g.z, x.w - st * g.w);
    float sn = wsum32(xn.x * xn.x + xn.y * xn.y + xn.z * xn.z + xn.w * xn.w);
    float sc2 = 10.0f / fmaxf(sqrtf(sn), 10.0f);  // STATE_CLIP = 10
    float4 o = make_float4(xn.x * sc2, xn.y * sc2, xn.z * sc2, xn.w * sc2);
    *(float4*)(out + (size_t)w * Dd + lane * 4) = o;
}

// ---------------------------------------------------------------------------
// Launch
// ---------------------------------------------------------------------------
extern "C" void kernel_launch(void* const* d_in, const int* in_sizes, int n_in,
                              void* d_out, int out_size) {
    const float* X    = (const float*)d_in[0];
    const int* c2     = (const int*)d_in[1];
    const int* u2     = (const int*)d_in[2];
    const int* c3     = (const int*)d_in[3];
    const int* u3     = (const int*)d_in[4];
    const int* v3     = (const int*)d_in[5];
    const int* tt     = (const int*)d_in[6];
    const int* batch  = (const int*)d_in[7];
    const float* a2   = (const float*)d_in[8];
    const float* step = (const float*)d_in[9];
    const float* gamma= (const float*)d_in[10];
    const float* beta = (const float*)d_in[11];
    const float* WQ2  = (const float*)d_in[12];
    const float* WK2  = (const float*)d_in[13];
    const float* WQ3  = (const float*)d_in[14];
    const float* WK3  = (const float*)d_in[15];
    const float* Ttau = (const float*)d_in[16];
    const float* WQm  = (const float*)d_in[17];
    const float* WKm  = (const float*)d_in[18];
    const float* Bmem = (const float*)d_in[19];
    float* out = (float*)d_out;
    float* Eg  = out + (size_t)Nn * Dd;

    void *pU, *pZ2, *pZ3, *pG, *pP, *pWc, *pWcT, *pdG;
    cudaGetSymbolAddress(&pU, g_U);
    cudaGetSymbolAddress(&pZ2, g_Z2);
    cudaGetSymbolAddress(&pZ3, g_Z3);
    cudaGetSymbolAddress(&pG, g_G);
    cudaGetSymbolAddress(&pP, g_P);
    cudaGetSymbolAddress(&pWc, g_Wcat);
    cudaGetSymbolAddress(&pWcT, g_WcatT);
    cudaGetSymbolAddress(&pdG, g_dG);

    cudaMemsetAsync(pU, 0, sizeof(float) * (size_t)Nn * PW);
    cudaMemsetAsync(pZ2, 0, sizeof(float) * Nn * Hh);
    cudaMemsetAsync(pZ3, 0, sizeof(float) * Nn * Hh);
    cudaMemsetAsync(Eg, 0, sizeof(float) * NGg);

    k_ln<<<Nn / 8, 256>>>(X, gamma, beta);
    k_wcat<<<(PW * Dd + 255) / 256, 256>>>(WQ2, WK2, WQ3, WK3, WQm);
    k_km<<<(Hh * KSL * HDm + 255) / 256, 256>>>(Bmem, WKm);

    // Forward projections: P = G[N,128] x WcatT[128,896]   (tensor core, tf32)
    k_gemm_tf32<<<dim3(PW / 128, Nn / 128), 256>>>((const float*)pG, Dd,
                                                   (const float*)pWcT, PW,
                                                   (float*)pP, PW, Dd);

    k_pair_fwd<<<Ee / 8, 256>>>(c2, u2, a2);
    k_motif_fwd<<<Mm / 8, 256>>>(c3, u3, v3, tt, Ttau);
    k_mem<<<(Nn * Hh) / 8, 256>>>();

    k_energy<<<Nn / 8, 256>>>(X, batch, Eg);

    k_pair_bwd<<<Ee / 8, 256>>>(c2, u2);
    k_motif_bwd<<<Mm / 8, 256>>>(c3, u3, v3, tt, Ttau);

    // Backward projections: dG = U[N,896] x Wcat[896,128]  (tensor core, tf32)
    k_gemm_tf32<<<dim3(Dd / 128, Nn / 128), 256>>>((const float*)pU, PW,
                                                   (const float*)pWc, Dd,
                                                   (float*)pdG, Dd, PW);

    k_final<<<Nn / 8, 256>>>(X, gamma, step, out);
}

// round 6
// speedup vs baseline: 2.2658x; 1.0087x over previous
#include <cuda_runtime.h>
#include <cuda_bf16.h>
#include <math.h>
#include <stdint.h>

// ---------------------------------------------------------------------------
// Problem constants (shapes fixed by the dataset)
// ---------------------------------------------------------------------------
#define Nn   32768
#define Dd   128
#define Hh   2
#define HDm  64
#define Ee   262144
#define Mm   131072
#define NGg  32
#define PW   896          // 128(Q2)+128(K2)+256(Q3)+256(K3)+128(Qm)
#define PB   768          // bf16 mirror width (Q2|K2|Q3|K3)
#define KSL  32           // memory slots
#define LAM3 0.5f
#define EPSV 1e-5f

// ---------------------------------------------------------------------------
// Scratch (static device globals; no runtime allocation allowed)
// ---------------------------------------------------------------------------
__device__ float g_G[(size_t)Nn * Dd];
__device__ float g_mu[Nn];
__device__ float g_rstd[Nn];
__device__ float g_P[(size_t)Nn * PW];             // only cols 768.. (Qm) valid fp32
__device__ __align__(256) __nv_bfloat16 g_Pb[(size_t)Nn * PB];  // bf16 mirror of cols 0..767
__device__ float g_U[(size_t)Nn * PW];             // grads wrt the projections
__device__ float g_dG[(size_t)Nn * Dd];
__device__ float g_Wcat[PW * Dd];
__device__ float g_WcatT[Dd * PW];
__device__ float g_Km[Hh * KSL * HDm];     // [h][k][z]
__device__ float g_KmT[Hh * HDm * KSL];    // [h][z][k]
__device__ float g_s2[(size_t)Ee * Hh];    // holds exp(s2)
__device__ float g_Z2[Nn * Hh];
__device__ float g_qk[(size_t)Mm * 4];
__device__ float g_tv[(size_t)Mm * 4];
__device__ float g_s3[(size_t)Mm * Hh];    // holds exp(s3)
__device__ float g_Z3[Nn * Hh];
__device__ float g_Lm[Nn * Hh];

// ---------------------------------------------------------------------------
// Helpers
// ---------------------------------------------------------------------------
__device__ __forceinline__ float wsum32(float v) {
#pragma unroll
    for (int m = 16; m > 0; m >>= 1) v += __shfl_xor_sync(0xffffffffu, v, m);
    return v;
}
__device__ __forceinline__ float wsum16(float v) {
#pragma unroll
    for (int m = 8; m > 0; m >>= 1) v += __shfl_xor_sync(0xffffffffu, v, m);
    return v;
}
__device__ __forceinline__ float wsum8(float v) {
#pragma unroll
    for (int m = 4; m > 0; m >>= 1) v += __shfl_xor_sync(0xffffffffu, v, m);
    return v;
}
__device__ __forceinline__ void red_add_v4(float* addr, float a, float b, float c, float d) {
    asm volatile("red.global.add.v4.f32 [%0], {%1, %2, %3, %4};"
                 :: "l"(addr), "f"(a), "f"(b), "f"(c), "f"(d) : "memory");
}
__device__ __forceinline__ float totf32(float x) {
    uint32_t r;
    asm("cvt.rna.tf32.f32 %0, %1;" : "=r"(r) : "f"(x));
    return __uint_as_float(r);
}
// load 4 bf16 -> 4 floats (8B aligned)
__device__ __forceinline__ void ld4bf(const __nv_bfloat16* p, float* f) {
    uint2 r = *(const uint2*)p;
    __nv_bfloat162 h0 = *reinterpret_cast<const __nv_bfloat162*>(&r.x);
    __nv_bfloat162 h1 = *reinterpret_cast<const __nv_bfloat162*>(&r.y);
    float2 a = __bfloat1622float2(h0), b = __bfloat1622float2(h1);
    f[0] = a.x; f[1] = a.y; f[2] = b.x; f[3] = b.y;
}
// load 8 bf16 -> 8 floats (16B aligned)
__device__ __forceinline__ void ld8bf(const __nv_bfloat16* p, float* f) {
    uint4 r = *(const uint4*)p;
    __nv_bfloat162 h0 = *reinterpret_cast<const __nv_bfloat162*>(&r.x);
    __nv_bfloat162 h1 = *reinterpret_cast<const __nv_bfloat162*>(&r.y);
    __nv_bfloat162 h2 = *reinterpret_cast<const __nv_bfloat162*>(&r.z);
    __nv_bfloat162 h3 = *reinterpret_cast<const __nv_bfloat162*>(&r.w);
    float2 a = __bfloat1622float2(h0), b = __bfloat1622float2(h1);
    float2 c = __bfloat1622float2(h2), d = __bfloat1622float2(h3);
    f[0] = a.x; f[1] = a.y; f[2] = b.x; f[3] = b.y;
    f[4] = c.x; f[5] = c.y; f[6] = d.x; f[7] = d.y;
}

// ---------------------------------------------------------------------------
// LayerNorm forward (warp per row), saves mu/rstd
// ---------------------------------------------------------------------------
__global__ void k_ln(const float* __restrict__ X, const float* __restrict__ gamma,
                     const float* __restrict__ beta) {
    int w = (blockIdx.x * blockDim.x + threadIdx.x) >> 5;
    int lane = threadIdx.x & 31;
    if (w >= Nn) return;
    const float4 x = *(const float4*)(X + (size_t)w * Dd + lane * 4);
    float s = x.x + x.y + x.z + x.w;
    float mu = wsum32(s) * (1.0f / Dd);
    float4 xc = make_float4(x.x - mu, x.y - mu, x.z - mu, x.w - mu);
    float v = xc.x * xc.x + xc.y * xc.y + xc.z * xc.z + xc.w * xc.w;
    v = wsum32(v) * (1.0f / Dd);
    float rstd = rsqrtf(v + EPSV);
    const float4 g4 = *(const float4*)(gamma + lane * 4);
    const float4 b4 = *(const float4*)(beta + lane * 4);
    float4 G;
    G.x = g4.x * xc.x * rstd + b4.x;
    G.y = g4.y * xc.y * rstd + b4.y;
    G.z = g4.z * xc.z * rstd + b4.z;
    G.w = g4.w * xc.w * rstd + b4.w;
    *(float4*)(g_G + (size_t)w * Dd + lane * 4) = G;
    if (lane == 0) { g_mu[w] = mu; g_rstd[w] = rstd; }
}

// ---------------------------------------------------------------------------
// Build stacked weight matrix (and its transpose)
// ---------------------------------------------------------------------------
__global__ void k_wcat(const float* __restrict__ WQ2, const float* __restrict__ WK2,
                       const float* __restrict__ WQ3, const float* __restrict__ WK3,
                       const float* __restrict__ WQm) {
    int idx = blockIdx.x * blockDim.x + threadIdx.x;
    if (idx >= PW * Dd) return;
    int j = idx / Dd, d = idx - j * Dd;
    float v;
    if (j < 128)      v = WQ2[j * Dd + d];
    else if (j < 256) v = WK2[(j - 128) * Dd + d];
    else if (j < 512) v = WQ3[(j - 256) * Dd + d];
    else if (j < 768) v = WK3[(j - 512) * Dd + d];
    else              v = WQm[(j - 768) * Dd + d];
    g_Wcat[j * Dd + d] = v;
    g_WcatT[d * PW + j] = v;
}

// ---------------------------------------------------------------------------
// Km = B_mem @ W_Km^T per head (tiny), both layouts
// ---------------------------------------------------------------------------
__global__ void k_km(const float* __restrict__ Bm, const float* __restrict__ WKm) {
    int idx = blockIdx.x * blockDim.x + threadIdx.x;
    if (idx >= Hh * KSL * HDm) return;
    int h = idx / (KSL * HDm);
    int k = (idx / HDm) % KSL;
    int z = idx % HDm;
    const float* b = Bm + k * Dd;
    const float* w = WKm + (h * HDm + z) * Dd;
    float acc = 0.f;
#pragma unroll 8
    for (int d = 0; d < Dd; d++) acc += b[d] * w[d];
    g_Km[idx] = acc;
    g_KmT[(h * HDm + z) * KSL + k] = acc;
}

// ---------------------------------------------------------------------------
// TF32 tensor-core GEMM: C[M,J] = A[M,K] * B[K,J], row-major.
// Block 128x128x16, 8 warps, warp tile 64x32 (4x4 m16n8k8 frags).
// If Cb != nullptr, column blocks with col0 < PB write bf16 to Cb (stride PB)
// INSTEAD of fp32 to C.
// ---------------------------------------------------------------------------
__global__ void __launch_bounds__(256)
k_gemm_tf32(const float* __restrict__ A, int lda,
            const float* __restrict__ B, int ldb,
            float* __restrict__ C, int ldc, int Kdim,
            __nv_bfloat16* __restrict__ Cb) {
    __shared__ float As[2][128][20];
    __shared__ float Bs[2][16][136];
    int tid = threadIdx.x;
    int warp = tid >> 5, lane = tid & 31;
    int g = lane >> 2, tg = lane & 3;
    int wm = (warp >> 2) * 64;      // 0 or 64
    int wn = (warp & 3) * 32;       // 0,32,64,96
    int row0 = blockIdx.y * 128, col0 = blockIdx.x * 128;

    int ar = tid >> 2;              // 0..63 (+64 second pass)
    int ac = (tid & 3) * 4;         // 0,4,8,12
    int br = tid >> 5;              // 0..7 (+8 second pass)
    int bc = lane * 4;              // 0..124
    const float* Ap0 = A + (size_t)(row0 + ar) * lda + ac;
    const float* Ap1 = Ap0 + (size_t)64 * lda;
    const float* Bp0 = B + (size_t)br * ldb + col0 + bc;
    const float* Bp1 = Bp0 + (size_t)8 * ldb;

    float acc[16][4];
#pragma unroll
    for (int i = 0; i < 16; i++)
#pragma unroll
        for (int j = 0; j < 4; j++) acc[i][j] = 0.f;

    float4 a0v = *(const float4*)(Ap0);
    float4 a1v = *(const float4*)(Ap1);
    float4 b0v = *(const float4*)(Bp0);
    float4 b1v = *(const float4*)(Bp1);
    {
        float* d0 = &As[0][ar][ac];
        d0[0] = totf32(a0v.x); d0[1] = totf32(a0v.y); d0[2] = totf32(a0v.z); d0[3] = totf32(a0v.w);
        float* d1 = &As[0][64 + ar][ac];
        d1[0] = totf32(a1v.x); d1[1] = totf32(a1v.y); d1[2] = totf32(a1v.z); d1[3] = totf32(a1v.w);
        float* e0 = &Bs[0][br][bc];
        e0[0] = totf32(b0v.x); e0[1] = totf32(b0v.y); e0[2] = totf32(b0v.z); e0[3] = totf32(b0v.w);
        float* e1 = &Bs[0][8 + br][bc];
        e1[0] = totf32(b1v.x); e1[1] = totf32(b1v.y); e1[2] = totf32(b1v.z); e1[3] = totf32(b1v.w);
    }
    __syncthreads();

    int nk = Kdim >> 4;
    for (int kt = 0; kt < nk; kt++) {
        int cur = kt & 1, nxt = cur ^ 1;
        if (kt + 1 < nk) {
            a0v = *(const float4*)(Ap0 + (kt + 1) * 16);
            a1v = *(const float4*)(Ap1 + (kt + 1) * 16);
            b0v = *(const float4*)(Bp0 + (size_t)(kt + 1) * 16 * ldb);
            b1v = *(const float4*)(Bp1 + (size_t)(kt + 1) * 16 * ldb);
        }
#pragma unroll
        for (int kk = 0; kk < 2; kk++) {
            int k0 = kk * 8;
            uint32_t af[4][4];
            uint32_t bf[4][2];
#pragma unroll
            for (int mi = 0; mi < 4; mi++) {
                int r = wm + mi * 16 + g;
                af[mi][0] = __float_as_uint(As[cur][r][k0 + tg]);
                af[mi][1] = __float_as_uint(As[cur][r + 8][k0 + tg]);
                af[mi][2] = __float_as_uint(As[cur][r][k0 + tg + 4]);
                af[mi][3] = __float_as_uint(As[cur][r + 8][k0 + tg + 4]);
            }
#pragma unroll
            for (int ni = 0; ni < 4; ni++) {
                int n = wn + ni * 8 + g;
                bf[ni][0] = __float_as_uint(Bs[cur][k0 + tg][n]);
                bf[ni][1] = __float_as_uint(Bs[cur][k0 + tg + 4][n]);
            }
#pragma unroll
            for (int mi = 0; mi < 4; mi++)
#pragma unroll
                for (int ni = 0; ni < 4; ni++) {
                    float* c = acc[mi * 4 + ni];
                    asm volatile(
                        "mma.sync.aligned.m16n8k8.row.col.f32.tf32.tf32.f32 "
                        "{%0,%1,%2,%3}, {%4,%5,%6,%7}, {%8,%9}, {%0,%1,%2,%3};"
                        : "+f"(c[0]), "+f"(c[1]), "+f"(c[2]), "+f"(c[3])
                        : "r"(af[mi][0]), "r"(af[mi][1]), "r"(af[mi][2]), "r"(af[mi][3]),
                          "r"(bf[ni][0]), "r"(bf[ni][1]));
                }
        }
        if (kt + 1 < nk) {
            float* d0 = &As[nxt][ar][ac];
            d0[0] = totf32(a0v.x); d0[1] = totf32(a0v.y); d0[2] = totf32(a0v.z); d0[3] = totf32(a0v.w);
            float* d1 = &As[nxt][64 + ar][ac];
            d1[0] = totf32(a1v.x); d1[1] = totf32(a1v.y); d1[2] = totf32(a1v.z); d1[3] = totf32(a1v.w);
            float* e0 = &Bs[nxt][br][bc];
            e0[0] = totf32(b0v.x); e0[1] = totf32(b0v.y); e0[2] = totf32(b0v.z); e0[3] = totf32(b0v.w);
            float* e1 = &Bs[nxt][8 + br][bc];
            e1[0] = totf32(b1v.x); e1[1] = totf32(b1v.y); e1[2] = totf32(b1v.z); e1[3] = totf32(b1v.w);
            __syncthreads();
        }
    }

    bool asbf = (Cb != nullptr) && (col0 < PB);
#pragma unroll
    for (int mi = 0; mi < 4; mi++)
#pragma unroll
        for (int ni = 0; ni < 4; ni++) {
            float* c = acc[mi * 4 + ni];
            int r = row0 + wm + mi * 16 + g;
            int col = col0 + wn + ni * 8 + 2 * tg;
            if (asbf) {
                *(__nv_bfloat162*)(Cb + (size_t)r * PB + col) =
                    __floats2bfloat162_rn(c[0], c[1]);
                *(__nv_bfloat162*)(Cb + (size_t)(r + 8) * PB + col) =
                    __floats2bfloat162_rn(c[2], c[3]);
            } else {
                *(float2*)(C + (size_t)r * ldc + col) = make_float2(c[0], c[1]);
                *(float2*)(C + (size_t)(r + 8) * ldc + col) = make_float2(c[2], c[3]);
            }
        }
}

// ---------------------------------------------------------------------------
// Pair term forward: warp per edge (bf16 gathers). Stores exp(s2).
// ---------------------------------------------------------------------------
__global__ void k_pair_fwd(const int* __restrict__ c2, const int* __restrict__ u2,
                           const float* __restrict__ a2) {
    int e = (blockIdx.x * 256 + threadIdx.x) >> 5;
    int lane = threadIdx.x & 31;
    if (e >= Ee) return;
    int c = c2[e], u = u2[e];
    float q[4], k[4];
    ld4bf(g_Pb + (size_t)c * PB + lane * 4, q);
    ld4bf(g_Pb + (size_t)u * PB + 128 + lane * 4, k);
    float part = q[0] * k[0] + q[1] * k[1] + q[2] * k[2] + q[3] * k[3];
    part = wsum16(part);
    int h = lane >> 4;
    if ((lane & 15) == 0) {
        float s = part * 0.125f + a2[e * 2 + h];
        float ex = __expf(s);
        g_s2[(size_t)e * 2 + h] = ex;
        atomicAdd(&g_Z2[c * 2 + h], ex);
    }
}

// Pair backward: dQ2[c] += w*K2[u], dK2[u] += w*Q2[c], w = -p/8  (vector RED)
__global__ void k_pair_bwd(const int* __restrict__ c2, const int* __restrict__ u2) {
    int e = (blockIdx.x * 256 + threadIdx.x) >> 5;
    int lane = threadIdx.x & 31;
    if (e >= Ee) return;
    int c = c2[e], u = u2[e];
    int h = lane >> 4;
    float p = g_s2[(size_t)e * 2 + h] / g_Z2[c * 2 + h];
    float wt = -0.125f * p;
    float q[4], k[4];
    ld4bf(g_Pb + (size_t)c * PB + lane * 4, q);
    ld4bf(g_Pb + (size_t)u * PB + 128 + lane * 4, k);
    red_add_v4(g_U + (size_t)c * PW + lane * 4, wt * k[0], wt * k[1], wt * k[2], wt * k[3]);
    red_add_v4(g_U + (size_t)u * PW + 128 + lane * 4, wt * q[0], wt * q[1], wt * q[2], wt * q[3]);
}

// ---------------------------------------------------------------------------
// Motif forward: warp per motif (bf16 gathers). Stores exp(s3).
// ---------------------------------------------------------------------------
__global__ void k_motif_fwd(const int* __restrict__ c3, const int* __restrict__ u3,
                            const int* __restrict__ v3, const int* __restrict__ tt,
                            const float* __restrict__ Ttau) {
    int m = (blockIdx.x * 256 + threadIdx.x) >> 5;
    int lane = threadIdx.x & 31;
    if (m >= Mm) return;
    int c = c3[m], ua = u3[m], vb = v3[m], t = tt[m];
    int off = lane * 8;
    float q[8], ku[8], kv[8];
    ld8bf(g_Pb + (size_t)c  * PB + 256 + off, q);
    ld8bf(g_Pb + (size_t)ua * PB + 512 + off, ku);
    ld8bf(g_Pb + (size_t)vb * PB + 512 + off, kv);
    const float* tp = Ttau + t * 256 + off;
    float qk = 0.f, tv = 0.f;
#pragma unroll
    for (int i = 0; i < 8; i++) {
        qk += q[i] * ku[i];
        tv += tp[i] * kv[i];
    }
    qk = wsum8(qk);
    tv = wsum8(tv);
    int g = lane >> 3;
    if ((lane & 7) == 0) {
        g_qk[(size_t)m * 4 + g] = qk;
        g_tv[(size_t)m * 4 + g] = tv;
    }
    float qk0 = __shfl_sync(0xffffffffu, qk, 0),  tv0 = __shfl_sync(0xffffffffu, tv, 0);
    float qk1 = __shfl_sync(0xffffffffu, qk, 8),  tv1 = __shfl_sync(0xffffffffu, tv, 8);
    float qk2 = __shfl_sync(0xffffffffu, qk, 16), tv2 = __shfl_sync(0xffffffffu, tv, 16);
    float qk3 = __shfl_sync(0xffffffffu, qk, 24), tv3 = __shfl_sync(0xffffffffu, tv, 24);
    if (lane < 2) {
        float s3 = (lane == 0) ? (qk0 * tv0 + qk1 * tv1) * (1.0f / 64)
                               : (qk2 * tv2 + qk3 * tv3) * (1.0f / 64);
        float ex = __expf(s3);
        g_s3[(size_t)m * 2 + lane] = ex;
        atomicAdd(&g_Z3[c * 2 + lane], ex);
    }
}

// Motif backward (bf16 gathers + vector RED)
__global__ void k_motif_bwd(const int* __restrict__ c3, const int* __restrict__ u3,
                            const int* __restrict__ v3, const int* __restrict__ tt,
                            const float* __restrict__ Ttau) {
    int m = (blockIdx.x * 256 + threadIdx.x) >> 5;
    int lane = threadIdx.x & 31;
    if (m >= Mm) return;
    int c = c3[m], ua = u3[m], vb = v3[m], t = tt[m];
    int g = lane >> 3;
    int h = g >> 1;
    float p = g_s3[(size_t)m * 2 + h] / g_Z3[c * 2 + h];
    float gg = -LAM3 * p * (1.0f / 64);
    float cA = gg * g_tv[(size_t)m * 4 + g];
    float cB = gg * g_qk[(size_t)m * 4 + g];
    int off = lane * 8;
    float q[8], ku[8];
    ld8bf(g_Pb + (size_t)c  * PB + 256 + off, q);
    ld8bf(g_Pb + (size_t)ua * PB + 512 + off, ku);
    const float* tp = Ttau + t * 256 + off;
    float* dq  = g_U + (size_t)c  * PW + 256 + off;
    float* dku = g_U + (size_t)ua * PW + 512 + off;
    float* dkv = g_U + (size_t)vb * PW + 512 + off;
#pragma unroll
    for (int i = 0; i < 8; i += 4) {
        red_add_v4(dq + i,  cA * ku[i], cA * ku[i+1], cA * ku[i+2], cA * ku[i+3]);
        red_add_v4(dku + i, cA * q[i],  cA * q[i+1],  cA * q[i+2],  cA * q[i+3]);
        red_add_v4(dkv + i, cB * tp[i], cB * tp[i+1], cB * tp[i+2], cB * tp[i+3]);
    }
}

// ---------------------------------------------------------------------------
// Memory term: warp per (node, head). Computes Lm and dQm directly (no atomics)
// ---------------------------------------------------------------------------
__global__ void k_mem() {
    int w = (blockIdx.x * 256 + threadIdx.x) >> 5;
    int lane = threadIdx.x & 31;
    if (w >= Nn * Hh) return;
    int n = w >> 1, h = w & 1;
    const float* qm = g_P + (size_t)n * PW + 768 + h * HDm;
    const float* kt = g_KmT + h * HDm * KSL;   // [z][k]
    const float* km = g_Km + h * KSL * HDm;    // [k][z]
    float sm = 0.f;
#pragma unroll 8
    for (int z = 0; z < HDm; z++) sm += qm[z] * kt[z * KSL + lane];
    sm *= 0.125f;
    float e = expf(sm);
    float Z = wsum32(e);
    float p = e / Z;
    if (lane == 0) g_Lm[w] = logf(Z);
    float a0 = 0.f, a1 = 0.f;
#pragma unroll
    for (int kk = 0; kk < KSL; kk++) {
        float pk = __shfl_sync(0xffffffffu, p, kk);
        a0 += pk * km[kk * HDm + lane];
        a1 += pk * km[kk * HDm + lane + 32];
    }
    float* du = g_U + (size_t)n * PW + 768 + h * HDm;
    du[lane] = -0.125f * a0;
    du[lane + 32] = -0.125f * a1;
}

// ---------------------------------------------------------------------------
// Per-node energy + per-graph reduction (block-local bins)
// ---------------------------------------------------------------------------
__global__ void k_energy(const float* __restrict__ X, const int* __restrict__ batch,
                         float* __restrict__ Eg) {
    __shared__ float bins[NGg];
    int tid = threadIdx.x;
    if (tid < NGg) bins[tid] = 0.f;
    __syncthreads();
    int w = (blockIdx.x * 256 + tid) >> 5;
    int lane = tid & 31;
    if (w < Nn) {
        const float4 x = *(const float4*)(X + (size_t)w * Dd + lane * 4);
        float ss = wsum32(x.x * x.x + x.y * x.y + x.z * x.z + x.w * x.w);
        if (lane == 0) {
            float e = 0.5f * ss;
            float z0 = g_Z2[w * 2], z1 = g_Z2[w * 2 + 1];
            e -= (z0 > 0.f ? logf(z0) : 0.f) + (z1 > 0.f ? logf(z1) : 0.f);
            float y0 = g_Z3[w * 2], y1 = g_Z3[w * 2 + 1];
            e -= LAM3 * ((y0 > 0.f ? logf(y0) : 0.f) + (y1 > 0.f ? logf(y1) : 0.f));
            e -= g_Lm[w * 2] + g_Lm[w * 2 + 1];
            atomicAdd(&bins[batch[w]], e);
        }
    }
    __syncthreads();
    if (tid < NGg) atomicAdd(&Eg[tid], bins[tid]);
}

// ---------------------------------------------------------------------------
// LN backward + grad clip + step + state clip (warp per row)
// ---------------------------------------------------------------------------
__global__ void k_final(const float* __restrict__ X, const float* __restrict__ gamma,
                        const float* __restrict__ step, float* __restrict__ out) {
    int w = (blockIdx.x * blockDim.x + threadIdx.x) >> 5;
    int lane = threadIdx.x & 31;
    if (w >= Nn) return;
    const float4 x = *(const float4*)(X + (size_t)w * Dd + lane * 4);
    const float4 dg = *(const float4*)(g_dG + (size_t)w * Dd + lane * 4);
    const float4 gm = *(const float4*)(gamma + lane * 4);
    float mu = g_mu[w], rstd = g_rstd[w];
    float4 xh = make_float4((x.x - mu) * rstd, (x.y - mu) * rstd,
                            (x.z - mu) * rstd, (x.w - mu) * rstd);
    float4 dxh = make_float4(dg.x * gm.x, dg.y * gm.y, dg.z * gm.z, dg.w * gm.w);
    float S1 = wsum32(dxh.x + dxh.y + dxh.z + dxh.w) * (1.0f / Dd);
    float S2 = wsum32(dxh.x * xh.x + dxh.y * xh.y + dxh.z * xh.z + dxh.w * xh.w) * (1.0f / Dd);
    float4 g;
    g.x = x.x + rstd * (dxh.x - S1 - xh.x * S2);
    g.y = x.y + rstd * (dxh.y - S1 - xh.y * S2);
    g.z = x.z + rstd * (dxh.z - S1 - xh.z * S2);
    g.w = x.w + rstd * (dxh.w - S1 - xh.w * S2);
    float gss = wsum32(g.x * g.x + g.y * g.y + g.z * g.z + g.w * g.w);
    float sc1 = 1.0f / fmaxf(sqrtf(gss), 1.0f);   // GRAD_CLIP = 1
    float st = step[0] * sc1;                      // DAMPING = 1
    float4 xn = make_float4(x.x - st * g.x, x.y - st * g.y,
                            x.z - st * g.z, x.w - st * g.w);
    float sn = wsum32(xn.x * xn.x + xn.y * xn.y + xn.z * xn.z + xn.w * xn.w);
    float sc2 = 10.0f / fmaxf(sqrtf(sn), 10.0f);  // STATE_CLIP = 10
    float4 o = make_float4(xn.x * sc2, xn.y * sc2, xn.z * sc2, xn.w * sc2);
    *(float4*)(out + (size_t)w * Dd + lane * 4) = o;
}

// ---------------------------------------------------------------------------
// Launch
// ---------------------------------------------------------------------------
extern "C" void kernel_launch(void* const* d_in, const int* in_sizes, int n_in,
                              void* d_out, int out_size) {
    const float* X    = (const float*)d_in[0];
    const int* c2     = (const int*)d_in[1];
    const int* u2     = (const int*)d_in[2];
    const int* c3     = (const int*)d_in[3];
    const int* u3     = (const int*)d_in[4];
    const int* v3     = (const int*)d_in[5];
    const int* tt     = (const int*)d_in[6];
    const int* batch  = (const int*)d_in[7];
    const float* a2   = (const float*)d_in[8];
    const float* step = (const float*)d_in[9];
    const float* gamma= (const float*)d_in[10];
    const float* beta = (const float*)d_in[11];
    const float* WQ2  = (const float*)d_in[12];
    const float* WK2  = (const float*)d_in[13];
    const float* WQ3  = (const float*)d_in[14];
    const float* WK3  = (const float*)d_in[15];
    const float* Ttau = (const float*)d_in[16];
    const float* WQm  = (const float*)d_in[17];
    const float* WKm  = (const float*)d_in[18];
    const float* Bmem = (const float*)d_in[19];
    float* out = (float*)d_out;
    float* Eg  = out + (size_t)Nn * Dd;

    void *pU, *pZ2, *pZ3, *pG, *pP, *pPb, *pWc, *pWcT, *pdG;
    cudaGetSymbolAddress(&pU, g_U);
    cudaGetSymbolAddress(&pZ2, g_Z2);
    cudaGetSymbolAddress(&pZ3, g_Z3);
    cudaGetSymbolAddress(&pG, g_G);
    cudaGetSymbolAddress(&pP, g_P);
    cudaGetSymbolAddress(&pPb, g_Pb);
    cudaGetSymbolAddress(&pWc, g_Wcat);
    cudaGetSymbolAddress(&pWcT, g_WcatT);
    cudaGetSymbolAddress(&pdG, g_dG);

    cudaMemsetAsync(pU, 0, sizeof(float) * (size_t)Nn * PW);
    cudaMemsetAsync(pZ2, 0, sizeof(float) * Nn * Hh);
    cudaMemsetAsync(pZ3, 0, sizeof(float) * Nn * Hh);
    cudaMemsetAsync(Eg, 0, sizeof(float) * NGg);

    k_ln<<<Nn / 8, 256>>>(X, gamma, beta);
    k_wcat<<<(PW * Dd + 255) / 256, 256>>>(WQ2, WK2, WQ3, WK3, WQm);
    k_km<<<(Hh * KSL * HDm + 255) / 256, 256>>>(Bmem, WKm);

    // Forward projections: P = G[N,128] x WcatT[128,896] (bf16 out for cols<768)
    k_gemm_tf32<<<dim3(PW / 128, Nn / 128), 256>>>((const float*)pG, Dd,
                                                   (const float*)pWcT, PW,
                                                   (float*)pP, PW, Dd,
                                                   (__nv_bfloat16*)pPb);

    k_pair_fwd<<<Ee / 8, 256>>>(c2, u2, a2);
    k_motif_fwd<<<Mm / 8, 256>>>(c3, u3, v3, tt, Ttau);
    k_mem<<<(Nn * Hh) / 8, 256>>>();

    k_energy<<<Nn / 8, 256>>>(X, batch, Eg);

    k_pair_bwd<<<Ee / 8, 256>>>(c2, u2);
    k_motif_bwd<<<Mm / 8, 256>>>(c3, u3, v3, tt, Ttau);

    // Backward projections: dG = U[N,896] x Wcat[896,128]  (pure fp32 out)
    k_gemm_tf32<<<dim3(Dd / 128, Nn / 128), 256>>>((const float*)pU, PW,
                                                   (const float*)pWc, Dd,
                                                   (float*)pdG, Dd, PW,
                                                   nullptr);

    k_final<<<Nn / 8, 256>>>(X, gamma, step, out);
}

// round 7
// speedup vs baseline: 2.7526x; 1.2148x over previous
#include <cuda_runtime.h>
#include <cuda_bf16.h>
#include <cuda_fp16.h>
#include <math.h>
#include <stdint.h>

// ---------------------------------------------------------------------------
// Problem constants
// ---------------------------------------------------------------------------
#define Nn   32768
#define Dd   128
#define Hh   2
#define HDm  64
#define Ee   262144
#define Mm   131072
#define NGg  32
#define PW   896          // 128(Q2)+128(K2)+256(Q3)+256(K3)+128(Qm)
#define PB   768          // bf16 mirror width (Q2|K2|Q3|K3)
#define KSL  32
#define TMt  2            // motif type count
#define LAM3 0.5f
#define EPSV 1e-5f

// ---------------------------------------------------------------------------
// Scratch
// ---------------------------------------------------------------------------
__device__ float g_G[(size_t)Nn * Dd];
__device__ float g_mu[Nn];
__device__ float g_rstd[Nn];
__device__ float g_P[(size_t)Nn * PW];                          // Qm cols (768..) fp32
__device__ __align__(256) __nv_bfloat16 g_Pb[(size_t)Nn * PB];  // bf16 mirror cols 0..767
__device__ __align__(256) __half g_Uh[(size_t)Nn * PW];         // f16 gradient accumulator
__device__ float g_dG[(size_t)Nn * Dd];
__device__ float g_WcatT[Dd * PW];                              // fp32 [d][j] for fwd GEMM
__device__ __align__(256) __half g_WcatHT[Dd * PW];             // f16 [d][j] (B^T) for bwd GEMM
__device__ __nv_bfloat16 g_TtH[TMt * Hh * 2 * HDm];             // bf16 Ttau mirror (512)
__device__ float g_Km[Hh * KSL * HDm];     // [h][k][z]
__device__ float g_KmT[Hh * HDm * KSL];    // [h][z][k]
__device__ float g_s2[(size_t)Ee * Hh];    // exp(s2)
__device__ float g_Z2[Nn * Hh];
__device__ float g_qk[(size_t)Mm * 4];
__device__ float g_tv[(size_t)Mm * 4];
__device__ float g_s3[(size_t)Mm * Hh];    // exp(s3)
__device__ float g_Z3[Nn * Hh];
__device__ float g_Lm[Nn * Hh];

// ---------------------------------------------------------------------------
// Helpers
// ---------------------------------------------------------------------------
__device__ __forceinline__ float wsum32(float v) {
#pragma unroll
    for (int m = 16; m > 0; m >>= 1) v += __shfl_xor_sync(0xffffffffu, v, m);
    return v;
}
__device__ __forceinline__ float wsum16(float v) {
#pragma unroll
    for (int m = 8; m > 0; m >>= 1) v += __shfl_xor_sync(0xffffffffu, v, m);
    return v;
}
__device__ __forceinline__ float wsum8(float v) {
#pragma unroll
    for (int m = 4; m > 0; m >>= 1) v += __shfl_xor_sync(0xffffffffu, v, m);
    return v;
}
// f16x2 vector RED: 16B = 8 halves in ONE lane-op
__device__ __forceinline__ void red_add_v4h(__half* addr, uint32_t a, uint32_t b,
                                            uint32_t c, uint32_t d) {
    asm volatile("red.global.add.noftz.v4.f16x2 [%0], {%1, %2, %3, %4};"
                 :: "l"(addr), "r"(a), "r"(b), "r"(c), "r"(d) : "memory");
}
__device__ __forceinline__ uint32_t pack2h(float a, float b) {
    __half2 h = __floats2half2_rn(a, b);
    return *reinterpret_cast<uint32_t*>(&h);
}
__device__ __forceinline__ float totf32(float x) {
    uint32_t r;
    asm("cvt.rna.tf32.f32 %0, %1;" : "=r"(r) : "f"(x));
    return __uint_as_float(r);
}
__device__ __forceinline__ void ld4bf(const __nv_bfloat16* p, float* f) {
    uint2 r = *(const uint2*)p;
    __nv_bfloat162 h0 = *reinterpret_cast<const __nv_bfloat162*>(&r.x);
    __nv_bfloat162 h1 = *reinterpret_cast<const __nv_bfloat162*>(&r.y);
    float2 a = __bfloat1622float2(h0), b = __bfloat1622float2(h1);
    f[0] = a.x; f[1] = a.y; f[2] = b.x; f[3] = b.y;
}
__device__ __forceinline__ void ld8bf(const __nv_bfloat16* p, float* f) {
    uint4 r = *(const uint4*)p;
    __nv_bfloat162 h0 = *reinterpret_cast<const __nv_bfloat162*>(&r.x);
    __nv_bfloat162 h1 = *reinterpret_cast<const __nv_bfloat162*>(&r.y);
    __nv_bfloat162 h2 = *reinterpret_cast<const __nv_bfloat162*>(&r.z);
    __nv_bfloat162 h3 = *reinterpret_cast<const __nv_bfloat162*>(&r.w);
    float2 a = __bfloat1622float2(h0), b = __bfloat1622float2(h1);
    float2 c = __bfloat1622float2(h2), d = __bfloat1622float2(h3);
    f[0] = a.x; f[1] = a.y; f[2] = b.x; f[3] = b.y;
    f[4] = c.x; f[5] = c.y; f[6] = d.x; f[7] = d.y;
}

// ---------------------------------------------------------------------------
// LayerNorm forward
// ---------------------------------------------------------------------------
__global__ void k_ln(const float* __restrict__ X, const float* __restrict__ gamma,
                     const float* __restrict__ beta) {
    int w = (blockIdx.x * blockDim.x + threadIdx.x) >> 5;
    int lane = threadIdx.x & 31;
    if (w >= Nn) return;
    const float4 x = *(const float4*)(X + (size_t)w * Dd + lane * 4);
    float s = x.x + x.y + x.z + x.w;
    float mu = wsum32(s) * (1.0f / Dd);
    float4 xc = make_float4(x.x - mu, x.y - mu, x.z - mu, x.w - mu);
    float v = xc.x * xc.x + xc.y * xc.y + xc.z * xc.z + xc.w * xc.w;
    v = wsum32(v) * (1.0f / Dd);
    float rstd = rsqrtf(v + EPSV);
    const float4 g4 = *(const float4*)(gamma + lane * 4);
    const float4 b4 = *(const float4*)(beta + lane * 4);
    float4 G;
    G.x = g4.x * xc.x * rstd + b4.x;
    G.y = g4.y * xc.y * rstd + b4.y;
    G.z = g4.z * xc.z * rstd + b4.z;
    G.w = g4.w * xc.w * rstd + b4.w;
    *(float4*)(g_G + (size_t)w * Dd + lane * 4) = G;
    if (lane == 0) { g_mu[w] = mu; g_rstd[w] = rstd; }
}

// ---------------------------------------------------------------------------
// Stacked weights: fp32 transpose (fwd) + f16 B^T (bwd) + bf16 Ttau mirror
// ---------------------------------------------------------------------------
__global__ void k_wcat(const float* __restrict__ WQ2, const float* __restrict__ WK2,
                       const float* __restrict__ WQ3, const float* __restrict__ WK3,
                       const float* __restrict__ WQm, const float* __restrict__ Ttau) {
    int idx = blockIdx.x * blockDim.x + threadIdx.x;
    if (idx < TMt * Hh * 2 * HDm) g_TtH[idx] = __float2bfloat16(Ttau[idx]);
    if (idx >= PW * Dd) return;
    int j = idx / Dd, d = idx - j * Dd;
    float v;
    if (j < 128)      v = WQ2[j * Dd + d];
    else if (j < 256) v = WK2[(j - 128) * Dd + d];
    else if (j < 512) v = WQ3[(j - 256) * Dd + d];
    else if (j < 768) v = WK3[(j - 512) * Dd + d];
    else              v = WQm[(j - 768) * Dd + d];
    g_WcatT[d * PW + j] = v;
    g_WcatHT[d * PW + j] = __float2half(v);
}

// ---------------------------------------------------------------------------
// Km = B_mem @ W_Km^T per head (tiny), both layouts
// ---------------------------------------------------------------------------
__global__ void k_km(const float* __restrict__ Bm, const float* __restrict__ WKm) {
    int idx = blockIdx.x * blockDim.x + threadIdx.x;
    if (idx >= Hh * KSL * HDm) return;
    int h = idx / (KSL * HDm);
    int k = (idx / HDm) % KSL;
    int z = idx % HDm;
    const float* b = Bm + k * Dd;
    const float* w = WKm + (h * HDm + z) * Dd;
    float acc = 0.f;
#pragma unroll 8
    for (int d = 0; d < Dd; d++) acc += b[d] * w[d];
    g_Km[idx] = acc;
    g_KmT[(h * HDm + z) * KSL + k] = acc;
}

// ---------------------------------------------------------------------------
// TF32 GEMM (forward projections): C=A*B, 128x128x16, bf16 out for cols<PB
// ---------------------------------------------------------------------------
__global__ void __launch_bounds__(256)
k_gemm_tf32(const float* __restrict__ A, int lda,
            const float* __restrict__ B, int ldb,
            float* __restrict__ C, int ldc, int Kdim,
            __nv_bfloat16* __restrict__ Cb) {
    __shared__ float As[2][128][20];
    __shared__ float Bs[2][16][136];
    int tid = threadIdx.x;
    int warp = tid >> 5, lane = tid & 31;
    int g = lane >> 2, tg = lane & 3;
    int wm = (warp >> 2) * 64;
    int wn = (warp & 3) * 32;
    int row0 = blockIdx.y * 128, col0 = blockIdx.x * 128;

    int ar = tid >> 2;
    int ac = (tid & 3) * 4;
    int br = tid >> 5;
    int bc = lane * 4;
    const float* Ap0 = A + (size_t)(row0 + ar) * lda + ac;
    const float* Ap1 = Ap0 + (size_t)64 * lda;
    const float* Bp0 = B + (size_t)br * ldb + col0 + bc;
    const float* Bp1 = Bp0 + (size_t)8 * ldb;

    float acc[16][4];
#pragma unroll
    for (int i = 0; i < 16; i++)
#pragma unroll
        for (int j = 0; j < 4; j++) acc[i][j] = 0.f;

    float4 a0v = *(const float4*)(Ap0);
    float4 a1v = *(const float4*)(Ap1);
    float4 b0v = *(const float4*)(Bp0);
    float4 b1v = *(const float4*)(Bp1);
    {
        float* d0 = &As[0][ar][ac];
        d0[0] = totf32(a0v.x); d0[1] = totf32(a0v.y); d0[2] = totf32(a0v.z); d0[3] = totf32(a0v.w);
        float* d1 = &As[0][64 + ar][ac];
        d1[0] = totf32(a1v.x); d1[1] = totf32(a1v.y); d1[2] = totf32(a1v.z); d1[3] = totf32(a1v.w);
        float* e0 = &Bs[0][br][bc];
        e0[0] = totf32(b0v.x); e0[1] = totf32(b0v.y); e0[2] = totf32(b0v.z); e0[3] = totf32(b0v.w);
        float* e1 = &Bs[0][8 + br][bc];
        e1[0] = totf32(b1v.x); e1[1] = totf32(b1v.y); e1[2] = totf32(b1v.z); e1[3] = totf32(b1v.w);
    }
    __syncthreads();

    int nk = Kdim >> 4;
    for (int kt = 0; kt < nk; kt++) {
        int cur = kt & 1, nxt = cur ^ 1;
        if (kt + 1 < nk) {
            a0v = *(const float4*)(Ap0 + (kt + 1) * 16);
            a1v = *(const float4*)(Ap1 + (kt + 1) * 16);
            b0v = *(const float4*)(Bp0 + (size_t)(kt + 1) * 16 * ldb);
            b1v = *(const float4*)(Bp1 + (size_t)(kt + 1) * 16 * ldb);
        }
#pragma unroll
        for (int kk = 0; kk < 2; kk++) {
            int k0 = kk * 8;
            uint32_t af[4][4];
            uint32_t bf[4][2];
#pragma unroll
            for (int mi = 0; mi < 4; mi++) {
                int r = wm + mi * 16 + g;
                af[mi][0] = __float_as_uint(As[cur][r][k0 + tg]);
                af[mi][1] = __float_as_uint(As[cur][r + 8][k0 + tg]);
                af[mi][2] = __float_as_uint(As[cur][r][k0 + tg + 4]);
                af[mi][3] = __float_as_uint(As[cur][r + 8][k0 + tg + 4]);
            }
#pragma unroll
            for (int ni = 0; ni < 4; ni++) {
                int n = wn + ni * 8 + g;
                bf[ni][0] = __float_as_uint(Bs[cur][k0 + tg][n]);
                bf[ni][1] = __float_as_uint(Bs[cur][k0 + tg + 4][n]);
            }
#pragma unroll
            for (int mi = 0; mi < 4; mi++)
#pragma unroll
                for (int ni = 0; ni < 4; ni++) {
                    float* c = acc[mi * 4 + ni];
                    asm volatile(
                        "mma.sync.aligned.m16n8k8.row.col.f32.tf32.tf32.f32 "
                        "{%0,%1,%2,%3}, {%4,%5,%6,%7}, {%8,%9}, {%0,%1,%2,%3};"
                        : "+f"(c[0]), "+f"(c[1]), "+f"(c[2]), "+f"(c[3])
                        : "r"(af[mi][0]), "r"(af[mi][1]), "r"(af[mi][2]), "r"(af[mi][3]),
                          "r"(bf[ni][0]), "r"(bf[ni][1]));
                }
        }
        if (kt + 1 < nk) {
            float* d0 = &As[nxt][ar][ac];
            d0[0] = totf32(a0v.x); d0[1] = totf32(a0v.y); d0[2] = totf32(a0v.z); d0[3] = totf32(a0v.w);
            float* d1 = &As[nxt][64 + ar][ac];
            d1[0] = totf32(a1v.x); d1[1] = totf32(a1v.y); d1[2] = totf32(a1v.z); d1[3] = totf32(a1v.w);
            float* e0 = &Bs[nxt][br][bc];
            e0[0] = totf32(b0v.x); e0[1] = totf32(b0v.y); e0[2] = totf32(b0v.z); e0[3] = totf32(b0v.w);
            float* e1 = &Bs[nxt][8 + br][bc];
            e1[0] = totf32(b1v.x); e1[1] = totf32(b1v.y); e1[2] = totf32(b1v.z); e1[3] = totf32(b1v.w);
            __syncthreads();
        }
    }

    bool asbf = (Cb != nullptr) && (col0 < PB);
#pragma unroll
    for (int mi = 0; mi < 4; mi++)
#pragma unroll
        for (int ni = 0; ni < 4; ni++) {
            float* c = acc[mi * 4 + ni];
            int r = row0 + wm + mi * 16 + g;
            int col = col0 + wn + ni * 8 + 2 * tg;
            if (asbf) {
                *(__nv_bfloat162*)(Cb + (size_t)r * PB + col) =
                    __floats2bfloat162_rn(c[0], c[1]);
                *(__nv_bfloat162*)(Cb + (size_t)(r + 8) * PB + col) =
                    __floats2bfloat162_rn(c[2], c[3]);
            } else {
                *(float2*)(C + (size_t)r * ldc + col) = make_float2(c[0], c[1]);
                *(float2*)(C + (size_t)(r + 8) * ldc + col) = make_float2(c[2], c[3]);
            }
        }
}

// ---------------------------------------------------------------------------
// F16 GEMM (backward): C[M,128] = A[M,K](f16) * Bt[128,K]^T(f16), fp32 out.
// 128x128 block, m16n8k16 MMA, double-buffered. Kdim mult of 16.
// ---------------------------------------------------------------------------
__global__ void __launch_bounds__(256)
k_gemm_f16(const __half* __restrict__ A, int lda,
           const __half* __restrict__ Bt, int ldb,
           float* __restrict__ C, int ldc, int Kdim) {
    __shared__ __half As[2][128][24];
    __shared__ __half Bs[2][128][24];
    int tid = threadIdx.x;
    int warp = tid >> 5, lane = tid & 31;
    int g = lane >> 2, tg = lane & 3;
    int wm = (warp >> 2) * 64;
    int wn = (warp & 3) * 32;
    int row0 = blockIdx.y * 128, col0 = blockIdx.x * 128;
    int lr = tid >> 1;             // 0..127
    int lc = (tid & 1) * 8;        // 0 or 8
    const __half* Ap = A + (size_t)(row0 + lr) * lda + lc;
    const __half* Bp = Bt + (size_t)(col0 + lr) * ldb + lc;

    float acc[16][4];
#pragma unroll
    for (int i = 0; i < 16; i++)
#pragma unroll
        for (int j = 0; j < 4; j++) acc[i][j] = 0.f;

    uint4 av = *(const uint4*)Ap;
    uint4 bv = *(const uint4*)Bp;
    *(uint4*)&As[0][lr][lc] = av;
    *(uint4*)&Bs[0][lr][lc] = bv;
    __syncthreads();

    int nk = Kdim >> 4;
    for (int kt = 0; kt < nk; kt++) {
        int cur = kt & 1, nxt = cur ^ 1;
        if (kt + 1 < nk) {
            av = *(const uint4*)(Ap + (kt + 1) * 16);
            bv = *(const uint4*)(Bp + (kt + 1) * 16);
        }
        uint32_t af[4][4], bf[4][2];
#pragma unroll
        for (int mi = 0; mi < 4; mi++) {
            int r = wm + mi * 16 + g;
            af[mi][0] = *(const uint32_t*)&As[cur][r][2 * tg];
            af[mi][1] = *(const uint32_t*)&As[cur][r + 8][2 * tg];
            af[mi][2] = *(const uint32_t*)&As[cur][r][2 * tg + 8];
            af[mi][3] = *(const uint32_t*)&As[cur][r + 8][2 * tg + 8];
        }
#pragma unroll
        for (int ni = 0; ni < 4; ni++) {
            int n = wn + ni * 8 + g;
            bf[ni][0] = *(const uint32_t*)&Bs[cur][n][2 * tg];
            bf[ni][1] = *(const uint32_t*)&Bs[cur][n][2 * tg + 8];
        }
#pragma unroll
        for (int mi = 0; mi < 4; mi++)
#pragma unroll
            for (int ni = 0; ni < 4; ni++) {
                float* c = acc[mi * 4 + ni];
                asm volatile(
                    "mma.sync.aligned.m16n8k16.row.col.f32.f16.f16.f32 "
                    "{%0,%1,%2,%3}, {%4,%5,%6,%7}, {%8,%9}, {%0,%1,%2,%3};"
                    : "+f"(c[0]), "+f"(c[1]), "+f"(c[2]), "+f"(c[3])
                    : "r"(af[mi][0]), "r"(af[mi][1]), "r"(af[mi][2]), "r"(af[mi][3]),
                      "r"(bf[ni][0]), "r"(bf[ni][1]));
            }
        if (kt + 1 < nk) {
            *(uint4*)&As[nxt][lr][lc] = av;
            *(uint4*)&Bs[nxt][lr][lc] = bv;
            __syncthreads();
        }
    }
#pragma unroll
    for (int mi = 0; mi < 4; mi++)
#pragma unroll
        for (int ni = 0; ni < 4; ni++) {
            float* c = acc[mi * 4 + ni];
            int r = row0 + wm + mi * 16 + g;
            int col = col0 + wn + ni * 8 + 2 * tg;
            *(float2*)(C + (size_t)r * ldc + col) = make_float2(c[0], c[1]);
            *(float2*)(C + (size_t)(r + 8) * ldc + col) = make_float2(c[2], c[3]);
        }
}

// ---------------------------------------------------------------------------
// Pair forward: warp per edge; stores exp(s2); Z2 via atomic
// ---------------------------------------------------------------------------
__global__ void k_pair_fwd(const int* __restrict__ c2, const int* __restrict__ u2,
                           const float* __restrict__ a2) {
    int e = (blockIdx.x * 256 + threadIdx.x) >> 5;
    int lane = threadIdx.x & 31;
    if (e >= Ee) return;
    int c = c2[e], u = u2[e];
    float q[4], k[4];
    ld4bf(g_Pb + (size_t)c * PB + lane * 4, q);
    ld4bf(g_Pb + (size_t)u * PB + 128 + lane * 4, k);
    float part = q[0] * k[0] + q[1] * k[1] + q[2] * k[2] + q[3] * k[3];
    part = wsum16(part);
    int h = lane >> 4;
    if ((lane & 15) == 0) {
        float s = part * 0.125f + a2[e * 2 + h];
        float ex = __expf(s);
        g_s2[(size_t)e * 2 + h] = ex;
        atomicAdd(&g_Z2[c * 2 + h], ex);
    }
}

// Pair backward: 16 lanes -> dQ2[c], 16 lanes -> dK2[u]. ONE gather + ONE f16 RED per lane.
__global__ void k_pair_bwd(const int* __restrict__ c2, const int* __restrict__ u2) {
    int e = (blockIdx.x * 256 + threadIdx.x) >> 5;
    int lane = threadIdx.x & 31;
    if (e >= Ee) return;
    int c = c2[e], u = u2[e];
    float2 ex = *(const float2*)&g_s2[(size_t)e * 2];
    float2 Z  = *(const float2*)&g_Z2[c * 2];
    float wt0 = -0.125f * ex.x / Z.x;
    float wt1 = -0.125f * ex.y / Z.y;
    int dk_side = lane >> 4;       // 0: dQ2[c] += wt*K2[u]; 1: dK2[u] += wt*Q2[c]
    int i = lane & 15;             // 8-col slot (cols i*8 .. i*8+7 within the 128-block)
    float wt = (i >> 3) ? wt1 : wt0;
    const __nv_bfloat16* src = dk_side ? (g_Pb + (size_t)c * PB + i * 8)
                                       : (g_Pb + (size_t)u * PB + 128 + i * 8);
    float v[8];
    ld8bf(src, v);
    uint32_t p0 = pack2h(wt * v[0], wt * v[1]);
    uint32_t p1 = pack2h(wt * v[2], wt * v[3]);
    uint32_t p2 = pack2h(wt * v[4], wt * v[5]);
    uint32_t p3 = pack2h(wt * v[6], wt * v[7]);
    __half* dst = dk_side ? (g_Uh + (size_t)u * PW + 128 + i * 8)
                          : (g_Uh + (size_t)c * PW + i * 8);
    red_add_v4h(dst, p0, p1, p2, p3);
}

// ---------------------------------------------------------------------------
// Motif forward: warp per motif; stores exp(s3)
// ---------------------------------------------------------------------------
__global__ void k_motif_fwd(const int* __restrict__ c3, const int* __restrict__ u3,
                            const int* __restrict__ v3, const int* __restrict__ tt,
                            const float* __restrict__ Ttau) {
    int m = (blockIdx.x * 256 + threadIdx.x) >> 5;
    int lane = threadIdx.x & 31;
    if (m >= Mm) return;
    int c = c3[m], ua = u3[m], vb = v3[m], t = tt[m];
    int off = lane * 8;
    float q[8], ku[8], kv[8];
    ld8bf(g_Pb + (size_t)c  * PB + 256 + off, q);
    ld8bf(g_Pb + (size_t)ua * PB + 512 + off, ku);
    ld8bf(g_Pb + (size_t)vb * PB + 512 + off, kv);
    const float* tp = Ttau + t * 256 + off;
    float qk = 0.f, tv = 0.f;
#pragma unroll
    for (int i = 0; i < 8; i++) {
        qk += q[i] * ku[i];
        tv += tp[i] * kv[i];
    }
    qk = wsum8(qk);
    tv = wsum8(tv);
    int g = lane >> 3;
    if ((lane & 7) == 0) {
        g_qk[(size_t)m * 4 + g] = qk;
        g_tv[(size_t)m * 4 + g] = tv;
    }
    float qk0 = __shfl_sync(0xffffffffu, qk, 0),  tv0 = __shfl_sync(0xffffffffu, tv, 0);
    float qk1 = __shfl_sync(0xffffffffu, qk, 8),  tv1 = __shfl_sync(0xffffffffu, tv, 8);
    float qk2 = __shfl_sync(0xffffffffu, qk, 16), tv2 = __shfl_sync(0xffffffffu, tv, 16);
    float qk3 = __shfl_sync(0xffffffffu, qk, 24), tv3 = __shfl_sync(0xffffffffu, tv, 24);
    if (lane < 2) {
        float s3 = (lane == 0) ? (qk0 * tv0 + qk1 * tv1) * (1.0f / 64)
                               : (qk2 * tv2 + qk3 * tv3) * (1.0f / 64);
        float ex = __expf(s3);
        g_s3[(size_t)m * 2 + lane] = ex;
        atomicAdd(&g_Z3[c * 2 + lane], ex);
    }
}

// Motif backward: 3 gathers + 3 f16 REDs per warp (was 6 fp32 REDs)
__global__ void k_motif_bwd(const int* __restrict__ c3, const int* __restrict__ u3,
                            const int* __restrict__ v3, const int* __restrict__ tt) {
    int m = (blockIdx.x * 256 + threadIdx.x) >> 5;
    int lane = threadIdx.x & 31;
    if (m >= Mm) return;
    int c = c3[m], ua = u3[m], vb = v3[m], t = tt[m];
    int g = lane >> 3;
    int h = g >> 1;
    float2 ex = *(const float2*)&g_s3[(size_t)m * 2];
    float2 Z  = *(const float2*)&g_Z3[c * 2];
    float p = h ? (ex.y / Z.y) : (ex.x / Z.x);
    float gg = -LAM3 * p * (1.0f / 64);
    float cA = gg * g_tv[(size_t)m * 4 + g];
    float cB = gg * g_qk[(size_t)m * 4 + g];
    int off = lane * 8;
    float q[8], ku[8], tp8[8];
    ld8bf(g_Pb + (size_t)c  * PB + 256 + off, q);
    ld8bf(g_Pb + (size_t)ua * PB + 512 + off, ku);
    ld8bf(g_TtH + t * 256 + off, tp8);
    __half* dq  = g_Uh + (size_t)c  * PW + 256 + off;
    __half* dku = g_Uh + (size_t)ua * PW + 512 + off;
    __half* dkv = g_Uh + (size_t)vb * PW + 512 + off;
    red_add_v4h(dq,  pack2h(cA*ku[0],cA*ku[1]), pack2h(cA*ku[2],cA*ku[3]),
                     pack2h(cA*ku[4],cA*ku[5]), pack2h(cA*ku[6],cA*ku[7]));
    red_add_v4h(dku, pack2h(cA*q[0],cA*q[1]),   pack2h(cA*q[2],cA*q[3]),
                     pack2h(cA*q[4],cA*q[5]),   pack2h(cA*q[6],cA*q[7]));
    red_add_v4h(dkv, pack2h(cB*tp8[0],cB*tp8[1]), pack2h(cB*tp8[2],cB*tp8[3]),
                     pack2h(cB*tp8[4],cB*tp8[5]), pack2h(cB*tp8[6],cB*tp8[7]));
}

// ---------------------------------------------------------------------------
// Memory term: warp per (node, head). Vector qm load + shfl broadcast.
// ---------------------------------------------------------------------------
__global__ void k_mem() {
    int w = (blockIdx.x * 256 + threadIdx.x) >> 5;
    int lane = threadIdx.x & 31;
    if (w >= Nn * Hh) return;
    int n = w >> 1, h = w & 1;
    const float* qm = g_P + (size_t)n * PW + 768 + h * HDm;
    const float* kt = g_KmT + h * HDm * KSL;   // [z][k]
    const float* km = g_Km + h * KSL * HDm;    // [k][z]
    float2 qv = ((const float2*)qm)[lane];     // z = 2*lane, 2*lane+1
    float sm = 0.f;
#pragma unroll
    for (int z2 = 0; z2 < 32; z2++) {
        float qa = __shfl_sync(0xffffffffu, qv.x, z2);
        float qb = __shfl_sync(0xffffffffu, qv.y, z2);
        sm += qa * kt[(2 * z2) * KSL + lane] + qb * kt[(2 * z2 + 1) * KSL + lane];
    }
    sm *= 0.125f;
    float e = __expf(sm);
    float Z = wsum32(e);
    float p = e / Z;
    if (lane == 0) g_Lm[w] = logf(Z);
    float a0 = 0.f, a1 = 0.f;
#pragma unroll
    for (int kk = 0; kk < KSL; kk++) {
        float pk = __shfl_sync(0xffffffffu, p, kk);
        a0 += pk * km[kk * HDm + lane];
        a1 += pk * km[kk * HDm + lane + 32];
    }
    __half* du = g_Uh + (size_t)n * PW + 768 + h * HDm;
    du[lane] = __float2half(-0.125f * a0);
    du[lane + 32] = __float2half(-0.125f * a1);
}

// ---------------------------------------------------------------------------
// Per-node energy + per-graph reduction
// ---------------------------------------------------------------------------
__global__ void k_energy(const float* __restrict__ X, const int* __restrict__ batch,
                         float* __restrict__ Eg) {
    __shared__ float bins[NGg];
    int tid = threadIdx.x;
    if (tid < NGg) bins[tid] = 0.f;
    __syncthreads();
    int w = (blockIdx.x * 256 + tid) >> 5;
    int lane = tid & 31;
    if (w < Nn) {
        const float4 x = *(const float4*)(X + (size_t)w * Dd + lane * 4);
        float ss = wsum32(x.x * x.x + x.y * x.y + x.z * x.z + x.w * x.w);
        if (lane == 0) {
            float e = 0.5f * ss;
            float z0 = g_Z2[w * 2], z1 = g_Z2[w * 2 + 1];
            e -= (z0 > 0.f ? logf(z0) : 0.f) + (z1 > 0.f ? logf(z1) : 0.f);
            float y0 = g_Z3[w * 2], y1 = g_Z3[w * 2 + 1];
            e -= LAM3 * ((y0 > 0.f ? logf(y0) : 0.f) + (y1 > 0.f ? logf(y1) : 0.f));
            e -= g_Lm[w * 2] + g_Lm[w * 2 + 1];
            atomicAdd(&bins[batch[w]], e);
        }
    }
    __syncthreads();
    if (tid < NGg) atomicAdd(&Eg[tid], bins[tid]);
}

// ---------------------------------------------------------------------------
// LN backward + grad clip + step + state clip
// ---------------------------------------------------------------------------
__global__ void k_final(const float* __restrict__ X, const float* __restrict__ gamma,
                        const float* __restrict__ step, float* __restrict__ out) {
    int w = (blockIdx.x * blockDim.x + threadIdx.x) >> 5;
    int lane = threadIdx.x & 31;
    if (w >= Nn) return;
    const float4 x = *(const float4*)(X + (size_t)w * Dd + lane * 4);
    const float4 dg = *(const float4*)(g_dG + (size_t)w * Dd + lane * 4);
    const float4 gm = *(const float4*)(gamma + lane * 4);
    float mu = g_mu[w], rstd = g_rstd[w];
    float4 xh = make_float4((x.x - mu) * rstd, (x.y - mu) * rstd,
                            (x.z - mu) * rstd, (x.w - mu) * rstd);
    float4 dxh = make_float4(dg.x * gm.x, dg.y * gm.y, dg.z * gm.z, dg.w * gm.w);
    float S1 = wsum32(dxh.x + dxh.y + dxh.z + dxh.w) * (1.0f / Dd);
    float S2 = wsum32(dxh.x * xh.x + dxh.y * xh.y + dxh.z * xh.z + dxh.w * xh.w) * (1.0f / Dd);
    float4 g;
    g.x = x.x + rstd * (dxh.x - S1 - xh.x * S2);
    g.y = x.y + rstd * (dxh.y - S1 - xh.y * S2);
    g.z = x.z + rstd * (dxh.z - S1 - xh.z * S2);
    g.w = x.w + rstd * (dxh.w - S1 - xh.w * S2);
    float gss = wsum32(g.x * g.x + g.y * g.y + g.z * g.z + g.w * g.w);
    float sc1 = 1.0f / fmaxf(sqrtf(gss), 1.0f);
    float st = step[0] * sc1;
    float4 xn = make_float4(x.x - st * g.x, x.y - st * g.y,
                            x.z - st * g.z, x.w - st * g.w);
    float sn = wsum32(xn.x * xn.x + xn.y * xn.y + xn.z * xn.z + xn.w * xn.w);
    float sc2 = 10.0f / fmaxf(sqrtf(sn), 10.0f);
    float4 o = make_float4(xn.x * sc2, xn.y * sc2, xn.z * sc2, xn.w * sc2);
    *(float4*)(out + (size_t)w * Dd + lane * 4) = o;
}

// ---------------------------------------------------------------------------
// Launch
// ---------------------------------------------------------------------------
extern "C" void kernel_launch(void* const* d_in, const int* in_sizes, int n_in,
                              void* d_out, int out_size) {
    const float* X    = (const float*)d_in[0];
    const int* c2     = (const int*)d_in[1];
    const int* u2     = (const int*)d_in[2];
    const int* c3     = (const int*)d_in[3];
    const int* u3     = (const int*)d_in[4];
    const int* v3     = (const int*)d_in[5];
    const int* tt     = (const int*)d_in[6];
    const int* batch  = (const int*)d_in[7];
    const float* a2   = (const float*)d_in[8];
    const float* step = (const float*)d_in[9];
    const float* gamma= (const float*)d_in[10];
    const float* beta = (const float*)d_in[11];
    const float* WQ2  = (const float*)d_in[12];
    const float* WK2  = (const float*)d_in[13];
    const float* WQ3  = (const float*)d_in[14];
    const float* WK3  = (const float*)d_in[15];
    const float* Ttau = (const float*)d_in[16];
    const float* WQm  = (const float*)d_in[17];
    const float* WKm  = (const float*)d_in[18];
    const float* Bmem = (const float*)d_in[19];
    float* out = (float*)d_out;
    float* Eg  = out + (size_t)Nn * Dd;

    void *pUh, *pZ2, *pZ3, *pG, *pP, *pPb, *pWcT, *pWcHT, *pdG;
    cudaGetSymbolAddress(&pUh, g_Uh);
    cudaGetSymbolAddress(&pZ2, g_Z2);
    cudaGetSymbolAddress(&pZ3, g_Z3);
    cudaGetSymbolAddress(&pG, g_G);
    cudaGetSymbolAddress(&pP, g_P);
    cudaGetSymbolAddress(&pPb, g_Pb);
    cudaGetSymbolAddress(&pWcT, g_WcatT);
    cudaGetSymbolAddress(&pWcHT, g_WcatHT);
    cudaGetSymbolAddress(&pdG, g_dG);

    cudaMemsetAsync(pUh, 0, sizeof(__half) * (size_t)Nn * PW);
    cudaMemsetAsync(pZ2, 0, sizeof(float) * Nn * Hh);
    cudaMemsetAsync(pZ3, 0, sizeof(float) * Nn * Hh);
    cudaMemsetAsync(Eg, 0, sizeof(float) * NGg);

    k_ln<<<Nn / 8, 256>>>(X, gamma, beta);
    k_wcat<<<(PW * Dd + 255) / 256, 256>>>(WQ2, WK2, WQ3, WK3, WQm, Ttau);
    k_km<<<(Hh * KSL * HDm + 255) / 256, 256>>>(Bmem, WKm);

    // Forward projections (tf32 tensor cores; bf16 out for cols<768)
    k_gemm_tf32<<<dim3(PW / 128, Nn / 128), 256>>>((const float*)pG, Dd,
                                                   (const float*)pWcT, PW,
                                                   (float*)pP, PW, Dd,
                                                   (__nv_bfloat16*)pPb);

    k_pair_fwd<<<Ee / 8, 256>>>(c2, u2, a2);
    k_motif_fwd<<<Mm / 8, 256>>>(c3, u3, v3, tt, Ttau);
    k_mem<<<(Nn * Hh) / 8, 256>>>();

    k_energy<<<Nn / 8, 256>>>(X, batch, Eg);

    k_pair_bwd<<<Ee / 8, 256>>>(c2, u2);
    k_motif_bwd<<<Mm / 8, 256>>>(c3, u3, v3, tt);

    // Backward projections (f16 tensor cores): dG = U[N,896] x Wcat[896,128]
    k_gemm_f16<<<dim3(Dd / 128, Nn / 128), 256>>>((const __half*)pUh, PW,
                                                  (const __half*)pWcHT, PW,
                                                  (float*)pdG, Dd, PW);

    k_final<<<Nn / 8, 256>>>(X, gamma, step, out);
}

// round 8
// speedup vs baseline: 3.0284x; 1.1002x over previous
#include <cuda_runtime.h>
#include <cuda_bf16.h>
#include <cuda_fp16.h>
#include <math.h>
#include <stdint.h>

// ---------------------------------------------------------------------------
// Problem constants
// ---------------------------------------------------------------------------
#define Nn   32768
#define Dd   128
#define Hh   2
#define HDm  64
#define Ee   262144
#define Mm   131072
#define NGg  32
#define PW   896          // 128(Q2)+128(K2)+256(Q3)+256(K3)+128(Qm)
#define PB   768          // bf16 mirror width (Q2|K2|Q3|K3)
#define KSL  32
#define TMt  2
#define LAM3 0.5f
#define EPSV 1e-5f

// ---------------------------------------------------------------------------
// Scratch
// ---------------------------------------------------------------------------
__device__ __align__(256) __nv_bfloat16 g_Gh[(size_t)Nn * Dd];  // bf16 LN output
__device__ float g_mu[Nn];
__device__ float g_rstd[Nn];
__device__ float g_P[(size_t)Nn * PW];                          // Qm cols (768..) fp32
__device__ __align__(256) __nv_bfloat16 g_Pb[(size_t)Nn * PB];  // bf16 cols 0..767
__device__ __align__(256) __half g_Uh[(size_t)Nn * PW];         // f16 grad accumulator
__device__ float g_dG[(size_t)Nn * Dd];
__device__ __align__(256) __nv_bfloat16 g_WcatB[PW * Dd];       // bf16 [j][d] for fwd GEMM
__device__ __align__(256) __half g_WcatHT[Dd * PW];             // f16 [d][j] for bwd GEMM
__device__ __nv_bfloat16 g_TtH[TMt * Hh * 2 * HDm];             // bf16 Ttau mirror
__device__ float g_Km[Hh * KSL * HDm];     // [h][k][z]
__device__ float g_KmT[Hh * HDm * KSL];    // [h][z][k]
__device__ float g_s2[(size_t)Ee * Hh];    // exp(s2)
__device__ float g_Z2[Nn * Hh];
__device__ float g_qk[(size_t)Mm * 4];
__device__ float g_tv[(size_t)Mm * 4];
__device__ float g_s3[(size_t)Mm * Hh];    // exp(s3)
__device__ float g_Z3[Nn * Hh];
__device__ float g_Lm[Nn * Hh];

// ---------------------------------------------------------------------------
// Helpers
// ---------------------------------------------------------------------------
__device__ __forceinline__ float wsum32(float v) {
#pragma unroll
    for (int m = 16; m > 0; m >>= 1) v += __shfl_xor_sync(0xffffffffu, v, m);
    return v;
}
__device__ __forceinline__ float wsum16(float v) {
#pragma unroll
    for (int m = 8; m > 0; m >>= 1) v += __shfl_xor_sync(0xffffffffu, v, m);
    return v;
}
__device__ __forceinline__ float wsum8(float v) {
#pragma unroll
    for (int m = 4; m > 0; m >>= 1) v += __shfl_xor_sync(0xffffffffu, v, m);
    return v;
}
__device__ __forceinline__ void red_add_v4h(__half* addr, uint32_t a, uint32_t b,
                                            uint32_t c, uint32_t d) {
    asm volatile("red.global.add.noftz.v4.f16x2 [%0], {%1, %2, %3, %4};"
                 :: "l"(addr), "r"(a), "r"(b), "r"(c), "r"(d) : "memory");
}
__device__ __forceinline__ uint32_t pack2h(float a, float b) {
    __half2 h = __floats2half2_rn(a, b);
    return *reinterpret_cast<uint32_t*>(&h);
}
__device__ __forceinline__ void ld4bf(const __nv_bfloat16* p, float* f) {
    uint2 r = *(const uint2*)p;
    __nv_bfloat162 h0 = *reinterpret_cast<const __nv_bfloat162*>(&r.x);
    __nv_bfloat162 h1 = *reinterpret_cast<const __nv_bfloat162*>(&r.y);
    float2 a = __bfloat1622float2(h0), b = __bfloat1622float2(h1);
    f[0] = a.x; f[1] = a.y; f[2] = b.x; f[3] = b.y;
}
__device__ __forceinline__ void ld8bf(const __nv_bfloat16* p, float* f) {
    uint4 r = *(const uint4*)p;
    __nv_bfloat162 h0 = *reinterpret_cast<const __nv_bfloat162*>(&r.x);
    __nv_bfloat162 h1 = *reinterpret_cast<const __nv_bfloat162*>(&r.y);
    __nv_bfloat162 h2 = *reinterpret_cast<const __nv_bfloat162*>(&r.z);
    __nv_bfloat162 h3 = *reinterpret_cast<const __nv_bfloat162*>(&r.w);
    float2 a = __bfloat1622float2(h0), b = __bfloat1622float2(h1);
    float2 c = __bfloat1622float2(h2), d = __bfloat1622float2(h3);
    f[0] = a.x; f[1] = a.y; f[2] = b.x; f[3] = b.y;
    f[4] = c.x; f[5] = c.y; f[6] = d.x; f[7] = d.y;
}
// mma m16n8k16, fp32 accum, per-type
__device__ __forceinline__ void mma16(float* c, const uint32_t* a, const uint32_t* b, __half) {
    asm volatile(
        "mma.sync.aligned.m16n8k16.row.col.f32.f16.f16.f32 "
        "{%0,%1,%2,%3}, {%4,%5,%6,%7}, {%8,%9}, {%0,%1,%2,%3};"
        : "+f"(c[0]), "+f"(c[1]), "+f"(c[2]), "+f"(c[3])
        : "r"(a[0]), "r"(a[1]), "r"(a[2]), "r"(a[3]), "r"(b[0]), "r"(b[1]));
}
__device__ __forceinline__ void mma16(float* c, const uint32_t* a, const uint32_t* b, __nv_bfloat16) {
    asm volatile(
        "mma.sync.aligned.m16n8k16.row.col.f32.bf16.bf16.f32 "
        "{%0,%1,%2,%3}, {%4,%5,%6,%7}, {%8,%9}, {%0,%1,%2,%3};"
        : "+f"(c[0]), "+f"(c[1]), "+f"(c[2]), "+f"(c[3])
        : "r"(a[0]), "r"(a[1]), "r"(a[2]), "r"(a[3]), "r"(b[0]), "r"(b[1]));
}

// ---------------------------------------------------------------------------
// LayerNorm forward -> bf16 G, saves mu/rstd
// ---------------------------------------------------------------------------
__global__ void k_ln(const float* __restrict__ X, const float* __restrict__ gamma,
                     const float* __restrict__ beta) {
    int w = (blockIdx.x * blockDim.x + threadIdx.x) >> 5;
    int lane = threadIdx.x & 31;
    if (w >= Nn) return;
    const float4 x = *(const float4*)(X + (size_t)w * Dd + lane * 4);
    float s = x.x + x.y + x.z + x.w;
    float mu = wsum32(s) * (1.0f / Dd);
    float4 xc = make_float4(x.x - mu, x.y - mu, x.z - mu, x.w - mu);
    float v = xc.x * xc.x + xc.y * xc.y + xc.z * xc.z + xc.w * xc.w;
    v = wsum32(v) * (1.0f / Dd);
    float rstd = rsqrtf(v + EPSV);
    const float4 g4 = *(const float4*)(gamma + lane * 4);
    const float4 b4 = *(const float4*)(beta + lane * 4);
    float Gx = g4.x * xc.x * rstd + b4.x;
    float Gy = g4.y * xc.y * rstd + b4.y;
    float Gz = g4.z * xc.z * rstd + b4.z;
    float Gw = g4.w * xc.w * rstd + b4.w;
    uint2 pk;
    __nv_bfloat162 h0 = __floats2bfloat162_rn(Gx, Gy);
    __nv_bfloat162 h1 = __floats2bfloat162_rn(Gz, Gw);
    pk.x = *reinterpret_cast<uint32_t*>(&h0);
    pk.y = *reinterpret_cast<uint32_t*>(&h1);
    *(uint2*)(g_Gh + (size_t)w * Dd + lane * 4) = pk;
    if (lane == 0) { g_mu[w] = mu; g_rstd[w] = rstd; }
}

// ---------------------------------------------------------------------------
// Stacked weights: bf16 [j][d] (fwd) + f16 [d][j] (bwd) + bf16 Ttau mirror
// ---------------------------------------------------------------------------
__global__ void k_wcat(const float* __restrict__ WQ2, const float* __restrict__ WK2,
                       const float* __restrict__ WQ3, const float* __restrict__ WK3,
                       const float* __restrict__ WQm, const float* __restrict__ Ttau) {
    int idx = blockIdx.x * blockDim.x + threadIdx.x;
    if (idx < TMt * Hh * 2 * HDm) g_TtH[idx] = __float2bfloat16(Ttau[idx]);
    if (idx >= PW * Dd) return;
    int j = idx / Dd, d = idx - j * Dd;
    float v;
    if (j < 128)      v = WQ2[j * Dd + d];
    else if (j < 256) v = WK2[(j - 128) * Dd + d];
    else if (j < 512) v = WQ3[(j - 256) * Dd + d];
    else if (j < 768) v = WK3[(j - 512) * Dd + d];
    else              v = WQm[(j - 768) * Dd + d];
    g_WcatB[j * Dd + d] = __float2bfloat16(v);
    g_WcatHT[d * PW + j] = __float2half(v);
}

// ---------------------------------------------------------------------------
// Km = B_mem @ W_Km^T per head (tiny), both layouts
// ---------------------------------------------------------------------------
__global__ void k_km(const float* __restrict__ Bm, const float* __restrict__ WKm) {
    int idx = blockIdx.x * blockDim.x + threadIdx.x;
    if (idx >= Hh * KSL * HDm) return;
    int h = idx / (KSL * HDm);
    int k = (idx / HDm) % KSL;
    int z = idx % HDm;
    const float* b = Bm + k * Dd;
    const float* w = WKm + (h * HDm + z) * Dd;
    float acc = 0.f;
#pragma unroll 8
    for (int d = 0; d < Dd; d++) acc += b[d] * w[d];
    g_Km[idx] = acc;
    g_KmT[(h * HDm + z) * KSL + k] = acc;
}

// ---------------------------------------------------------------------------
// 16-bit tensor GEMM: C[M,128cols-of-block] = A[M,K] * Bt[J,K]^T, fp32 accum.
// 128x128 block, m16n8k16, double-buffered. Kdim multiple of 16.
// SPLIT: column blocks with col0 < PB emit bf16 to Cb (stride PB), else fp32 C.
// ---------------------------------------------------------------------------
template<typename T, bool SPLIT>
__global__ void __launch_bounds__(256)
k_gemm16(const T* __restrict__ A, int lda,
         const T* __restrict__ Bt, int ldb,
         float* __restrict__ C, int ldc, int Kdim,
         __nv_bfloat16* __restrict__ Cb) {
    __shared__ T As[2][128][24];
    __shared__ T Bs[2][128][24];
    int tid = threadIdx.x;
    int warp = tid >> 5, lane = tid & 31;
    int g = lane >> 2, tg = lane & 3;
    int wm = (warp >> 2) * 64;
    int wn = (warp & 3) * 32;
    int row0 = blockIdx.y * 128, col0 = blockIdx.x * 128;
    int lr = tid >> 1;             // 0..127
    int lc = (tid & 1) * 8;        // 0 or 8
    const T* Ap = A + (size_t)(row0 + lr) * lda + lc;
    const T* Bp = Bt + (size_t)(col0 + lr) * ldb + lc;

    float acc[16][4];
#pragma unroll
    for (int i = 0; i < 16; i++)
#pragma unroll
        for (int j = 0; j < 4; j++) acc[i][j] = 0.f;

    uint4 av = *(const uint4*)Ap;
    uint4 bv = *(const uint4*)Bp;
    *(uint4*)&As[0][lr][lc] = av;
    *(uint4*)&Bs[0][lr][lc] = bv;
    __syncthreads();

    int nk = Kdim >> 4;
    for (int kt = 0; kt < nk; kt++) {
        int cur = kt & 1, nxt = cur ^ 1;
        if (kt + 1 < nk) {
            av = *(const uint4*)(Ap + (kt + 1) * 16);
            bv = *(const uint4*)(Bp + (kt + 1) * 16);
        }
        uint32_t af[4][4], bf[4][2];
#pragma unroll
        for (int mi = 0; mi < 4; mi++) {
            int r = wm + mi * 16 + g;
            af[mi][0] = *(const uint32_t*)&As[cur][r][2 * tg];
            af[mi][1] = *(const uint32_t*)&As[cur][r + 8][2 * tg];
            af[mi][2] = *(const uint32_t*)&As[cur][r][2 * tg + 8];
            af[mi][3] = *(const uint32_t*)&As[cur][r + 8][2 * tg + 8];
        }
#pragma unroll
        for (int ni = 0; ni < 4; ni++) {
            int n = wn + ni * 8 + g;
            bf[ni][0] = *(const uint32_t*)&Bs[cur][n][2 * tg];
            bf[ni][1] = *(const uint32_t*)&Bs[cur][n][2 * tg + 8];
        }
#pragma unroll
        for (int mi = 0; mi < 4; mi++)
#pragma unroll
            for (int ni = 0; ni < 4; ni++)
                mma16(acc[mi * 4 + ni], af[mi], bf[ni], T{});
        if (kt + 1 < nk) {
            *(uint4*)&As[nxt][lr][lc] = av;
            *(uint4*)&Bs[nxt][lr][lc] = bv;
            __syncthreads();
        }
    }
    bool asbf = SPLIT && (col0 < PB);
#pragma unroll
    for (int mi = 0; mi < 4; mi++)
#pragma unroll
        for (int ni = 0; ni < 4; ni++) {
            float* c = acc[mi * 4 + ni];
            int r = row0 + wm + mi * 16 + g;
            int col = col0 + wn + ni * 8 + 2 * tg;
            if (asbf) {
                *(__nv_bfloat162*)(Cb + (size_t)r * PB + col) =
                    __floats2bfloat162_rn(c[0], c[1]);
                *(__nv_bfloat162*)(Cb + (size_t)(r + 8) * PB + col) =
                    __floats2bfloat162_rn(c[2], c[3]);
            } else {
                *(float2*)(C + (size_t)r * ldc + col) = make_float2(c[0], c[1]);
                *(float2*)(C + (size_t)(r + 8) * ldc + col) = make_float2(c[2], c[3]);
            }
        }
}

// ---------------------------------------------------------------------------
// Pair forward: warp per edge; stores exp(s2)
// ---------------------------------------------------------------------------
__global__ void k_pair_fwd(const int* __restrict__ c2, const int* __restrict__ u2,
                           const float* __restrict__ a2) {
    int e = (blockIdx.x * 256 + threadIdx.x) >> 5;
    int lane = threadIdx.x & 31;
    if (e >= Ee) return;
    int c = c2[e], u = u2[e];
    float q[4], k[4];
    ld4bf(g_Pb + (size_t)c * PB + lane * 4, q);
    ld4bf(g_Pb + (size_t)u * PB + 128 + lane * 4, k);
    float part = q[0] * k[0] + q[1] * k[1] + q[2] * k[2] + q[3] * k[3];
    part = wsum16(part);
    int h = lane >> 4;
    if ((lane & 15) == 0) {
        float s = part * 0.125f + a2[e * 2 + h];
        float ex = __expf(s);
        g_s2[(size_t)e * 2 + h] = ex;
        atomicAdd(&g_Z2[c * 2 + h], ex);
    }
}

// Pair backward: 16 lanes -> dQ2[c], 16 lanes -> dK2[u]
__global__ void k_pair_bwd(const int* __restrict__ c2, const int* __restrict__ u2) {
    int e = (blockIdx.x * 256 + threadIdx.x) >> 5;
    int lane = threadIdx.x & 31;
    if (e >= Ee) return;
    int c = c2[e], u = u2[e];
    float2 ex = *(const float2*)&g_s2[(size_t)e * 2];
    float2 Z  = *(const float2*)&g_Z2[c * 2];
    float wt0 = -0.125f * ex.x / Z.x;
    float wt1 = -0.125f * ex.y / Z.y;
    int dk_side = lane >> 4;
    int i = lane & 15;
    float wt = (i >> 3) ? wt1 : wt0;
    const __nv_bfloat16* src = dk_side ? (g_Pb + (size_t)c * PB + i * 8)
                                       : (g_Pb + (size_t)u * PB + 128 + i * 8);
    float v[8];
    ld8bf(src, v);
    __half* dst = dk_side ? (g_Uh + (size_t)u * PW + 128 + i * 8)
                          : (g_Uh + (size_t)c * PW + i * 8);
    red_add_v4h(dst, pack2h(wt*v[0],wt*v[1]), pack2h(wt*v[2],wt*v[3]),
                     pack2h(wt*v[4],wt*v[5]), pack2h(wt*v[6],wt*v[7]));
}

// ---------------------------------------------------------------------------
// Motif forward: warp per motif; stores exp(s3)
// ---------------------------------------------------------------------------
__global__ void k_motif_fwd(const int* __restrict__ c3, const int* __restrict__ u3,
                            const int* __restrict__ v3, const int* __restrict__ tt,
                            const float* __restrict__ Ttau) {
    int m = (blockIdx.x * 256 + threadIdx.x) >> 5;
    int lane = threadIdx.x & 31;
    if (m >= Mm) return;
    int c = c3[m], ua = u3[m], vb = v3[m], t = tt[m];
    int off = lane * 8;
    float q[8], ku[8], kv[8];
    ld8bf(g_Pb + (size_t)c  * PB + 256 + off, q);
    ld8bf(g_Pb + (size_t)ua * PB + 512 + off, ku);
    ld8bf(g_Pb + (size_t)vb * PB + 512 + off, kv);
    const float* tp = Ttau + t * 256 + off;
    float qk = 0.f, tv = 0.f;
#pragma unroll
    for (int i = 0; i < 8; i++) {
        qk += q[i] * ku[i];
        tv += tp[i] * kv[i];
    }
    qk = wsum8(qk);
    tv = wsum8(tv);
    int g = lane >> 3;
    if ((lane & 7) == 0) {
        g_qk[(size_t)m * 4 + g] = qk;
        g_tv[(size_t)m * 4 + g] = tv;
    }
    float qk0 = __shfl_sync(0xffffffffu, qk, 0),  tv0 = __shfl_sync(0xffffffffu, tv, 0);
    float qk1 = __shfl_sync(0xffffffffu, qk, 8),  tv1 = __shfl_sync(0xffffffffu, tv, 8);
    float qk2 = __shfl_sync(0xffffffffu, qk, 16), tv2 = __shfl_sync(0xffffffffu, tv, 16);
    float qk3 = __shfl_sync(0xffffffffu, qk, 24), tv3 = __shfl_sync(0xffffffffu, tv, 24);
    if (lane < 2) {
        float s3 = (lane == 0) ? (qk0 * tv0 + qk1 * tv1) * (1.0f / 64)
                               : (qk2 * tv2 + qk3 * tv3) * (1.0f / 64);
        float ex = __expf(s3);
        g_s3[(size_t)m * 2 + lane] = ex;
        atomicAdd(&g_Z3[c * 2 + lane], ex);
    }
}

// Motif backward: 3 gathers + 3 f16 REDs per warp
__global__ void k_motif_bwd(const int* __restrict__ c3, const int* __restrict__ u3,
                            const int* __restrict__ v3, const int* __restrict__ tt) {
    int m = (blockIdx.x * 256 + threadIdx.x) >> 5;
    int lane = threadIdx.x & 31;
    if (m >= Mm) return;
    int c = c3[m], ua = u3[m], vb = v3[m], t = tt[m];
    int g = lane >> 3;
    int h = g >> 1;
    float2 ex = *(const float2*)&g_s3[(size_t)m * 2];
    float2 Z  = *(const float2*)&g_Z3[c * 2];
    float p = h ? (ex.y / Z.y) : (ex.x / Z.x);
    float gg = -LAM3 * p * (1.0f / 64);
    float cA = gg * g_tv[(size_t)m * 4 + g];
    float cB = gg * g_qk[(size_t)m * 4 + g];
    int off = lane * 8;
    float q[8], ku[8], tp8[8];
    ld8bf(g_Pb + (size_t)c  * PB + 256 + off, q);
    ld8bf(g_Pb + (size_t)ua * PB + 512 + off, ku);
    ld8bf(g_TtH + t * 256 + off, tp8);
    __half* dq  = g_Uh + (size_t)c  * PW + 256 + off;
    __half* dku = g_Uh + (size_t)ua * PW + 512 + off;
    __half* dkv = g_Uh + (size_t)vb * PW + 512 + off;
    red_add_v4h(dq,  pack2h(cA*ku[0],cA*ku[1]), pack2h(cA*ku[2],cA*ku[3]),
                     pack2h(cA*ku[4],cA*ku[5]), pack2h(cA*ku[6],cA*ku[7]));
    red_add_v4h(dku, pack2h(cA*q[0],cA*q[1]),   pack2h(cA*q[2],cA*q[3]),
                     pack2h(cA*q[4],cA*q[5]),   pack2h(cA*q[6],cA*q[7]));
    red_add_v4h(dkv, pack2h(cB*tp8[0],cB*tp8[1]), pack2h(cB*tp8[2],cB*tp8[3]),
                     pack2h(cB*tp8[4],cB*tp8[5]), pack2h(cB*tp8[6],cB*tp8[7]));
}

// ---------------------------------------------------------------------------
// Memory term: warp per (node, head)
// ---------------------------------------------------------------------------
__global__ void k_mem() {
    int w = (blockIdx.x * 256 + threadIdx.x) >> 5;
    int lane = threadIdx.x & 31;
    if (w >= Nn * Hh) return;
    int n = w >> 1, h = w & 1;
    const float* qm = g_P + (size_t)n * PW + 768 + h * HDm;
    const float* kt = g_KmT + h * HDm * KSL;
    const float* km = g_Km + h * KSL * HDm;
    float2 qv = ((const float2*)qm)[lane];
    float sm = 0.f;
#pragma unroll
    for (int z2 = 0; z2 < 32; z2++) {
        float qa = __shfl_sync(0xffffffffu, qv.x, z2);
        float qb = __shfl_sync(0xffffffffu, qv.y, z2);
        sm += qa * kt[(2 * z2) * KSL + lane] + qb * kt[(2 * z2 + 1) * KSL + lane];
    }
    sm *= 0.125f;
    float e = __expf(sm);
    float Z = wsum32(e);
    float p = e / Z;
    if (lane == 0) g_Lm[w] = logf(Z);
    float a0 = 0.f, a1 = 0.f;
#pragma unroll
    for (int kk = 0; kk < KSL; kk++) {
        float pk = __shfl_sync(0xffffffffu, p, kk);
        a0 += pk * km[kk * HDm + lane];
        a1 += pk * km[kk * HDm + lane + 32];
    }
    __half* du = g_Uh + (size_t)n * PW + 768 + h * HDm;
    du[lane] = __float2half(-0.125f * a0);
    du[lane + 32] = __float2half(-0.125f * a1);
}

// ---------------------------------------------------------------------------
// Fused: LN backward + grad clip + step + state clip + per-graph energy
// ---------------------------------------------------------------------------
__global__ void k_final(const float* __restrict__ X, const float* __restrict__ gamma,
                        const float* __restrict__ step, const int* __restrict__ batch,
                        float* __restrict__ out, float* __restrict__ Eg) {
    __shared__ float bins[NGg];
    int tid = threadIdx.x;
    if (tid < NGg) bins[tid] = 0.f;
    __syncthreads();
    int w = (blockIdx.x * blockDim.x + tid) >> 5;
    int lane = tid & 31;
    if (w < Nn) {
        const float4 x = *(const float4*)(X + (size_t)w * Dd + lane * 4);
        const float4 dg = *(const float4*)(g_dG + (size_t)w * Dd + lane * 4);
        const float4 gm = *(const float4*)(gamma + lane * 4);
        float mu = g_mu[w], rstd = g_rstd[w];
        float4 xh = make_float4((x.x - mu) * rstd, (x.y - mu) * rstd,
                                (x.z - mu) * rstd, (x.w - mu) * rstd);
        float4 dxh = make_float4(dg.x * gm.x, dg.y * gm.y, dg.z * gm.z, dg.w * gm.w);
        float S1 = wsum32(dxh.x + dxh.y + dxh.z + dxh.w) * (1.0f / Dd);
        float S2 = wsum32(dxh.x * xh.x + dxh.y * xh.y + dxh.z * xh.z + dxh.w * xh.w) * (1.0f / Dd);
        float ss = wsum32(x.x * x.x + x.y * x.y + x.z * x.z + x.w * x.w);
        float4 g;
        g.x = x.x + rstd * (dxh.x - S1 - xh.x * S2);
        g.y = x.y + rstd * (dxh.y - S1 - xh.y * S2);
        g.z = x.z + rstd * (dxh.z - S1 - xh.z * S2);
        g.w = x.w + rstd * (dxh.w - S1 - xh.w * S2);
        float gss = wsum32(g.x * g.x + g.y * g.y + g.z * g.z + g.w * g.w);
        float sc1 = 1.0f / fmaxf(sqrtf(gss), 1.0f);
        float st = step[0] * sc1;
        float4 xn = make_float4(x.x - st * g.x, x.y - st * g.y,
                                x.z - st * g.z, x.w - st * g.w);
        float sn = wsum32(xn.x * xn.x + xn.y * xn.y + xn.z * xn.z + xn.w * xn.w);
        float sc2 = 10.0f / fmaxf(sqrtf(sn), 10.0f);
        float4 o = make_float4(xn.x * sc2, xn.y * sc2, xn.z * sc2, xn.w * sc2);
        *(float4*)(out + (size_t)w * Dd + lane * 4) = o;
        if (lane == 0) {
            float e = 0.5f * ss;
            float z0 = g_Z2[w * 2], z1 = g_Z2[w * 2 + 1];
            e -= (z0 > 0.f ? logf(z0) : 0.f) + (z1 > 0.f ? logf(z1) : 0.f);
            float y0 = g_Z3[w * 2], y1 = g_Z3[w * 2 + 1];
            e -= LAM3 * ((y0 > 0.f ? logf(y0) : 0.f) + (y1 > 0.f ? logf(y1) : 0.f));
            e -= g_Lm[w * 2] + g_Lm[w * 2 + 1];
            atomicAdd(&bins[batch[w]], e);
        }
    }
    __syncthreads();
    if (tid < NGg) atomicAdd(&Eg[tid], bins[tid]);
}

// ---------------------------------------------------------------------------
// Launch
// ---------------------------------------------------------------------------
extern "C" void kernel_launch(void* const* d_in, const int* in_sizes, int n_in,
                              void* d_out, int out_size) {
    const float* X    = (const float*)d_in[0];
    const int* c2     = (const int*)d_in[1];
    const int* u2     = (const int*)d_in[2];
    const int* c3     = (const int*)d_in[3];
    const int* u3     = (const int*)d_in[4];
    const int* v3     = (const int*)d_in[5];
    const int* tt     = (const int*)d_in[6];
    const int* batch  = (const int*)d_in[7];
    const float* a2   = (const float*)d_in[8];
    const float* step = (const float*)d_in[9];
    const float* gamma= (const float*)d_in[10];
    const float* beta = (const float*)d_in[11];
    const float* WQ2  = (const float*)d_in[12];
    const float* WK2  = (const float*)d_in[13];
    const float* WQ3  = (const float*)d_in[14];
    const float* WK3  = (const float*)d_in[15];
    const float* Ttau = (const float*)d_in[16];
    const float* WQm  = (const float*)d_in[17];
    const float* WKm  = (const float*)d_in[18];
    const float* Bmem = (const float*)d_in[19];
    float* out = (float*)d_out;
    float* Eg  = out + (size_t)Nn * Dd;

    void *pUh, *pZ2, *pZ3, *pGh, *pP, *pPb, *pWcB, *pWcHT, *pdG;
    cudaGetSymbolAddress(&pUh, g_Uh);
    cudaGetSymbolAddress(&pZ2, g_Z2);
    cudaGetSymbolAddress(&pZ3, g_Z3);
    cudaGetSymbolAddress(&pGh, g_Gh);
    cudaGetSymbolAddress(&pP, g_P);
    cudaGetSymbolAddress(&pPb, g_Pb);
    cudaGetSymbolAddress(&pWcB, g_WcatB);
    cudaGetSymbolAddress(&pWcHT, g_WcatHT);
    cudaGetSymbolAddress(&pdG, g_dG);

    cudaMemsetAsync(pUh, 0, sizeof(__half) * (size_t)Nn * PW);
    cudaMemsetAsync(pZ2, 0, sizeof(float) * Nn * Hh);
    cudaMemsetAsync(pZ3, 0, sizeof(float) * Nn * Hh);
    cudaMemsetAsync(Eg, 0, sizeof(float) * NGg);

    k_ln<<<Nn / 8, 256>>>(X, gamma, beta);
    k_wcat<<<(PW * Dd + 255) / 256, 256>>>(WQ2, WK2, WQ3, WK3, WQm, Ttau);
    k_km<<<(Hh * KSL * HDm + 255) / 256, 256>>>(Bmem, WKm);

    // Forward projections (bf16 tensor cores): P = G x Wcat^T; bf16 out cols<768
    k_gemm16<__nv_bfloat16, true><<<dim3(PW / 128, Nn / 128), 256>>>(
        (const __nv_bfloat16*)pGh, Dd,
        (const __nv_bfloat16*)pWcB, Dd,
        (float*)pP, PW, Dd,
        (__nv_bfloat16*)pPb);

    k_pair_fwd<<<Ee / 8, 256>>>(c2, u2, a2);
    k_motif_fwd<<<Mm / 8, 256>>>(c3, u3, v3, tt, Ttau);
    k_mem<<<(Nn * Hh) / 8, 256>>>();

    k_pair_bwd<<<Ee / 8, 256>>>(c2, u2);
    k_motif_bwd<<<Mm / 8, 256>>>(c3, u3, v3, tt);

    // Backward projections (f16 tensor cores): dG = U[N,896] x Wcat[896,128]
    k_gemm16<__half, false><<<dim3(Dd / 128, Nn / 128), 256>>>(
        (const __half*)pUh, PW,
        (const __half*)pWcHT, PW,
        (float*)pdG, Dd, PW,
        nullptr);

    k_final<<<Nn / 8, 256>>>(X, gamma, step, batch, out, Eg);
}

// round 9
// speedup vs baseline: 3.0921x; 1.0210x over previous
#include <cuda_runtime.h>
#include <cuda_bf16.h>
#include <cuda_fp16.h>
#include <math.h>
#include <stdint.h>

// ---------------------------------------------------------------------------
// Problem constants
// ---------------------------------------------------------------------------
#define Nn   32768
#define Dd   128
#define Hh   2
#define HDm  64
#define Ee   262144
#define Mm   131072
#define NGg  32
#define PW   896          // 128(Q2)+128(K2)+256(Q3)+256(K3)+128(Qm)
#define PB   768          // bf16 mirror width (Q2|K2|Q3|K3)
#define KSL  32
#define TMt  2
#define LAM3 0.5f
#define EPSV 1e-5f

// ---------------------------------------------------------------------------
// Scratch
// ---------------------------------------------------------------------------
__device__ __align__(256) __nv_bfloat16 g_Gh[(size_t)Nn * Dd];  // bf16 LN output
__device__ float g_mu[Nn];
__device__ float g_rstd[Nn];
__device__ float g_P[(size_t)Nn * PW];                          // Qm cols (768..) fp32
__device__ __align__(256) __nv_bfloat16 g_Pb[(size_t)Nn * PB];  // bf16 cols 0..767
__device__ __align__(256) __half g_Uh[(size_t)Nn * PW];         // f16 grad accumulator
__device__ float g_dG[(size_t)Nn * Dd];
__device__ __align__(256) __nv_bfloat16 g_WcatB[PW * Dd];       // bf16 [j][d] for fwd GEMM
__device__ __align__(256) __half g_WcatHT[Dd * PW];             // f16 [d][j] for bwd GEMM
__device__ __nv_bfloat16 g_TtH[TMt * Hh * 2 * HDm];             // bf16 Ttau mirror
__device__ float g_Km[Hh * KSL * HDm];     // [h][k][z]
__device__ float g_KmT[Hh * HDm * KSL];    // [h][z][k]
__device__ float g_s2[(size_t)Ee * Hh];    // exp(s2)
__device__ float g_Z2[Nn * Hh];
__device__ float g_qk[(size_t)Mm * 4];
__device__ float g_tv[(size_t)Mm * 4];
__device__ float g_s3[(size_t)Mm * Hh];    // exp(s3)
__device__ float g_Z3[Nn * Hh];
__device__ float g_Lm[Nn * Hh];

// ---------------------------------------------------------------------------
// Helpers
// ---------------------------------------------------------------------------
__device__ __forceinline__ float wsum32(float v) {
#pragma unroll
    for (int m = 16; m > 0; m >>= 1) v += __shfl_xor_sync(0xffffffffu, v, m);
    return v;
}
__device__ __forceinline__ float wsum16(float v) {
#pragma unroll
    for (int m = 8; m > 0; m >>= 1) v += __shfl_xor_sync(0xffffffffu, v, m);
    return v;
}
__device__ __forceinline__ float wsum8(float v) {
#pragma unroll
    for (int m = 4; m > 0; m >>= 1) v += __shfl_xor_sync(0xffffffffu, v, m);
    return v;
}
__device__ __forceinline__ void red_add_v4h(__half* addr, uint32_t a, uint32_t b,
                                            uint32_t c, uint32_t d) {
    asm volatile("red.global.add.noftz.v4.f16x2 [%0], {%1, %2, %3, %4};"
                 :: "l"(addr), "r"(a), "r"(b), "r"(c), "r"(d) : "memory");
}
__device__ __forceinline__ uint32_t pack2h(float a, float b) {
    __half2 h = __floats2half2_rn(a, b);
    return *reinterpret_cast<uint32_t*>(&h);
}
__device__ __forceinline__ void ld4bf(const __nv_bfloat16* p, float* f) {
    uint2 r = *(const uint2*)p;
    __nv_bfloat162 h0 = *reinterpret_cast<const __nv_bfloat162*>(&r.x);
    __nv_bfloat162 h1 = *reinterpret_cast<const __nv_bfloat162*>(&r.y);
    float2 a = __bfloat1622float2(h0), b = __bfloat1622float2(h1);
    f[0] = a.x; f[1] = a.y; f[2] = b.x; f[3] = b.y;
}
__device__ __forceinline__ void ld8bf(const __nv_bfloat16* p, float* f) {
    uint4 r = *(const uint4*)p;
    __nv_bfloat162 h0 = *reinterpret_cast<const __nv_bfloat162*>(&r.x);
    __nv_bfloat162 h1 = *reinterpret_cast<const __nv_bfloat162*>(&r.y);
    __nv_bfloat162 h2 = *reinterpret_cast<const __nv_bfloat162*>(&r.z);
    __nv_bfloat162 h3 = *reinterpret_cast<const __nv_bfloat162*>(&r.w);
    float2 a = __bfloat1622float2(h0), b = __bfloat1622float2(h1);
    float2 c = __bfloat1622float2(h2), d = __bfloat1622float2(h3);
    f[0] = a.x; f[1] = a.y; f[2] = b.x; f[3] = b.y;
    f[4] = c.x; f[5] = c.y; f[6] = d.x; f[7] = d.y;
}
__device__ __forceinline__ void ldsm4(uint32_t* r, uint32_t addr) {
    asm volatile("ldmatrix.sync.aligned.m8n8.x4.shared.b16 {%0,%1,%2,%3}, [%4];"
                 : "=r"(r[0]), "=r"(r[1]), "=r"(r[2]), "=r"(r[3]) : "r"(addr));
}
__device__ __forceinline__ void mma16(float* c, const uint32_t* a, const uint32_t* b, __half) {
    asm volatile(
        "mma.sync.aligned.m16n8k16.row.col.f32.f16.f16.f32 "
        "{%0,%1,%2,%3}, {%4,%5,%6,%7}, {%8,%9}, {%0,%1,%2,%3};"
        : "+f"(c[0]), "+f"(c[1]), "+f"(c[2]), "+f"(c[3])
        : "r"(a[0]), "r"(a[1]), "r"(a[2]), "r"(a[3]), "r"(b[0]), "r"(b[1]));
}
__device__ __forceinline__ void mma16(float* c, const uint32_t* a, const uint32_t* b, __nv_bfloat16) {
    asm volatile(
        "mma.sync.aligned.m16n8k16.row.col.f32.bf16.bf16.f32 "
        "{%0,%1,%2,%3}, {%4,%5,%6,%7}, {%8,%9}, {%0,%1,%2,%3};"
        : "+f"(c[0]), "+f"(c[1]), "+f"(c[2]), "+f"(c[3])
        : "r"(a[0]), "r"(a[1]), "r"(a[2]), "r"(a[3]), "r"(b[0]), "r"(b[1]));
}

// ---------------------------------------------------------------------------
// LayerNorm forward -> bf16 G, saves mu/rstd
// ---------------------------------------------------------------------------
__global__ void k_ln(const float* __restrict__ X, const float* __restrict__ gamma,
                     const float* __restrict__ beta) {
    int w = (blockIdx.x * blockDim.x + threadIdx.x) >> 5;
    int lane = threadIdx.x & 31;
    if (w >= Nn) return;
    const float4 x = *(const float4*)(X + (size_t)w * Dd + lane * 4);
    float s = x.x + x.y + x.z + x.w;
    float mu = wsum32(s) * (1.0f / Dd);
    float4 xc = make_float4(x.x - mu, x.y - mu, x.z - mu, x.w - mu);
    float v = xc.x * xc.x + xc.y * xc.y + xc.z * xc.z + xc.w * xc.w;
    v = wsum32(v) * (1.0f / Dd);
    float rstd = rsqrtf(v + EPSV);
    const float4 g4 = *(const float4*)(gamma + lane * 4);
    const float4 b4 = *(const float4*)(beta + lane * 4);
    float Gx = g4.x * xc.x * rstd + b4.x;
    float Gy = g4.y * xc.y * rstd + b4.y;
    float Gz = g4.z * xc.z * rstd + b4.z;
    float Gw = g4.w * xc.w * rstd + b4.w;
    uint2 pk;
    __nv_bfloat162 h0 = __floats2bfloat162_rn(Gx, Gy);
    __nv_bfloat162 h1 = __floats2bfloat162_rn(Gz, Gw);
    pk.x = *reinterpret_cast<uint32_t*>(&h0);
    pk.y = *reinterpret_cast<uint32_t*>(&h1);
    *(uint2*)(g_Gh + (size_t)w * Dd + lane * 4) = pk;
    if (lane == 0) { g_mu[w] = mu; g_rstd[w] = rstd; }
}

// ---------------------------------------------------------------------------
// Stacked weights: bf16 [j][d] (fwd) + f16 [d][j] (bwd) + bf16 Ttau mirror
// ---------------------------------------------------------------------------
__global__ void k_wcat(const float* __restrict__ WQ2, const float* __restrict__ WK2,
                       const float* __restrict__ WQ3, const float* __restrict__ WK3,
                       const float* __restrict__ WQm, const float* __restrict__ Ttau) {
    int idx = blockIdx.x * blockDim.x + threadIdx.x;
    if (idx < TMt * Hh * 2 * HDm) g_TtH[idx] = __float2bfloat16(Ttau[idx]);
    if (idx >= PW * Dd) return;
    int j = idx / Dd, d = idx - j * Dd;
    float v;
    if (j < 128)      v = WQ2[j * Dd + d];
    else if (j < 256) v = WK2[(j - 128) * Dd + d];
    else if (j < 512) v = WQ3[(j - 256) * Dd + d];
    else if (j < 768) v = WK3[(j - 512) * Dd + d];
    else              v = WQm[(j - 768) * Dd + d];
    g_WcatB[j * Dd + d] = __float2bfloat16(v);
    g_WcatHT[d * PW + j] = __float2half(v);
}

// ---------------------------------------------------------------------------
// Km = B_mem @ W_Km^T per head (tiny), both layouts
// ---------------------------------------------------------------------------
__global__ void k_km(const float* __restrict__ Bm, const float* __restrict__ WKm) {
    int idx = blockIdx.x * blockDim.x + threadIdx.x;
    if (idx >= Hh * KSL * HDm) return;
    int h = idx / (KSL * HDm);
    int k = (idx / HDm) % KSL;
    int z = idx % HDm;
    const float* b = Bm + k * Dd;
    const float* w = WKm + (h * HDm + z) * Dd;
    float acc = 0.f;
#pragma unroll 8
    for (int d = 0; d < Dd; d++) acc += b[d] * w[d];
    g_Km[idx] = acc;
    g_KmT[(h * HDm + z) * KSL + k] = acc;
}

// ---------------------------------------------------------------------------
// 16-bit tensor GEMM with ldmatrix fragment loads.
// C[M,J] = A[M,K] * Bt[J,K]^T, fp32 accum. 128x128 block, m16n8k16.
// SPLIT: column blocks with col0 < PB emit bf16 to Cb (stride PB), else fp32 C.
// ---------------------------------------------------------------------------
template<typename T, bool SPLIT>
__global__ void __launch_bounds__(256)
k_gemm16(const T* __restrict__ A, int lda,
         const T* __restrict__ Bt, int ldb,
         float* __restrict__ C, int ldc, int Kdim,
         __nv_bfloat16* __restrict__ Cb) {
    __shared__ T As[2][128][24];
    __shared__ T Bs[2][128][24];
    int tid = threadIdx.x;
    int warp = tid >> 5, lane = tid & 31;
    int g = lane >> 2, tg = lane & 3;
    int wm = (warp >> 2) * 64;
    int wn = (warp & 3) * 32;
    int row0 = blockIdx.y * 128, col0 = blockIdx.x * 128;
    int lr = tid >> 1;             // 0..127
    int lc = (tid & 1) * 8;        // 0 or 8
    const T* Ap = A + (size_t)(row0 + lr) * lda + lc;
    const T* Bp = Bt + (size_t)(col0 + lr) * ldb + lc;

    // ldmatrix lane addresses:
    // A (m16k16 x4): row = wm + (lane&15), col = (lane>>4)*8    (+ mi*16 rows)
    // B (two n8 tiles per x4): row = wn + ((lane>>4)&1)*8 + (lane&7),
    //                          col = ((lane>>3)&1)*8            (+ ni2*16 rows)
    uint32_t aAddr[2], bAddr[2];
#pragma unroll
    for (int b = 0; b < 2; b++) {
        aAddr[b] = (uint32_t)__cvta_generic_to_shared(
            &As[b][wm + (lane & 15)][(lane >> 4) * 8]);
        bAddr[b] = (uint32_t)__cvta_generic_to_shared(
            &Bs[b][wn + ((lane >> 4) & 1) * 8 + (lane & 7)][((lane >> 3) & 1) * 8]);
    }
    const uint32_t rowPitch = 24 * sizeof(T);

    float acc[16][4];
#pragma unroll
    for (int i = 0; i < 16; i++)
#pragma unroll
        for (int j = 0; j < 4; j++) acc[i][j] = 0.f;

    uint4 av = *(const uint4*)Ap;
    uint4 bv = *(const uint4*)Bp;
    *(uint4*)&As[0][lr][lc] = av;
    *(uint4*)&Bs[0][lr][lc] = bv;
    __syncthreads();

    int nk = Kdim >> 4;
    for (int kt = 0; kt < nk; kt++) {
        int cur = kt & 1, nxt = cur ^ 1;
        if (kt + 1 < nk) {
            av = *(const uint4*)(Ap + (kt + 1) * 16);
            bv = *(const uint4*)(Bp + (kt + 1) * 16);
        }
        uint32_t af[4][4], bq[2][4];
#pragma unroll
        for (int mi = 0; mi < 4; mi++)
            ldsm4(af[mi], aAddr[cur] + mi * 16 * rowPitch);
#pragma unroll
        for (int ni2 = 0; ni2 < 2; ni2++)
            ldsm4(bq[ni2], bAddr[cur] + ni2 * 16 * rowPitch);
#pragma unroll
        for (int mi = 0; mi < 4; mi++)
#pragma unroll
            for (int ni = 0; ni < 4; ni++)
                mma16(acc[mi * 4 + ni], af[mi], &bq[ni >> 1][(ni & 1) * 2], T{});
        if (kt + 1 < nk) {
            *(uint4*)&As[nxt][lr][lc] = av;
            *(uint4*)&Bs[nxt][lr][lc] = bv;
            __syncthreads();
        }
    }
    bool asbf = SPLIT && (col0 < PB);
#pragma unroll
    for (int mi = 0; mi < 4; mi++)
#pragma unroll
        for (int ni = 0; ni < 4; ni++) {
            float* c = acc[mi * 4 + ni];
            int r = row0 + wm + mi * 16 + g;
            int col = col0 + wn + ni * 8 + 2 * tg;
            if (asbf) {
                *(__nv_bfloat162*)(Cb + (size_t)r * PB + col) =
                    __floats2bfloat162_rn(c[0], c[1]);
                *(__nv_bfloat162*)(Cb + (size_t)(r + 8) * PB + col) =
                    __floats2bfloat162_rn(c[2], c[3]);
            } else {
                *(float2*)(C + (size_t)r * ldc + col) = make_float2(c[0], c[1]);
                *(float2*)(C + (size_t)(r + 8) * ldc + col) = make_float2(c[2], c[3]);
            }
        }
}

// ---------------------------------------------------------------------------
// Pair forward: warp per edge; stores exp(s2)
// ---------------------------------------------------------------------------
__global__ void k_pair_fwd(const int* __restrict__ c2, const int* __restrict__ u2,
                           const float* __restrict__ a2) {
    int e = (blockIdx.x * 256 + threadIdx.x) >> 5;
    int lane = threadIdx.x & 31;
    if (e >= Ee) return;
    int c = c2[e], u = u2[e];
    float q[4], k[4];
    ld4bf(g_Pb + (size_t)c * PB + lane * 4, q);
    ld4bf(g_Pb + (size_t)u * PB + 128 + lane * 4, k);
    float part = q[0] * k[0] + q[1] * k[1] + q[2] * k[2] + q[3] * k[3];
    part = wsum16(part);
    int h = lane >> 4;
    if ((lane & 15) == 0) {
        float s = part * 0.125f + a2[e * 2 + h];
        float ex = __expf(s);
        g_s2[(size_t)e * 2 + h] = ex;
        atomicAdd(&g_Z2[c * 2 + h], ex);
    }
}

// Pair backward: 16 lanes -> dQ2[c], 16 lanes -> dK2[u]
__global__ void k_pair_bwd(const int* __restrict__ c2, const int* __restrict__ u2) {
    int e = (blockIdx.x * 256 + threadIdx.x) >> 5;
    int lane = threadIdx.x & 31;
    if (e >= Ee) return;
    int c = c2[e], u = u2[e];
    float2 ex = *(const float2*)&g_s2[(size_t)e * 2];
    float2 Z  = *(const float2*)&g_Z2[c * 2];
    float wt0 = -0.125f * ex.x / Z.x;
    float wt1 = -0.125f * ex.y / Z.y;
    int dk_side = lane >> 4;
    int i = lane & 15;
    float wt = (i >> 3) ? wt1 : wt0;
    const __nv_bfloat16* src = dk_side ? (g_Pb + (size_t)c * PB + i * 8)
                                       : (g_Pb + (size_t)u * PB + 128 + i * 8);
    float v[8];
    ld8bf(src, v);
    __half* dst = dk_side ? (g_Uh + (size_t)u * PW + 128 + i * 8)
                          : (g_Uh + (size_t)c * PW + i * 8);
    red_add_v4h(dst, pack2h(wt*v[0],wt*v[1]), pack2h(wt*v[2],wt*v[3]),
                     pack2h(wt*v[4],wt*v[5]), pack2h(wt*v[6],wt*v[7]));
}

// ---------------------------------------------------------------------------
// Motif forward: warp per motif; stores exp(s3)
// ---------------------------------------------------------------------------
__global__ void k_motif_fwd(const int* __restrict__ c3, const int* __restrict__ u3,
                            const int* __restrict__ v3, const int* __restrict__ tt,
                            const float* __restrict__ Ttau) {
    int m = (blockIdx.x * 256 + threadIdx.x) >> 5;
    int lane = threadIdx.x & 31;
    if (m >= Mm) return;
    int c = c3[m], ua = u3[m], vb = v3[m], t = tt[m];
    int off = lane * 8;
    float q[8], ku[8], kv[8];
    ld8bf(g_Pb + (size_t)c  * PB + 256 + off, q);
    ld8bf(g_Pb + (size_t)ua * PB + 512 + off, ku);
    ld8bf(g_Pb + (size_t)vb * PB + 512 + off, kv);
    const float* tp = Ttau + t * 256 + off;
    float qk = 0.f, tv = 0.f;
#pragma unroll
    for (int i = 0; i < 8; i++) {
        qk += q[i] * ku[i];
        tv += tp[i] * kv[i];
    }
    qk = wsum8(qk);
    tv = wsum8(tv);
    int g = lane >> 3;
    if ((lane & 7) == 0) {
        g_qk[(size_t)m * 4 + g] = qk;
        g_tv[(size_t)m * 4 + g] = tv;
    }
    float qk0 = __shfl_sync(0xffffffffu, qk, 0),  tv0 = __shfl_sync(0xffffffffu, tv, 0);
    float qk1 = __shfl_sync(0xffffffffu, qk, 8),  tv1 = __shfl_sync(0xffffffffu, tv, 8);
    float qk2 = __shfl_sync(0xffffffffu, qk, 16), tv2 = __shfl_sync(0xffffffffu, tv, 16);
    float qk3 = __shfl_sync(0xffffffffu, qk, 24), tv3 = __shfl_sync(0xffffffffu, tv, 24);
    if (lane < 2) {
        float s3 = (lane == 0) ? (qk0 * tv0 + qk1 * tv1) * (1.0f / 64)
                               : (qk2 * tv2 + qk3 * tv3) * (1.0f / 64);
        float ex = __expf(s3);
        g_s3[(size_t)m * 2 + lane] = ex;
        atomicAdd(&g_Z3[c * 2 + lane], ex);
    }
}

// Motif backward: 3 gathers + 3 f16 REDs per warp
__global__ void k_motif_bwd(const int* __restrict__ c3, const int* __restrict__ u3,
                            const int* __restrict__ v3, const int* __restrict__ tt) {
    int m = (blockIdx.x * 256 + threadIdx.x) >> 5;
    int lane = threadIdx.x & 31;
    if (m >= Mm) return;
    int c = c3[m], ua = u3[m], vb = v3[m], t = tt[m];
    int g = lane >> 3;
    int h = g >> 1;
    float2 ex = *(const float2*)&g_s3[(size_t)m * 2];
    float2 Z  = *(const float2*)&g_Z3[c * 2];
    float p = h ? (ex.y / Z.y) : (ex.x / Z.x);
    float gg = -LAM3 * p * (1.0f / 64);
    float cA = gg * g_tv[(size_t)m * 4 + g];
    float cB = gg * g_qk[(size_t)m * 4 + g];
    int off = lane * 8;
    float q[8], ku[8], tp8[8];
    ld8bf(g_Pb + (size_t)c  * PB + 256 + off, q);
    ld8bf(g_Pb + (size_t)ua * PB + 512 + off, ku);
    ld8bf(g_TtH + t * 256 + off, tp8);
    __half* dq  = g_Uh + (size_t)c  * PW + 256 + off;
    __half* dku = g_Uh + (size_t)ua * PW + 512 + off;
    __half* dkv = g_Uh + (size_t)vb * PW + 512 + off;
    red_add_v4h(dq,  pack2h(cA*ku[0],cA*ku[1]), pack2h(cA*ku[2],cA*ku[3]),
                     pack2h(cA*ku[4],cA*ku[5]), pack2h(cA*ku[6],cA*ku[7]));
    red_add_v4h(dku, pack2h(cA*q[0],cA*q[1]),   pack2h(cA*q[2],cA*q[3]),
                     pack2h(cA*q[4],cA*q[5]),   pack2h(cA*q[6],cA*q[7]));
    red_add_v4h(dkv, pack2h(cB*tp8[0],cB*tp8[1]), pack2h(cB*tp8[2],cB*tp8[3]),
                     pack2h(cB*tp8[4],cB*tp8[5]), pack2h(cB*tp8[6],cB*tp8[7]));
}

// ---------------------------------------------------------------------------
// Memory term: warp per (node, head)
// ---------------------------------------------------------------------------
__global__ void k_mem() {
    int w = (blockIdx.x * 256 + threadIdx.x) >> 5;
    int lane = threadIdx.x & 31;
    if (w >= Nn * Hh) return;
    int n = w >> 1, h = w & 1;
    const float* qm = g_P + (size_t)n * PW + 768 + h * HDm;
    const float* kt = g_KmT + h * HDm * KSL;
    const float* km = g_Km + h * KSL * HDm;
    float2 qv = ((const float2*)qm)[lane];
    float sm = 0.f;
#pragma unroll
    for (int z2 = 0; z2 < 32; z2++) {
        float qa = __shfl_sync(0xffffffffu, qv.x, z2);
        float qb = __shfl_sync(0xffffffffu, qv.y, z2);
        sm += qa * kt[(2 * z2) * KSL + lane] + qb * kt[(2 * z2 + 1) * KSL + lane];
    }
    sm *= 0.125f;
    float e = __expf(sm);
    float Z = wsum32(e);
    float p = e / Z;
    if (lane == 0) g_Lm[w] = logf(Z);
    float a0 = 0.f, a1 = 0.f;
#pragma unroll
    for (int kk = 0; kk < KSL; kk++) {
        float pk = __shfl_sync(0xffffffffu, p, kk);
        a0 += pk * km[kk * HDm + lane];
        a1 += pk * km[kk * HDm + lane + 32];
    }
    __half* du = g_Uh + (size_t)n * PW + 768 + h * HDm;
    du[lane] = __float2half(-0.125f * a0);
    du[lane + 32] = __float2half(-0.125f * a1);
}

// ---------------------------------------------------------------------------
// Fused: LN backward + grad clip + step + state clip + per-graph energy
// ---------------------------------------------------------------------------
__global__ void k_final(const float* __restrict__ X, const float* __restrict__ gamma,
                        const float* __restrict__ step, const int* __restrict__ batch,
                        float* __restrict__ out, float* __restrict__ Eg) {
    __shared__ float bins[NGg];
    int tid = threadIdx.x;
    if (tid < NGg) bins[tid] = 0.f;
    __syncthreads();
    int w = (blockIdx.x * blockDim.x + tid) >> 5;
    int lane = tid & 31;
    if (w < Nn) {
        const float4 x = *(const float4*)(X + (size_t)w * Dd + lane * 4);
        const float4 dg = *(const float4*)(g_dG + (size_t)w * Dd + lane * 4);
        const float4 gm = *(const float4*)(gamma + lane * 4);
        float mu = g_mu[w], rstd = g_rstd[w];
        float4 xh = make_float4((x.x - mu) * rstd, (x.y - mu) * rstd,
                                (x.z - mu) * rstd, (x.w - mu) * rstd);
        float4 dxh = make_float4(dg.x * gm.x, dg.y * gm.y, dg.z * gm.z, dg.w * gm.w);
        float S1 = wsum32(dxh.x + dxh.y + dxh.z + dxh.w) * (1.0f / Dd);
        float S2 = wsum32(dxh.x * xh.x + dxh.y * xh.y + dxh.z * xh.z + dxh.w * xh.w) * (1.0f / Dd);
        float ss = wsum32(x.x * x.x + x.y * x.y + x.z * x.z + x.w * x.w);
        float4 g;
        g.x = x.x + rstd * (dxh.x - S1 - xh.x * S2);
        g.y = x.y + rstd * (dxh.y - S1 - xh.y * S2);
        g.z = x.z + rstd * (dxh.z - S1 - xh.z * S2);
        g.w = x.w + rstd * (dxh.w - S1 - xh.w * S2);
        float gss = wsum32(g.x * g.x + g.y * g.y + g.z * g.z + g.w * g.w);
        float sc1 = 1.0f / fmaxf(sqrtf(gss), 1.0f);
        float st = step[0] * sc1;
        float4 xn = make_float4(x.x - st * g.x, x.y - st * g.y,
                                x.z - st * g.z, x.w - st * g.w);
        float sn = wsum32(xn.x * xn.x + xn.y * xn.y + xn.z * xn.z + xn.w * xn.w);
        float sc2 = 10.0f / fmaxf(sqrtf(sn), 10.0f);
        float4 o = make_float4(xn.x * sc2, xn.y * sc2, xn.z * sc2, xn.w * sc2);
        *(float4*)(out + (size_t)w * Dd + lane * 4) = o;
        if (lane == 0) {
            float e = 0.5f * ss;
            float z0 = g_Z2[w * 2], z1 = g_Z2[w * 2 + 1];
            e -= (z0 > 0.f ? logf(z0) : 0.f) + (z1 > 0.f ? logf(z1) : 0.f);
            float y0 = g_Z3[w * 2], y1 = g_Z3[w * 2 + 1];
            e -= LAM3 * ((y0 > 0.f ? logf(y0) : 0.f) + (y1 > 0.f ? logf(y1) : 0.f));
            e -= g_Lm[w * 2] + g_Lm[w * 2 + 1];
            atomicAdd(&bins[batch[w]], e);
        }
    }
    __syncthreads();
    if (tid < NGg) atomicAdd(&Eg[tid], bins[tid]);
}

// ---------------------------------------------------------------------------
// Launch
// ---------------------------------------------------------------------------
extern "C" void kernel_launch(void* const* d_in, const int* in_sizes, int n_in,
                              void* d_out, int out_size) {
    const float* X    = (const float*)d_in[0];
    const int* c2     = (const int*)d_in[1];
    const int* u2     = (const int*)d_in[2];
    const int* c3     = (const int*)d_in[3];
    const int* u3     = (const int*)d_in[4];
    const int* v3     = (const int*)d_in[5];
    const int* tt     = (const int*)d_in[6];
    const int* batch  = (const int*)d_in[7];
    const float* a2   = (const float*)d_in[8];
    const float* step = (const float*)d_in[9];
    const float* gamma= (const float*)d_in[10];
    const float* beta = (const float*)d_in[11];
    const float* WQ2  = (const float*)d_in[12];
    const float* WK2  = (const float*)d_in[13];
    const float* WQ3  = (const float*)d_in[14];
    const float* WK3  = (const float*)d_in[15];
    const float* Ttau = (const float*)d_in[16];
    const float* WQm  = (const float*)d_in[17];
    const float* WKm  = (const float*)d_in[18];
    const float* Bmem = (const float*)d_in[19];
    float* out = (float*)d_out;
    float* Eg  = out + (size_t)Nn * Dd;

    void *pUh, *pZ2, *pZ3, *pGh, *pP, *pPb, *pWcB, *pWcHT, *pdG;
    cudaGetSymbolAddress(&pUh, g_Uh);
    cudaGetSymbolAddress(&pZ2, g_Z2);
    cudaGetSymbolAddress(&pZ3, g_Z3);
    cudaGetSymbolAddress(&pGh, g_Gh);
    cudaGetSymbolAddress(&pP, g_P);
    cudaGetSymbolAddress(&pPb, g_Pb);
    cudaGetSymbolAddress(&pWcB, g_WcatB);
    cudaGetSymbolAddress(&pWcHT, g_WcatHT);
    cudaGetSymbolAddress(&pdG, g_dG);

    cudaMemsetAsync(pUh, 0, sizeof(__half) * (size_t)Nn * PW);
    cudaMemsetAsync(pZ2, 0, sizeof(float) * Nn * Hh);
    cudaMemsetAsync(pZ3, 0, sizeof(float) * Nn * Hh);
    cudaMemsetAsync(Eg, 0, sizeof(float) * NGg);

    k_ln<<<Nn / 8, 256>>>(X, gamma, beta);
    k_wcat<<<(PW * Dd + 255) / 256, 256>>>(WQ2, WK2, WQ3, WK3, WQm, Ttau);
    k_km<<<(Hh * KSL * HDm + 255) / 256, 256>>>(Bmem, WKm);

    // Forward projections (bf16 tensor cores): P = G x Wcat^T; bf16 out cols<768
    k_gemm16<__nv_bfloat16, true><<<dim3(PW / 128, Nn / 128), 256>>>(
        (const __nv_bfloat16*)pGh, Dd,
        (const __nv_bfloat16*)pWcB, Dd,
        (float*)pP, PW, Dd,
        (__nv_bfloat16*)pPb);

    k_pair_fwd<<<Ee / 8, 256>>>(c2, u2, a2);
    k_motif_fwd<<<Mm / 8, 256>>>(c3, u3, v3, tt, Ttau);
    k_mem<<<(Nn * Hh) / 8, 256>>>();

    k_pair_bwd<<<Ee / 8, 256>>>(c2, u2);
    k_motif_bwd<<<Mm / 8, 256>>>(c3, u3, v3, tt);

    // Backward projections (f16 tensor cores): dG = U[N,896] x Wcat[896,128]
    k_gemm16<__half, false><<<dim3(Dd / 128, Nn / 128), 256>>>(
        (const __half*)pUh, PW,
        (const __half*)pWcHT, PW,
        (float*)pdG, Dd, PW,
        nullptr);

    k_final<<<Nn / 8, 256>>>(X, gamma, step, batch, out, Eg);
}

// round 10
// speedup vs baseline: 3.2449x; 1.0494x over previous
#include <cuda_runtime.h>
#include <cuda_bf16.h>
#include <cuda_fp16.h>
#include <math.h>
#include <stdint.h>

// ---------------------------------------------------------------------------
// Problem constants
// ---------------------------------------------------------------------------
#define Nn   32768
#define Dd   128
#define Hh   2
#define HDm  64
#define Ee   262144
#define Mm   131072
#define NGg  32
#define PW   896          // 128(Q2)+128(K2)+256(Q3)+256(K3)+128(Qm)
#define PB   768          // bf16 mirror width (Q2|K2|Q3|K3)
#define KSL  32
#define TMt  2
#define LAM3 0.5f
#define EPSV 1e-5f

// ---------------------------------------------------------------------------
// Scratch
// ---------------------------------------------------------------------------
__device__ __align__(256) __nv_bfloat16 g_Gh[(size_t)Nn * Dd];  // bf16 LN output
__device__ float g_mu[Nn];
__device__ float g_rstd[Nn];
__device__ float g_P[(size_t)Nn * PW];                          // Qm cols (768..) fp32
__device__ __align__(256) __nv_bfloat16 g_Pb[(size_t)Nn * PB];  // bf16 cols 0..767
__device__ __align__(256) __half g_Uh[(size_t)Nn * PW];         // f16 grad accumulator
__device__ float g_dG[(size_t)Nn * Dd];
__device__ __align__(256) __nv_bfloat16 g_WcatB[PW * Dd];       // bf16 [j][d] for fwd GEMM
__device__ __align__(256) __half g_WcatHT[Dd * PW];             // f16 [d][j] for bwd GEMM
__device__ __nv_bfloat16 g_TtH[TMt * Hh * 2 * HDm];             // bf16 Ttau mirror
__device__ float g_Km[Hh * KSL * HDm];     // [h][k][z]
__device__ float g_KmT[Hh * HDm * KSL];    // [h][z][k]
__device__ float g_s2[(size_t)Ee * Hh];    // exp(s2)
__device__ float g_Z2[Nn * Hh];
__device__ float g_qk[(size_t)Mm * 4];
__device__ float g_tv[(size_t)Mm * 4];
__device__ float g_s3[(size_t)Mm * Hh];    // exp(s3)
__device__ float g_Z3[Nn * Hh];
__device__ float g_Lm[Nn * Hh];

// ---------------------------------------------------------------------------
// Helpers
// ---------------------------------------------------------------------------
__device__ __forceinline__ float wsum32(float v) {
#pragma unroll
    for (int m = 16; m > 0; m >>= 1) v += __shfl_xor_sync(0xffffffffu, v, m);
    return v;
}
__device__ __forceinline__ float wsum16(float v) {
#pragma unroll
    for (int m = 8; m > 0; m >>= 1) v += __shfl_xor_sync(0xffffffffu, v, m);
    return v;
}
__device__ __forceinline__ float wsum8(float v) {
#pragma unroll
    for (int m = 4; m > 0; m >>= 1) v += __shfl_xor_sync(0xffffffffu, v, m);
    return v;
}
__device__ __forceinline__ void red_add_v4h(__half* addr, uint32_t a, uint32_t b,
                                            uint32_t c, uint32_t d) {
    asm volatile("red.global.add.noftz.v4.f16x2 [%0], {%1, %2, %3, %4};"
                 :: "l"(addr), "r"(a), "r"(b), "r"(c), "r"(d) : "memory");
}
__device__ __forceinline__ uint32_t pack2h(float a, float b) {
    __half2 h = __floats2half2_rn(a, b);
    return *reinterpret_cast<uint32_t*>(&h);
}
__device__ __forceinline__ void ld4bf(const __nv_bfloat16* p, float* f) {
    uint2 r = *(const uint2*)p;
    __nv_bfloat162 h0 = *reinterpret_cast<const __nv_bfloat162*>(&r.x);
    __nv_bfloat162 h1 = *reinterpret_cast<const __nv_bfloat162*>(&r.y);
    float2 a = __bfloat1622float2(h0), b = __bfloat1622float2(h1);
    f[0] = a.x; f[1] = a.y; f[2] = b.x; f[3] = b.y;
}
__device__ __forceinline__ void ld8bf(const __nv_bfloat16* p, float* f) {
    uint4 r = *(const uint4*)p;
    __nv_bfloat162 h0 = *reinterpret_cast<const __nv_bfloat162*>(&r.x);
    __nv_bfloat162 h1 = *reinterpret_cast<const __nv_bfloat162*>(&r.y);
    __nv_bfloat162 h2 = *reinterpret_cast<const __nv_bfloat162*>(&r.z);
    __nv_bfloat162 h3 = *reinterpret_cast<const __nv_bfloat162*>(&r.w);
    float2 a = __bfloat1622float2(h0), b = __bfloat1622float2(h1);
    float2 c = __bfloat1622float2(h2), d = __bfloat1622float2(h3);
    f[0] = a.x; f[1] = a.y; f[2] = b.x; f[3] = b.y;
    f[4] = c.x; f[5] = c.y; f[6] = d.x; f[7] = d.y;
}
__device__ __forceinline__ void ldsm4(uint32_t* r, uint32_t addr) {
    asm volatile("ldmatrix.sync.aligned.m8n8.x4.shared.b16 {%0,%1,%2,%3}, [%4];"
                 : "=r"(r[0]), "=r"(r[1]), "=r"(r[2]), "=r"(r[3]) : "r"(addr));
}
__device__ __forceinline__ void mma16(float* c, const uint32_t* a, const uint32_t* b, __half) {
    asm volatile(
        "mma.sync.aligned.m16n8k16.row.col.f32.f16.f16.f32 "
        "{%0,%1,%2,%3}, {%4,%5,%6,%7}, {%8,%9}, {%0,%1,%2,%3};"
        : "+f"(c[0]), "+f"(c[1]), "+f"(c[2]), "+f"(c[3])
        : "r"(a[0]), "r"(a[1]), "r"(a[2]), "r"(a[3]), "r"(b[0]), "r"(b[1]));
}
__device__ __forceinline__ void mma16(float* c, const uint32_t* a, const uint32_t* b, __nv_bfloat16) {
    asm volatile(
        "mma.sync.aligned.m16n8k16.row.col.f32.bf16.bf16.f32 "
        "{%0,%1,%2,%3}, {%4,%5,%6,%7}, {%8,%9}, {%0,%1,%2,%3};"
        : "+f"(c[0]), "+f"(c[1]), "+f"(c[2]), "+f"(c[3])
        : "r"(a[0]), "r"(a[1]), "r"(a[2]), "r"(a[3]), "r"(b[0]), "r"(b[1]));
}

// ---------------------------------------------------------------------------
// LayerNorm forward -> bf16 G
// ---------------------------------------------------------------------------
__global__ void k_ln(const float* __restrict__ X, const float* __restrict__ gamma,
                     const float* __restrict__ beta) {
    int w = (blockIdx.x * blockDim.x + threadIdx.x) >> 5;
    int lane = threadIdx.x & 31;
    if (w >= Nn) return;
    const float4 x = *(const float4*)(X + (size_t)w * Dd + lane * 4);
    float s = x.x + x.y + x.z + x.w;
    float mu = wsum32(s) * (1.0f / Dd);
    float4 xc = make_float4(x.x - mu, x.y - mu, x.z - mu, x.w - mu);
    float v = xc.x * xc.x + xc.y * xc.y + xc.z * xc.z + xc.w * xc.w;
    v = wsum32(v) * (1.0f / Dd);
    float rstd = rsqrtf(v + EPSV);
    const float4 g4 = *(const float4*)(gamma + lane * 4);
    const float4 b4 = *(const float4*)(beta + lane * 4);
    float Gx = g4.x * xc.x * rstd + b4.x;
    float Gy = g4.y * xc.y * rstd + b4.y;
    float Gz = g4.z * xc.z * rstd + b4.z;
    float Gw = g4.w * xc.w * rstd + b4.w;
    uint2 pk;
    __nv_bfloat162 h0 = __floats2bfloat162_rn(Gx, Gy);
    __nv_bfloat162 h1 = __floats2bfloat162_rn(Gz, Gw);
    pk.x = *reinterpret_cast<uint32_t*>(&h0);
    pk.y = *reinterpret_cast<uint32_t*>(&h1);
    *(uint2*)(g_Gh + (size_t)w * Dd + lane * 4) = pk;
    if (lane == 0) { g_mu[w] = mu; g_rstd[w] = rstd; }
}

// ---------------------------------------------------------------------------
// Stacked weights + Ttau mirror
// ---------------------------------------------------------------------------
__global__ void k_wcat(const float* __restrict__ WQ2, const float* __restrict__ WK2,
                       const float* __restrict__ WQ3, const float* __restrict__ WK3,
                       const float* __restrict__ WQm, const float* __restrict__ Ttau) {
    int idx = blockIdx.x * blockDim.x + threadIdx.x;
    if (idx < TMt * Hh * 2 * HDm) g_TtH[idx] = __float2bfloat16(Ttau[idx]);
    if (idx >= PW * Dd) return;
    int j = idx / Dd, d = idx - j * Dd;
    float v;
    if (j < 128)      v = WQ2[j * Dd + d];
    else if (j < 256) v = WK2[(j - 128) * Dd + d];
    else if (j < 512) v = WQ3[(j - 256) * Dd + d];
    else if (j < 768) v = WK3[(j - 512) * Dd + d];
    else              v = WQm[(j - 768) * Dd + d];
    g_WcatB[j * Dd + d] = __float2bfloat16(v);
    g_WcatHT[d * PW + j] = __float2half(v);
}

// ---------------------------------------------------------------------------
// Km = B_mem @ W_Km^T per head
// ---------------------------------------------------------------------------
__global__ void k_km(const float* __restrict__ Bm, const float* __restrict__ WKm) {
    int idx = blockIdx.x * blockDim.x + threadIdx.x;
    if (idx >= Hh * KSL * HDm) return;
    int h = idx / (KSL * HDm);
    int k = (idx / HDm) % KSL;
    int z = idx % HDm;
    const float* b = Bm + k * Dd;
    const float* w = WKm + (h * HDm + z) * Dd;
    float acc = 0.f;
#pragma unroll 8
    for (int d = 0; d < Dd; d++) acc += b[d] * w[d];
    g_Km[idx] = acc;
    g_KmT[(h * HDm + z) * KSL + k] = acc;
}

// ---------------------------------------------------------------------------
// Forward GEMM, K=128 entirely staged in smem, single barrier, no pipeline.
// C[M,J] = A[M,128] * Bt[J,128]^T, bf16 in, SPLIT out (bf16 cols<PB / fp32).
// Dynamic smem: 2 * 128 * 136 bf16 = 69632 B.
// ---------------------------------------------------------------------------
#define FP 136   // smem row pitch (elements); 272 B -> conflict-free LDSM
__global__ void __launch_bounds__(256)
k_gemmF(const __nv_bfloat16* __restrict__ A,
        const __nv_bfloat16* __restrict__ Bt,
        float* __restrict__ C, __nv_bfloat16* __restrict__ Cb) {
    extern __shared__ __nv_bfloat16 smF[];
    __nv_bfloat16* As = smF;                 // [128][FP]
    __nv_bfloat16* Bs = smF + 128 * FP;      // [128][FP]
    int tid = threadIdx.x;
    int warp = tid >> 5, lane = tid & 31;
    int g = lane >> 2, tg = lane & 3;
    int wm = (warp >> 2) * 64;
    int wn = (warp & 3) * 32;
    int row0 = blockIdx.y * 128, col0 = blockIdx.x * 128;

    // Stage both 128x128 tiles: each thread 8+8 uint4 loads
    {
        int r = tid & 127;
        int half = tid >> 7;                 // 0/1 -> cols 0..63 / 64..127
        const uint4* Ag = (const uint4*)(A + (size_t)(row0 + r) * 128 + half * 64);
        const uint4* Bg = (const uint4*)(Bt + (size_t)(col0 + r) * 128 + half * 64);
        uint4* Asr = (uint4*)(As + r * FP + half * 64);
        uint4* Bsr = (uint4*)(Bs + r * FP + half * 64);
#pragma unroll
        for (int i = 0; i < 8; i++) Asr[i] = Ag[i];
#pragma unroll
        for (int i = 0; i < 8; i++) Bsr[i] = Bg[i];
    }
    __syncthreads();

    uint32_t aBase = (uint32_t)__cvta_generic_to_shared(
        As + (wm + (lane & 15)) * FP + (lane >> 4) * 8);
    uint32_t bBase = (uint32_t)__cvta_generic_to_shared(
        Bs + (wn + ((lane >> 4) & 1) * 8 + (lane & 7)) * FP + ((lane >> 3) & 1) * 8);
    const uint32_t pit = FP * 2;             // bytes per row

    float acc[16][4];
#pragma unroll
    for (int i = 0; i < 16; i++)
#pragma unroll
        for (int j = 0; j < 4; j++) acc[i][j] = 0.f;

#pragma unroll
    for (int kk = 0; kk < 8; kk++) {
        uint32_t af[4][4], bq[2][4];
#pragma unroll
        for (int mi = 0; mi < 4; mi++)
            ldsm4(af[mi], aBase + mi * 16 * pit + kk * 32);
#pragma unroll
        for (int ni2 = 0; ni2 < 2; ni2++)
            ldsm4(bq[ni2], bBase + ni2 * 16 * pit + kk * 32);
#pragma unroll
        for (int mi = 0; mi < 4; mi++)
#pragma unroll
            for (int ni = 0; ni < 4; ni++)
                mma16(acc[mi * 4 + ni], af[mi], &bq[ni >> 1][(ni & 1) * 2],
                      __nv_bfloat16{});
    }

    bool asbf = (col0 < PB);
#pragma unroll
    for (int mi = 0; mi < 4; mi++)
#pragma unroll
        for (int ni = 0; ni < 4; ni++) {
            float* c = acc[mi * 4 + ni];
            int r = row0 + wm + mi * 16 + g;
            int col = col0 + wn + ni * 8 + 2 * tg;
            if (asbf) {
                *(__nv_bfloat162*)(Cb + (size_t)r * PB + col) =
                    __floats2bfloat162_rn(c[0], c[1]);
                *(__nv_bfloat162*)(Cb + (size_t)(r + 8) * PB + col) =
                    __floats2bfloat162_rn(c[2], c[3]);
            } else {
                *(float2*)(C + (size_t)r * PW + col) = make_float2(c[0], c[1]);
                *(float2*)(C + (size_t)(r + 8) * PW + col) = make_float2(c[2], c[3]);
            }
        }
}

// ---------------------------------------------------------------------------
// Backward GEMM (f16, K=896), pipelined k16 with ldmatrix (unchanged)
// ---------------------------------------------------------------------------
__global__ void __launch_bounds__(256)
k_gemmB(const __half* __restrict__ A, int lda,
        const __half* __restrict__ Bt, int ldb,
        float* __restrict__ C, int ldc, int Kdim) {
    __shared__ __half As[2][128][24];
    __shared__ __half Bs[2][128][24];
    int tid = threadIdx.x;
    int warp = tid >> 5, lane = tid & 31;
    int g = lane >> 2, tg = lane & 3;
    int wm = (warp >> 2) * 64;
    int wn = (warp & 3) * 32;
    int row0 = blockIdx.y * 128, col0 = blockIdx.x * 128;
    int lr = tid >> 1;
    int lc = (tid & 1) * 8;
    const __half* Ap = A + (size_t)(row0 + lr) * lda + lc;
    const __half* Bp = Bt + (size_t)(col0 + lr) * ldb + lc;

    uint32_t aAddr[2], bAddr[2];
#pragma unroll
    for (int b = 0; b < 2; b++) {
        aAddr[b] = (uint32_t)__cvta_generic_to_shared(
            &As[b][wm + (lane & 15)][(lane >> 4) * 8]);
        bAddr[b] = (uint32_t)__cvta_generic_to_shared(
            &Bs[b][wn + ((lane >> 4) & 1) * 8 + (lane & 7)][((lane >> 3) & 1) * 8]);
    }
    const uint32_t rowPitch = 24 * sizeof(__half);

    float acc[16][4];
#pragma unroll
    for (int i = 0; i < 16; i++)
#pragma unroll
        for (int j = 0; j < 4; j++) acc[i][j] = 0.f;

    uint4 av = *(const uint4*)Ap;
    uint4 bv = *(const uint4*)Bp;
    *(uint4*)&As[0][lr][lc] = av;
    *(uint4*)&Bs[0][lr][lc] = bv;
    __syncthreads();

    int nk = Kdim >> 4;
    for (int kt = 0; kt < nk; kt++) {
        int cur = kt & 1, nxt = cur ^ 1;
        if (kt + 1 < nk) {
            av = *(const uint4*)(Ap + (kt + 1) * 16);
            bv = *(const uint4*)(Bp + (kt + 1) * 16);
        }
        uint32_t af[4][4], bq[2][4];
#pragma unroll
        for (int mi = 0; mi < 4; mi++)
            ldsm4(af[mi], aAddr[cur] + mi * 16 * rowPitch);
#pragma unroll
        for (int ni2 = 0; ni2 < 2; ni2++)
            ldsm4(bq[ni2], bAddr[cur] + ni2 * 16 * rowPitch);
#pragma unroll
        for (int mi = 0; mi < 4; mi++)
#pragma unroll
            for (int ni = 0; ni < 4; ni++)
                mma16(acc[mi * 4 + ni], af[mi], &bq[ni >> 1][(ni & 1) * 2], __half{});
        if (kt + 1 < nk) {
            *(uint4*)&As[nxt][lr][lc] = av;
            *(uint4*)&Bs[nxt][lr][lc] = bv;
            __syncthreads();
        }
    }
#pragma unroll
    for (int mi = 0; mi < 4; mi++)
#pragma unroll
        for (int ni = 0; ni < 4; ni++) {
            float* c = acc[mi * 4 + ni];
            int r = row0 + wm + mi * 16 + g;
            int col = col0 + wn + ni * 8 + 2 * tg;
            *(float2*)(C + (size_t)r * ldc + col) = make_float2(c[0], c[1]);
            *(float2*)(C + (size_t)(r + 8) * ldc + col) = make_float2(c[2], c[3]);
        }
}

// ---------------------------------------------------------------------------
// Pair forward
// ---------------------------------------------------------------------------
__global__ void k_pair_fwd(const int* __restrict__ c2, const int* __restrict__ u2,
                           const float* __restrict__ a2) {
    int e = (blockIdx.x * 256 + threadIdx.x) >> 5;
    int lane = threadIdx.x & 31;
    if (e >= Ee) return;
    int c = c2[e], u = u2[e];
    float q[4], k[4];
    ld4bf(g_Pb + (size_t)c * PB + lane * 4, q);
    ld4bf(g_Pb + (size_t)u * PB + 128 + lane * 4, k);
    float part = q[0] * k[0] + q[1] * k[1] + q[2] * k[2] + q[3] * k[3];
    part = wsum16(part);
    int h = lane >> 4;
    if ((lane & 15) == 0) {
        float s = part * 0.125f + a2[e * 2 + h];
        float ex = __expf(s);
        g_s2[(size_t)e * 2 + h] = ex;
        atomicAdd(&g_Z2[c * 2 + h], ex);
    }
}

// Pair backward
__global__ void k_pair_bwd(const int* __restrict__ c2, const int* __restrict__ u2) {
    int e = (blockIdx.x * 256 + threadIdx.x) >> 5;
    int lane = threadIdx.x & 31;
    if (e >= Ee) return;
    int c = c2[e], u = u2[e];
    float2 ex = *(const float2*)&g_s2[(size_t)e * 2];
    float2 Z  = *(const float2*)&g_Z2[c * 2];
    float wt0 = -0.125f * ex.x / Z.x;
    float wt1 = -0.125f * ex.y / Z.y;
    int dk_side = lane >> 4;
    int i = lane & 15;
    float wt = (i >> 3) ? wt1 : wt0;
    const __nv_bfloat16* src = dk_side ? (g_Pb + (size_t)c * PB + i * 8)
                                       : (g_Pb + (size_t)u * PB + 128 + i * 8);
    float v[8];
    ld8bf(src, v);
    __half* dst = dk_side ? (g_Uh + (size_t)u * PW + 128 + i * 8)
                          : (g_Uh + (size_t)c * PW + i * 8);
    red_add_v4h(dst, pack2h(wt*v[0],wt*v[1]), pack2h(wt*v[2],wt*v[3]),
                     pack2h(wt*v[4],wt*v[5]), pack2h(wt*v[6],wt*v[7]));
}

// ---------------------------------------------------------------------------
// Motif forward
// ---------------------------------------------------------------------------
__global__ void k_motif_fwd(const int* __restrict__ c3, const int* __restrict__ u3,
                            const int* __restrict__ v3, const int* __restrict__ tt,
                            const float* __restrict__ Ttau) {
    int m = (blockIdx.x * 256 + threadIdx.x) >> 5;
    int lane = threadIdx.x & 31;
    if (m >= Mm) return;
    int c = c3[m], ua = u3[m], vb = v3[m], t = tt[m];
    int off = lane * 8;
    float q[8], ku[8], kv[8];
    ld8bf(g_Pb + (size_t)c  * PB + 256 + off, q);
    ld8bf(g_Pb + (size_t)ua * PB + 512 + off, ku);
    ld8bf(g_Pb + (size_t)vb * PB + 512 + off, kv);
    const float* tp = Ttau + t * 256 + off;
    float qk = 0.f, tv = 0.f;
#pragma unroll
    for (int i = 0; i < 8; i++) {
        qk += q[i] * ku[i];
        tv += tp[i] * kv[i];
    }
    qk = wsum8(qk);
    tv = wsum8(tv);
    int g = lane >> 3;
    if ((lane & 7) == 0) {
        g_qk[(size_t)m * 4 + g] = qk;
        g_tv[(size_t)m * 4 + g] = tv;
    }
    float qk0 = __shfl_sync(0xffffffffu, qk, 0),  tv0 = __shfl_sync(0xffffffffu, tv, 0);
    float qk1 = __shfl_sync(0xffffffffu, qk, 8),  tv1 = __shfl_sync(0xffffffffu, tv, 8);
    float qk2 = __shfl_sync(0xffffffffu, qk, 16), tv2 = __shfl_sync(0xffffffffu, tv, 16);
    float qk3 = __shfl_sync(0xffffffffu, qk, 24), tv3 = __shfl_sync(0xffffffffu, tv, 24);
    if (lane < 2) {
        float s3 = (lane == 0) ? (qk0 * tv0 + qk1 * tv1) * (1.0f / 64)
                               : (qk2 * tv2 + qk3 * tv3) * (1.0f / 64);
        float ex = __expf(s3);
        g_s3[(size_t)m * 2 + lane] = ex;
        atomicAdd(&g_Z3[c * 2 + lane], ex);
    }
}

// Motif backward
__global__ void k_motif_bwd(const int* __restrict__ c3, const int* __restrict__ u3,
                            const int* __restrict__ v3, const int* __restrict__ tt) {
    int m = (blockIdx.x * 256 + threadIdx.x) >> 5;
    int lane = threadIdx.x & 31;
    if (m >= Mm) return;
    int c = c3[m], ua = u3[m], vb = v3[m], t = tt[m];
    int g = lane >> 3;
    int h = g >> 1;
    float2 ex = *(const float2*)&g_s3[(size_t)m * 2];
    float2 Z  = *(const float2*)&g_Z3[c * 2];
    float p = h ? (ex.y / Z.y) : (ex.x / Z.x);
    float gg = -LAM3 * p * (1.0f / 64);
    float cA = gg * g_tv[(size_t)m * 4 + g];
    float cB = gg * g_qk[(size_t)m * 4 + g];
    int off = lane * 8;
    float q[8], ku[8], tp8[8];
    ld8bf(g_Pb + (size_t)c  * PB + 256 + off, q);
    ld8bf(g_Pb + (size_t)ua * PB + 512 + off, ku);
    ld8bf(g_TtH + t * 256 + off, tp8);
    __half* dq  = g_Uh + (size_t)c  * PW + 256 + off;
    __half* dku = g_Uh + (size_t)ua * PW + 512 + off;
    __half* dkv = g_Uh + (size_t)vb * PW + 512 + off;
    red_add_v4h(dq,  pack2h(cA*ku[0],cA*ku[1]), pack2h(cA*ku[2],cA*ku[3]),
                     pack2h(cA*ku[4],cA*ku[5]), pack2h(cA*ku[6],cA*ku[7]));
    red_add_v4h(dku, pack2h(cA*q[0],cA*q[1]),   pack2h(cA*q[2],cA*q[3]),
                     pack2h(cA*q[4],cA*q[5]),   pack2h(cA*q[6],cA*q[7]));
    red_add_v4h(dkv, pack2h(cB*tp8[0],cB*tp8[1]), pack2h(cB*tp8[2],cB*tp8[3]),
                     pack2h(cB*tp8[4],cB*tp8[5]), pack2h(cB*tp8[6],cB*tp8[7]));
}

// ---------------------------------------------------------------------------
// Memory term
// ---------------------------------------------------------------------------
__global__ void k_mem() {
    int w = (blockIdx.x * 256 + threadIdx.x) >> 5;
    int lane = threadIdx.x & 31;
    if (w >= Nn * Hh) return;
    int n = w >> 1, h = w & 1;
    const float* qm = g_P + (size_t)n * PW + 768 + h * HDm;
    const float* kt = g_KmT + h * HDm * KSL;
    const float* km = g_Km + h * KSL * HDm;
    float2 qv = ((const float2*)qm)[lane];
    float sm = 0.f;
#pragma unroll
    for (int z2 = 0; z2 < 32; z2++) {
        float qa = __shfl_sync(0xffffffffu, qv.x, z2);
        float qb = __shfl_sync(0xffffffffu, qv.y, z2);
        sm += qa * kt[(2 * z2) * KSL + lane] + qb * kt[(2 * z2 + 1) * KSL + lane];
    }
    sm *= 0.125f;
    float e = __expf(sm);
    float Z = wsum32(e);
    float p = e / Z;
    if (lane == 0) g_Lm[w] = logf(Z);
    float a0 = 0.f, a1 = 0.f;
#pragma unroll
    for (int kk = 0; kk < KSL; kk++) {
        float pk = __shfl_sync(0xffffffffu, p, kk);
        a0 += pk * km[kk * HDm + lane];
        a1 += pk * km[kk * HDm + lane + 32];
    }
    __half* du = g_Uh + (size_t)n * PW + 768 + h * HDm;
    du[lane] = __float2half(-0.125f * a0);
    du[lane + 32] = __float2half(-0.125f * a1);
}

// ---------------------------------------------------------------------------
// Fused: LN backward + clips + step + per-graph energy
// ---------------------------------------------------------------------------
__global__ void k_final(const float* __restrict__ X, const float* __restrict__ gamma,
                        const float* __restrict__ step, const int* __restrict__ batch,
                        float* __restrict__ out, float* __restrict__ Eg) {
    __shared__ float bins[NGg];
    int tid = threadIdx.x;
    if (tid < NGg) bins[tid] = 0.f;
    __syncthreads();
    int w = (blockIdx.x * blockDim.x + tid) >> 5;
    int lane = tid & 31;
    if (w < Nn) {
        const float4 x = *(const float4*)(X + (size_t)w * Dd + lane * 4);
        const float4 dg = *(const float4*)(g_dG + (size_t)w * Dd + lane * 4);
        const float4 gm = *(const float4*)(gamma + lane * 4);
        float mu = g_mu[w], rstd = g_rstd[w];
        float4 xh = make_float4((x.x - mu) * rstd, (x.y - mu) * rstd,
                                (x.z - mu) * rstd, (x.w - mu) * rstd);
        float4 dxh = make_float4(dg.x * gm.x, dg.y * gm.y, dg.z * gm.z, dg.w * gm.w);
        float S1 = wsum32(dxh.x + dxh.y + dxh.z + dxh.w) * (1.0f / Dd);
        float S2 = wsum32(dxh.x * xh.x + dxh.y * xh.y + dxh.z * xh.z + dxh.w * xh.w) * (1.0f / Dd);
        float ss = wsum32(x.x * x.x + x.y * x.y + x.z * x.z + x.w * x.w);
        float4 g;
        g.x = x.x + rstd * (dxh.x - S1 - xh.x * S2);
        g.y = x.y + rstd * (dxh.y - S1 - xh.y * S2);
        g.z = x.z + rstd * (dxh.z - S1 - xh.z * S2);
        g.w = x.w + rstd * (dxh.w - S1 - xh.w * S2);
        float gss = wsum32(g.x * g.x + g.y * g.y + g.z * g.z + g.w * g.w);
        float sc1 = 1.0f / fmaxf(sqrtf(gss), 1.0f);
        float st = step[0] * sc1;
        float4 xn = make_float4(x.x - st * g.x, x.y - st * g.y,
                                x.z - st * g.z, x.w - st * g.w);
        float sn = wsum32(xn.x * xn.x + xn.y * xn.y + xn.z * xn.z + xn.w * xn.w);
        float sc2 = 10.0f / fmaxf(sqrtf(sn), 10.0f);
        float4 o = make_float4(xn.x * sc2, xn.y * sc2, xn.z * sc2, xn.w * sc2);
        *(float4*)(out + (size_t)w * Dd + lane * 4) = o;
        if (lane == 0) {
            float e = 0.5f * ss;
            float z0 = g_Z2[w * 2], z1 = g_Z2[w * 2 + 1];
            e -= (z0 > 0.f ? logf(z0) : 0.f) + (z1 > 0.f ? logf(z1) : 0.f);
            float y0 = g_Z3[w * 2], y1 = g_Z3[w * 2 + 1];
            e -= LAM3 * ((y0 > 0.f ? logf(y0) : 0.f) + (y1 > 0.f ? logf(y1) : 0.f));
            e -= g_Lm[w * 2] + g_Lm[w * 2 + 1];
            atomicAdd(&bins[batch[w]], e);
        }
    }
    __syncthreads();
    if (tid < NGg) atomicAdd(&Eg[tid], bins[tid]);
}

// ---------------------------------------------------------------------------
// Launch: multi-stream fork/join (graph-capture-legal event pattern)
// ---------------------------------------------------------------------------
extern "C" void kernel_launch(void* const* d_in, const int* in_sizes, int n_in,
                              void* d_out, int out_size) {
    const float* X    = (const float*)d_in[0];
    const int* c2     = (const int*)d_in[1];
    const int* u2     = (const int*)d_in[2];
    const int* c3     = (const int*)d_in[3];
    const int* u3     = (const int*)d_in[4];
    const int* v3     = (const int*)d_in[5];
    const int* tt     = (const int*)d_in[6];
    const int* batch  = (const int*)d_in[7];
    const float* a2   = (const float*)d_in[8];
    const float* step = (const float*)d_in[9];
    const float* gamma= (const float*)d_in[10];
    const float* beta = (const float*)d_in[11];
    const float* WQ2  = (const float*)d_in[12];
    const float* WK2  = (const float*)d_in[13];
    const float* WQ3  = (const float*)d_in[14];
    const float* WK3  = (const float*)d_in[15];
    const float* Ttau = (const float*)d_in[16];
    const float* WQm  = (const float*)d_in[17];
    const float* WKm  = (const float*)d_in[18];
    const float* Bmem = (const float*)d_in[19];
    float* out = (float*)d_out;
    float* Eg  = out + (size_t)Nn * Dd;

    static cudaStream_t s1 = nullptr, s2 = nullptr;
    static cudaEvent_t evA, ev1, ev2, ev3, ev4, ev5;
    if (!s1) {
        cudaStreamCreateWithFlags(&s1, cudaStreamNonBlocking);
        cudaStreamCreateWithFlags(&s2, cudaStreamNonBlocking);
        cudaEventCreateWithFlags(&evA, cudaEventDisableTiming);
        cudaEventCreateWithFlags(&ev1, cudaEventDisableTiming);
        cudaEventCreateWithFlags(&ev2, cudaEventDisableTiming);
        cudaEventCreateWithFlags(&ev3, cudaEventDisableTiming);
        cudaEventCreateWithFlags(&ev4, cudaEventDisableTiming);
        cudaEventCreateWithFlags(&ev5, cudaEventDisableTiming);
        cudaFuncSetAttribute(k_gemmF, cudaFuncAttributeMaxDynamicSharedMemorySize,
                             2 * 128 * FP * 2);
    }

    void *pUh, *pZ2, *pZ3, *pGh, *pP, *pPb, *pWcB, *pWcHT, *pdG;
    cudaGetSymbolAddress(&pUh, g_Uh);
    cudaGetSymbolAddress(&pZ2, g_Z2);
    cudaGetSymbolAddress(&pZ3, g_Z3);
    cudaGetSymbolAddress(&pGh, g_Gh);
    cudaGetSymbolAddress(&pP, g_P);
    cudaGetSymbolAddress(&pPb, g_Pb);
    cudaGetSymbolAddress(&pWcB, g_WcatB);
    cudaGetSymbolAddress(&pWcHT, g_WcatHT);
    cudaGetSymbolAddress(&pdG, g_dG);

    // ---- fork ----
    cudaEventRecord(evA, 0);
    cudaStreamWaitEvent(s1, evA, 0);
    cudaStreamWaitEvent(s2, evA, 0);

    // L: LN   |  s1: weights   |  s2: km + memsets
    k_ln<<<Nn / 8, 256>>>(X, gamma, beta);
    k_wcat<<<(PW * Dd + 255) / 256, 256, 0, s1>>>(WQ2, WK2, WQ3, WK3, WQm, Ttau);
    k_km<<<(Hh * KSL * HDm + 255) / 256, 256, 0, s2>>>(Bmem, WKm);
    cudaMemsetAsync(pUh, 0, sizeof(__half) * (size_t)Nn * PW, s2);
    cudaMemsetAsync(pZ2, 0, sizeof(float) * Nn * Hh, s2);
    cudaMemsetAsync(pZ3, 0, sizeof(float) * Nn * Hh, s2);
    cudaMemsetAsync(Eg, 0, sizeof(float) * NGg, s2);
    cudaEventRecord(ev1, s1);
    cudaEventRecord(ev2, s2);

    // L: fwd GEMM (needs ln + wcat)
    cudaStreamWaitEvent(0, ev1, 0);
    k_gemmF<<<dim3(PW / 128, Nn / 128), 256, 2 * 128 * FP * 2>>>(
        (const __nv_bfloat16*)pGh, (const __nv_bfloat16*)pWcB,
        (float*)pP, (__nv_bfloat16*)pPb);
    cudaEventRecord(ev3, 0);

    // s1: pair chain (needs P + Z2/Uh zeroed)
    cudaStreamWaitEvent(s1, ev3, 0);
    cudaStreamWaitEvent(s1, ev2, 0);
    k_pair_fwd<<<Ee / 8, 256, 0, s1>>>(c2, u2, a2);
    k_pair_bwd<<<Ee / 8, 256, 0, s1>>>(c2, u2);
    cudaEventRecord(ev4, s1);

    // s2: motif chain (needs P; already ordered after its own memsets)
    cudaStreamWaitEvent(s2, ev3, 0);
    k_motif_fwd<<<Mm / 8, 256, 0, s2>>>(c3, u3, v3, tt, Ttau);
    k_motif_bwd<<<Mm / 8, 256, 0, s2>>>(c3, u3, v3, tt);
    cudaEventRecord(ev5, s2);

    // L: memory term (needs P + km/memset via ev2)
    cudaStreamWaitEvent(0, ev2, 0);
    k_mem<<<(Nn * Hh) / 8, 256>>>();

    // ---- join ----
    cudaStreamWaitEvent(0, ev4, 0);
    cudaStreamWaitEvent(0, ev5, 0);

    // L: bwd GEMM + fused finish
    k_gemmB<<<dim3(Dd / 128, Nn / 128), 256>>>(
        (const __half*)pUh, PW, (const __half*)pWcHT, PW,
        (float*)pdG, Dd, PW);
    k_final<<<Nn / 8, 256>>>(X, gamma, step, batch, out, Eg);
}